// round 2
// baseline (speedup 1.0000x reference)
#include <cuda_runtime.h>
#include <math.h>

#define BDIM 4
#define SDIM 2048
#define DDIM 1024
#define HNUM 16
#define HD   64
#define ROWS (BDIM * SDIM)   // 8192

// ---------------------------------------------------------------------------
// Scratch (device globals: allocation-free per harness rules)
// ---------------------------------------------------------------------------
__device__ float g_Q[(size_t)BDIM * HNUM * SDIM * HD];   // [B,H,S,Hd]
__device__ float g_K[(size_t)BDIM * HNUM * SDIM * HD];
__device__ float g_V[(size_t)BDIM * HNUM * SDIM * HD];
__device__ float g_CTX[(size_t)ROWS * DDIM];             // [B,S,D]

// ---------------------------------------------------------------------------
// 64x64 tiled SGEMM: out[row,col] = X[row,:] @ W[:,col] + bias[col]
// headSplit=1 -> scatter into [B,H,S,Hd]; headSplit=0 -> plain row-major
// 256 threads, 4x4 microtile per thread, K-tile 16.
// ---------------------------------------------------------------------------
__global__ __launch_bounds__(256) void gemm64(
    const float* __restrict__ X, const float* __restrict__ W,
    const float* __restrict__ bias, float* __restrict__ out, int headSplit)
{
    __shared__ float As[16][68];   // [k][m], padded
    __shared__ float Bs[16][64];   // [k][n]

    const int bn = blockIdx.x * 64;
    const int bm = blockIdx.y * 64;
    const int t  = threadIdx.x;
    const int tx = t & 15;
    const int ty = t >> 4;

    const int am  = t >> 2;          // 0..63 (row within tile)
    const int akq = (t & 3) << 2;    // 0,4,8,12 (k offset)
    const int bk  = t >> 4;          // 0..15
    const int bnq = (t & 15) << 2;   // 0..60

    float acc[4][4] = {};

    for (int k0 = 0; k0 < DDIM; k0 += 16) {
        float4 av = *(const float4*)(X + (size_t)(bm + am) * DDIM + k0 + akq);
        As[akq + 0][am] = av.x;
        As[akq + 1][am] = av.y;
        As[akq + 2][am] = av.z;
        As[akq + 3][am] = av.w;
        *(float4*)(&Bs[bk][bnq]) =
            *(const float4*)(W + (size_t)(k0 + bk) * DDIM + bn + bnq);
        __syncthreads();

#pragma unroll
        for (int k = 0; k < 16; k++) {
            float4 a = *(const float4*)(&As[k][ty << 2]);
            float4 b = *(const float4*)(&Bs[k][tx << 2]);
            float ar[4] = {a.x, a.y, a.z, a.w};
            float br[4] = {b.x, b.y, b.z, b.w};
#pragma unroll
            for (int i = 0; i < 4; i++)
#pragma unroll
                for (int j = 0; j < 4; j++)
                    acc[i][j] += ar[i] * br[j];
        }
        __syncthreads();
    }

#pragma unroll
    for (int i = 0; i < 4; i++) {
        const int row = bm + (ty << 2) + i;
#pragma unroll
        for (int j = 0; j < 4; j++) {
            const int col = bn + (tx << 2) + j;
            const float v = acc[i][j] + bias[col];
            if (headSplit) {
                const int b = row >> 11, s = row & (SDIM - 1);
                const int h = col >> 6,  hd = col & (HD - 1);
                out[(size_t)((b * HNUM + h) * SDIM + s) * HD + hd] = v;
            } else {
                out[(size_t)row * DDIM + col] = v;
            }
        }
    }
}

// ---------------------------------------------------------------------------
// Flash attention, fp32. Per block: one (b,h), one 64-query tile.
// Key chunks of 64, online softmax. 256 threads, 4x4 microtiles.
// Shared: exactly 48 KB static (Qs + KVs + Ps, 64x64 each).
// ---------------------------------------------------------------------------
__global__ __launch_bounds__(256) void attn64()
{
    __shared__ float Qs[64][64];   // [d][q]  (transposed)
    __shared__ float KVs[64][64];  // K phase: [d][key]; V phase: [key][d]
    __shared__ float Ps[64][64];   // [q][key]

    const int t  = threadIdx.x;
    const int tx = t & 15;
    const int ty = t >> 4;
    const int bh    = blockIdx.y;          // 0..63
    const int qbase = blockIdx.x * 64;

    const float* Qg = g_Q + (size_t)bh * SDIM * HD;
    const float* Kg = g_K + (size_t)bh * SDIM * HD;
    const float* Vg = g_V + (size_t)bh * SDIM * HD;

    // Load full Q tile (64 rows x 64 d) transposed into smem.
    // 4096 floats / 256 threads = 4 float4 per thread.
    for (int idx = t; idx < 64 * 16; idx += 256) {
        const int q  = idx >> 4;          // 0..63
        const int dq = (idx & 15) << 2;   // 0..60
        float4 v = *(const float4*)(Qg + (size_t)(qbase + q) * HD + dq);
        Qs[dq + 0][q] = v.x;
        Qs[dq + 1][q] = v.y;
        Qs[dq + 2][q] = v.z;
        Qs[dq + 3][q] = v.w;
    }

    float o[4][4] = {};
    float m_run[4], l_run[4];
#pragma unroll
    for (int i = 0; i < 4; i++) { m_run[i] = -1e30f; l_run[i] = 0.f; }

    const float scale = 0.125f;   // 1/sqrt(64)

    for (int kb = 0; kb < SDIM; kb += 64) {
        __syncthreads();   // prev PV done; safe to overwrite KVs (covers Q load on iter 0)

        // Load full K chunk transposed: KVs[d][key], 4 float4 per thread
        for (int idx = t; idx < 64 * 16; idx += 256) {
            const int key = idx >> 4;
            const int dq  = (idx & 15) << 2;
            float4 v = *(const float4*)(Kg + (size_t)(kb + key) * HD + dq);
            KVs[dq + 0][key] = v.x;
            KVs[dq + 1][key] = v.y;
            KVs[dq + 2][key] = v.z;
            KVs[dq + 3][key] = v.w;
        }
        __syncthreads();

        // S = Q @ K^T  (64 q x 64 key, contraction over d=64)
        float s[4][4] = {};
#pragma unroll 8
        for (int d = 0; d < 64; d++) {
            float4 a = *(const float4*)(&Qs[d][ty << 2]);
            float4 b = *(const float4*)(&KVs[d][tx << 2]);
            float ar[4] = {a.x, a.y, a.z, a.w};
            float br[4] = {b.x, b.y, b.z, b.w};
#pragma unroll
            for (int i = 0; i < 4; i++)
#pragma unroll
                for (int j = 0; j < 4; j++)
                    s[i][j] += ar[i] * br[j];
        }

        // Online softmax per query row (row = 16-lane half-warp group)
#pragma unroll
        for (int i = 0; i < 4; i++) {
#pragma unroll
            for (int j = 0; j < 4; j++) s[i][j] *= scale;
            float mx = fmaxf(fmaxf(s[i][0], s[i][1]), fmaxf(s[i][2], s[i][3]));
#pragma unroll
            for (int off = 1; off < 16; off <<= 1)
                mx = fmaxf(mx, __shfl_xor_sync(0xffffffffu, mx, off));
            const float m_new = fmaxf(m_run[i], mx);
            const float alpha = __expf(m_run[i] - m_new);
            m_run[i] = m_new;
            float ls = 0.f;
#pragma unroll
            for (int j = 0; j < 4; j++) {
                const float p = __expf(s[i][j] - m_new);
                s[i][j] = p;
                ls += p;
            }
#pragma unroll
            for (int off = 1; off < 16; off <<= 1)
                ls += __shfl_xor_sync(0xffffffffu, ls, off);
            l_run[i] = l_run[i] * alpha + ls;
#pragma unroll
            for (int j = 0; j < 4; j++) o[i][j] *= alpha;
            // stash P tile
            *(float4*)(&Ps[(ty << 2) + i][tx << 2]) =
                make_float4(s[i][0], s[i][1], s[i][2], s[i][3]);
        }
        __syncthreads();   // S-phase reads of KVs done; P fully written

        // Load V chunk natural layout: KVs[key][d]
        for (int idx = t; idx < 64 * 16; idx += 256) {
            const int key = idx >> 4;
            const int dq  = (idx & 15) << 2;
            *(float4*)(&KVs[key][dq]) =
                *(const float4*)(Vg + (size_t)(kb + key) * HD + dq);
        }
        __syncthreads();

        // O += P @ V  (64 q x 64 hd, contraction over key=64)
#pragma unroll 8
        for (int k = 0; k < 64; k++) {
            const float a0 = Ps[(ty << 2) + 0][k];
            const float a1 = Ps[(ty << 2) + 1][k];
            const float a2 = Ps[(ty << 2) + 2][k];
            const float a3 = Ps[(ty << 2) + 3][k];
            float4 b = *(const float4*)(&KVs[k][tx << 2]);
            o[0][0] += a0 * b.x; o[0][1] += a0 * b.y; o[0][2] += a0 * b.z; o[0][3] += a0 * b.w;
            o[1][0] += a1 * b.x; o[1][1] += a1 * b.y; o[1][2] += a1 * b.z; o[1][3] += a1 * b.w;
            o[2][0] += a2 * b.x; o[2][1] += a2 * b.y; o[2][2] += a2 * b.z; o[2][3] += a2 * b.w;
            o[3][0] += a3 * b.x; o[3][1] += a3 * b.y; o[3][2] += a3 * b.z; o[3][3] += a3 * b.w;
        }
    }

    // Epilogue: normalize and write ctx in [B,S,D] with head merge
    const int b = bh >> 4;
    const int h = bh & (HNUM - 1);
#pragma unroll
    for (int i = 0; i < 4; i++) {
        const float inv = 1.f / l_run[i];
        const int s_idx = qbase + (ty << 2) + i;
        float* dst = g_CTX + (size_t)(b * SDIM + s_idx) * DDIM + h * HD + (tx << 2);
        float4 v = make_float4(o[i][0] * inv, o[i][1] * inv, o[i][2] * inv, o[i][3] * inv);
        *(float4*)dst = v;
    }
}

// ---------------------------------------------------------------------------
// Launch
// ---------------------------------------------------------------------------
extern "C" void kernel_launch(void* const* d_in, const int* in_sizes, int n_in,
                              void* d_out, int out_size)
{
    const float* x  = (const float*)d_in[0];
    const float* Wq = (const float*)d_in[1];
    const float* bq = (const float*)d_in[2];
    const float* Wk = (const float*)d_in[3];
    const float* bk = (const float*)d_in[4];
    const float* Wv = (const float*)d_in[5];
    const float* bv = (const float*)d_in[6];
    const float* Wo = (const float*)d_in[7];
    const float* bo = (const float*)d_in[8];

    float* qp;  cudaGetSymbolAddress((void**)&qp,  g_Q);
    float* kp;  cudaGetSymbolAddress((void**)&kp,  g_K);
    float* vp;  cudaGetSymbolAddress((void**)&vp,  g_V);
    float* cp;  cudaGetSymbolAddress((void**)&cp,  g_CTX);

    dim3 gg(DDIM / 64, ROWS / 64);   // (16, 128)
    gemm64<<<gg, 256>>>(x, Wq, bq, qp, 1);
    gemm64<<<gg, 256>>>(x, Wk, bk, kp, 1);
    gemm64<<<gg, 256>>>(x, Wv, bv, vp, 1);

    attn64<<<dim3(SDIM / 64, BDIM * HNUM), 256>>>();   // (32, 64)

    gemm64<<<gg, 256>>>(cp, Wo, bo, (float*)d_out, 0);
}

// round 4
// speedup vs baseline: 1.3972x; 1.3972x over previous
#include <cuda_runtime.h>
#include <cuda_bf16.h>
#include <math.h>
#include <cstdint>

#define BDIM 4
#define SDIM 2048
#define DDIM 1024
#define HNUM 16
#define HD   64
#define ROWS (BDIM * SDIM)   // 8192

// ---------------------------------------------------------------------------
// Scratch
// ---------------------------------------------------------------------------
__device__ float g_Q[(size_t)BDIM * HNUM * SDIM * HD];
__device__ float g_K[(size_t)BDIM * HNUM * SDIM * HD];
__device__ float g_V[(size_t)BDIM * HNUM * SDIM * HD];
__device__ float g_CTX[(size_t)ROWS * DDIM];
__device__ __nv_bfloat16 g_Xh[(size_t)ROWS * DDIM];
__device__ __nv_bfloat16 g_Xl[(size_t)ROWS * DDIM];
__device__ __nv_bfloat16 g_Wth[4][(size_t)DDIM * DDIM];   // W^T hi, [n][k]
__device__ __nv_bfloat16 g_Wtl[4][(size_t)DDIM * DDIM];   // W^T lo

// ---------------------------------------------------------------------------
// mma.sync m16n8k16 bf16 (row.col), fp32 accumulate — portable PTX (sm_80+)
// ---------------------------------------------------------------------------
__device__ __forceinline__ void mma16816(float* c, const uint32_t* a, const uint32_t* b)
{
    asm volatile(
        "mma.sync.aligned.m16n8k16.row.col.f32.bf16.bf16.f32 "
        "{%0,%1,%2,%3}, {%4,%5,%6,%7}, {%8,%9}, {%0,%1,%2,%3};"
        : "+f"(c[0]), "+f"(c[1]), "+f"(c[2]), "+f"(c[3])
        : "r"(a[0]), "r"(a[1]), "r"(a[2]), "r"(a[3]), "r"(b[0]), "r"(b[1]));
}

// ---------------------------------------------------------------------------
// Prep kernels
// ---------------------------------------------------------------------------
__global__ void convert_split(const float* __restrict__ src,
                              __nv_bfloat16* __restrict__ hi,
                              __nv_bfloat16* __restrict__ lo, int n)
{
    for (int i = blockIdx.x * blockDim.x + threadIdx.x; i < n;
         i += gridDim.x * blockDim.x) {
        float x = src[i];
        __nv_bfloat16 h = __float2bfloat16(x);
        hi[i] = h;
        lo[i] = __float2bfloat16(x - __bfloat162float(h));
    }
}

__global__ void transpose_split(const float* __restrict__ W,
                                __nv_bfloat16* __restrict__ Th,
                                __nv_bfloat16* __restrict__ Tl)
{
    __shared__ float tile[32][33];
    const int tx = threadIdx.x, ty = threadIdx.y;
    const int kk = blockIdx.y * 32 + ty;
    const int nn = blockIdx.x * 32 + tx;
    tile[ty][tx] = W[(size_t)kk * DDIM + nn];
    __syncthreads();
    const int on = blockIdx.x * 32 + ty;
    const int ok = blockIdx.y * 32 + tx;
    float v = tile[tx][ty];
    __nv_bfloat16 h = __float2bfloat16(v);
    Th[(size_t)on * DDIM + ok] = h;
    Tl[(size_t)on * DDIM + ok] = __float2bfloat16(v - __bfloat162float(h));
}

// ---------------------------------------------------------------------------
// HMMA GEMM: C[8192,1024] = A @ W  (A row-major [m][k], Wt row-major [n][k])
// bf16 hi/lo 3-pass split, fp32 accum. CTA tile 128x128, K-chunk 64.
// 8 warps (2 x 4), warp tile 64x32. smem row stride 72 (conflict-free frags).
// ---------------------------------------------------------------------------
#define AKS 72
#define TILE_E (128 * AKS)                     // elements per smem tile
#define GEMM_SMEM (4 * TILE_E * 2)             // 73728 bytes (also covers epilogue 67584)

__global__ __launch_bounds__(256) void gemm_mma(
    const __nv_bfloat16* __restrict__ Ah_g, const __nv_bfloat16* __restrict__ Al_g,
    const __nv_bfloat16* __restrict__ Bh_g, const __nv_bfloat16* __restrict__ Bl_g,
    const float* __restrict__ bias, float* __restrict__ out, int headSplit)
{
    extern __shared__ char smem[];
    __nv_bfloat16* sAh = (__nv_bfloat16*)smem;
    __nv_bfloat16* sAl = sAh + TILE_E;
    __nv_bfloat16* sBh = sAl + TILE_E;
    __nv_bfloat16* sBl = sBh + TILE_E;

    const int t    = threadIdx.x;
    const int wid  = t >> 5;
    const int lane = t & 31;
    const int wr   = wid & 1;            // warp row: 0..1 (64 rows each)
    const int wc   = wid >> 1;           // warp col: 0..3 (32 cols each)
    const int lr   = lane >> 2;          // 0..7
    const int lc   = (lane & 3) << 1;    // 0,2,4,6
    const int bn = blockIdx.x * 128;
    const int bm = blockIdx.y * 128;

    float acc[4][4][4];
#pragma unroll
    for (int i = 0; i < 4; i++)
#pragma unroll
        for (int j = 0; j < 4; j++)
#pragma unroll
            for (int r = 0; r < 4; r++) acc[i][j][r] = 0.f;

    for (int c = 0; c < 16; c++) {
        const int k0g = c * 64;
        __syncthreads();   // previous chunk's mma reads done

        // load 4 tiles of 128 rows x 64 bf16 into smem (stride AKS)
        for (int i = t; i < 1024; i += 256) {
            const int r = i >> 3, seg = i & 7;        // 8 bf16 per (r,seg)
            const size_t ga = (size_t)(bm + r) * DDIM + k0g + seg * 8;
            const size_t gb = (size_t)(bn + r) * DDIM + k0g + seg * 8;
            const int so = r * AKS + seg * 8;
            uint4 v;
            v = *(const uint4*)(Ah_g + ga);
            *(uint2*)(sAh + so)     = make_uint2(v.x, v.y);
            *(uint2*)(sAh + so + 4) = make_uint2(v.z, v.w);
            v = *(const uint4*)(Al_g + ga);
            *(uint2*)(sAl + so)     = make_uint2(v.x, v.y);
            *(uint2*)(sAl + so + 4) = make_uint2(v.z, v.w);
            v = *(const uint4*)(Bh_g + gb);
            *(uint2*)(sBh + so)     = make_uint2(v.x, v.y);
            *(uint2*)(sBh + so + 4) = make_uint2(v.z, v.w);
            v = *(const uint4*)(Bl_g + gb);
            *(uint2*)(sBl + so)     = make_uint2(v.x, v.y);
            *(uint2*)(sBl + so + 4) = make_uint2(v.z, v.w);
        }
        __syncthreads();

#pragma unroll
        for (int kk = 0; kk < 4; kk++) {
            const int k0 = kk * 16;
            uint32_t ah[4][4], al[4][4], bh[4][2], bl[4][2];
#pragma unroll
            for (int mi = 0; mi < 4; mi++) {
                const int r0 = (wr * 64 + mi * 16 + lr) * AKS + k0 + lc;
                const int r8 = r0 + 8 * AKS;
                ah[mi][0] = *(const uint32_t*)(sAh + r0);
                ah[mi][1] = *(const uint32_t*)(sAh + r8);
                ah[mi][2] = *(const uint32_t*)(sAh + r0 + 8);
                ah[mi][3] = *(const uint32_t*)(sAh + r8 + 8);
                al[mi][0] = *(const uint32_t*)(sAl + r0);
                al[mi][1] = *(const uint32_t*)(sAl + r8);
                al[mi][2] = *(const uint32_t*)(sAl + r0 + 8);
                al[mi][3] = *(const uint32_t*)(sAl + r8 + 8);
            }
#pragma unroll
            for (int ni = 0; ni < 4; ni++) {
                const int c0 = (wc * 32 + ni * 8 + lr) * AKS + k0 + lc;
                bh[ni][0] = *(const uint32_t*)(sBh + c0);
                bh[ni][1] = *(const uint32_t*)(sBh + c0 + 8);
                bl[ni][0] = *(const uint32_t*)(sBl + c0);
                bl[ni][1] = *(const uint32_t*)(sBl + c0 + 8);
            }
#pragma unroll
            for (int mi = 0; mi < 4; mi++)
#pragma unroll
                for (int ni = 0; ni < 4; ni++) {
                    mma16816(acc[mi][ni], ah[mi], bh[ni]);
                    mma16816(acc[mi][ni], ah[mi], bl[ni]);
                    mma16816(acc[mi][ni], al[mi], bh[ni]);
                }
        }
    }

    // stage C through smem for coalesced global writes
    __syncthreads();
    float* Ds = (float*)smem;   // stride 132
#pragma unroll
    for (int mi = 0; mi < 4; mi++) {
        const int r = wr * 64 + mi * 16 + lr;
#pragma unroll
        for (int ni = 0; ni < 4; ni++) {
            const int cc = wc * 32 + ni * 8 + lc;
            Ds[r * 132 + cc]           = acc[mi][ni][0];
            Ds[r * 132 + cc + 1]       = acc[mi][ni][1];
            Ds[(r + 8) * 132 + cc]     = acc[mi][ni][2];
            Ds[(r + 8) * 132 + cc + 1] = acc[mi][ni][3];
        }
    }
    __syncthreads();

    for (int idx = t; idx < 128 * 128; idx += 256) {
        const int r = idx >> 7, cc = idx & 127;
        const int row = bm + r, col = bn + cc;
        const float v = Ds[r * 132 + cc] + __ldg(bias + col);
        if (headSplit) {
            const int b = row >> 11, s = row & (SDIM - 1);
            const int h = col >> 6,  hd = col & (HD - 1);
            out[(size_t)((b * HNUM + h) * SDIM + s) * HD + hd] = v;
        } else {
            out[(size_t)row * DDIM + col] = v;
        }
    }
}

// ---------------------------------------------------------------------------
// Flash attention, fp32 SIMT (unchanged from passing R2 version)
// ---------------------------------------------------------------------------
__global__ __launch_bounds__(256) void attn64()
{
    __shared__ float Qs[64][64];
    __shared__ float KVs[64][64];
    __shared__ float Ps[64][64];

    const int t  = threadIdx.x;
    const int tx = t & 15;
    const int ty = t >> 4;
    const int bh    = blockIdx.y;
    const int qbase = blockIdx.x * 64;

    const float* Qg = g_Q + (size_t)bh * SDIM * HD;
    const float* Kg = g_K + (size_t)bh * SDIM * HD;
    const float* Vg = g_V + (size_t)bh * SDIM * HD;

    for (int idx = t; idx < 64 * 16; idx += 256) {
        const int q  = idx >> 4;
        const int dq = (idx & 15) << 2;
        float4 v = *(const float4*)(Qg + (size_t)(qbase + q) * HD + dq);
        Qs[dq + 0][q] = v.x;
        Qs[dq + 1][q] = v.y;
        Qs[dq + 2][q] = v.z;
        Qs[dq + 3][q] = v.w;
    }

    float o[4][4] = {};
    float m_run[4], l_run[4];
#pragma unroll
    for (int i = 0; i < 4; i++) { m_run[i] = -1e30f; l_run[i] = 0.f; }

    const float scale = 0.125f;

    for (int kb = 0; kb < SDIM; kb += 64) {
        __syncthreads();
        for (int idx = t; idx < 64 * 16; idx += 256) {
            const int key = idx >> 4;
            const int dq  = (idx & 15) << 2;
            float4 v = *(const float4*)(Kg + (size_t)(kb + key) * HD + dq);
            KVs[dq + 0][key] = v.x;
            KVs[dq + 1][key] = v.y;
            KVs[dq + 2][key] = v.z;
            KVs[dq + 3][key] = v.w;
        }
        __syncthreads();

        float s[4][4] = {};
#pragma unroll 8
        for (int d = 0; d < 64; d++) {
            float4 a = *(const float4*)(&Qs[d][ty << 2]);
            float4 b = *(const float4*)(&KVs[d][tx << 2]);
            float ar[4] = {a.x, a.y, a.z, a.w};
            float br[4] = {b.x, b.y, b.z, b.w};
#pragma unroll
            for (int i = 0; i < 4; i++)
#pragma unroll
                for (int j = 0; j < 4; j++)
                    s[i][j] += ar[i] * br[j];
        }

#pragma unroll
        for (int i = 0; i < 4; i++) {
#pragma unroll
            for (int j = 0; j < 4; j++) s[i][j] *= scale;
            float mx = fmaxf(fmaxf(s[i][0], s[i][1]), fmaxf(s[i][2], s[i][3]));
#pragma unroll
            for (int off = 1; off < 16; off <<= 1)
                mx = fmaxf(mx, __shfl_xor_sync(0xffffffffu, mx, off));
            const float m_new = fmaxf(m_run[i], mx);
            const float alpha = __expf(m_run[i] - m_new);
            m_run[i] = m_new;
            float ls = 0.f;
#pragma unroll
            for (int j = 0; j < 4; j++) {
                const float p = __expf(s[i][j] - m_new);
                s[i][j] = p;
                ls += p;
            }
#pragma unroll
            for (int off = 1; off < 16; off <<= 1)
                ls += __shfl_xor_sync(0xffffffffu, ls, off);
            l_run[i] = l_run[i] * alpha + ls;
#pragma unroll
            for (int j = 0; j < 4; j++) o[i][j] *= alpha;
            *(float4*)(&Ps[(ty << 2) + i][tx << 2]) =
                make_float4(s[i][0], s[i][1], s[i][2], s[i][3]);
        }
        __syncthreads();

        for (int idx = t; idx < 64 * 16; idx += 256) {
            const int key = idx >> 4;
            const int dq  = (idx & 15) << 2;
            *(float4*)(&KVs[key][dq]) =
                *(const float4*)(Vg + (size_t)(kb + key) * HD + dq);
        }
        __syncthreads();

#pragma unroll 8
        for (int k = 0; k < 64; k++) {
            const float a0 = Ps[(ty << 2) + 0][k];
            const float a1 = Ps[(ty << 2) + 1][k];
            const float a2 = Ps[(ty << 2) + 2][k];
            const float a3 = Ps[(ty << 2) + 3][k];
            float4 b = *(const float4*)(&KVs[k][tx << 2]);
            o[0][0] += a0 * b.x; o[0][1] += a0 * b.y; o[0][2] += a0 * b.z; o[0][3] += a0 * b.w;
            o[1][0] += a1 * b.x; o[1][1] += a1 * b.y; o[1][2] += a1 * b.z; o[1][3] += a1 * b.w;
            o[2][0] += a2 * b.x; o[2][1] += a2 * b.y; o[2][2] += a2 * b.z; o[2][3] += a2 * b.w;
            o[3][0] += a3 * b.x; o[3][1] += a3 * b.y; o[3][2] += a3 * b.z; o[3][3] += a3 * b.w;
        }
    }

    const int b = bh >> 4;
    const int h = bh & (HNUM - 1);
#pragma unroll
    for (int i = 0; i < 4; i++) {
        const float inv = 1.f / l_run[i];
        const int s_idx = qbase + (ty << 2) + i;
        float* dst = g_CTX + (size_t)(b * SDIM + s_idx) * DDIM + h * HD + (tx << 2);
        *(float4*)dst = make_float4(o[i][0] * inv, o[i][1] * inv, o[i][2] * inv, o[i][3] * inv);
    }
}

// ---------------------------------------------------------------------------
// Launch
// ---------------------------------------------------------------------------
extern "C" void kernel_launch(void* const* d_in, const int* in_sizes, int n_in,
                              void* d_out, int out_size)
{
    const float* x  = (const float*)d_in[0];
    const float* Wq = (const float*)d_in[1];
    const float* bq = (const float*)d_in[2];
    const float* Wk = (const float*)d_in[3];
    const float* bk = (const float*)d_in[4];
    const float* Wv = (const float*)d_in[5];
    const float* bv = (const float*)d_in[6];
    const float* Wo = (const float*)d_in[7];
    const float* bo = (const float*)d_in[8];

    float *qp, *kp, *vp, *cp;
    __nv_bfloat16 *xh, *xl, *wth, *wtl;
    cudaGetSymbolAddress((void**)&qp,  g_Q);
    cudaGetSymbolAddress((void**)&kp,  g_K);
    cudaGetSymbolAddress((void**)&vp,  g_V);
    cudaGetSymbolAddress((void**)&cp,  g_CTX);
    cudaGetSymbolAddress((void**)&xh,  g_Xh);
    cudaGetSymbolAddress((void**)&xl,  g_Xl);
    cudaGetSymbolAddress((void**)&wth, g_Wth);
    cudaGetSymbolAddress((void**)&wtl, g_Wtl);

    cudaFuncSetAttribute(gemm_mma, cudaFuncAttributeMaxDynamicSharedMemorySize, GEMM_SMEM);

    const int N_ELEM = ROWS * DDIM;
    const size_t WSZ = (size_t)DDIM * DDIM;

    convert_split<<<2048, 256>>>(x, xh, xl, N_ELEM);
    dim3 tg(32, 32), tb(32, 32);
    transpose_split<<<tg, tb>>>(Wq, wth + 0 * WSZ, wtl + 0 * WSZ);
    transpose_split<<<tg, tb>>>(Wk, wth + 1 * WSZ, wtl + 1 * WSZ);
    transpose_split<<<tg, tb>>>(Wv, wth + 2 * WSZ, wtl + 2 * WSZ);
    transpose_split<<<tg, tb>>>(Wo, wth + 3 * WSZ, wtl + 3 * WSZ);

    dim3 gg(DDIM / 128, ROWS / 128);   // (8, 64)
    gemm_mma<<<gg, 256, GEMM_SMEM>>>(xh, xl, wth + 0 * WSZ, wtl + 0 * WSZ, bq, qp, 1);
    gemm_mma<<<gg, 256, GEMM_SMEM>>>(xh, xl, wth + 1 * WSZ, wtl + 1 * WSZ, bk, kp, 1);
    gemm_mma<<<gg, 256, GEMM_SMEM>>>(xh, xl, wth + 2 * WSZ, wtl + 2 * WSZ, bv, vp, 1);

    attn64<<<dim3(SDIM / 64, BDIM * HNUM), 256>>>();

    convert_split<<<2048, 256>>>(cp, xh, xl, N_ELEM);
    gemm_mma<<<gg, 256, GEMM_SMEM>>>(xh, xl, wth + 3 * WSZ, wtl + 3 * WSZ, bo, (float*)d_out, 0);
}

// round 6
// speedup vs baseline: 2.2900x; 1.6390x over previous
#include <cuda_runtime.h>
#include <cuda_bf16.h>
#include <math.h>
#include <cstdint>

#define BDIM 4
#define SDIM 2048
#define DDIM 1024
#define HNUM 16
#define HD   64
#define ROWS (BDIM * SDIM)   // 8192
#define BH   (BDIM * HNUM)   // 64

// ---------------------------------------------------------------------------
// Scratch
// ---------------------------------------------------------------------------
__device__ __nv_bfloat16 g_Xh[(size_t)ROWS * DDIM];
__device__ __nv_bfloat16 g_Xl[(size_t)ROWS * DDIM];
__device__ __nv_bfloat16 g_Wth[4][(size_t)DDIM * DDIM];   // W^T hi, [n][k]
__device__ __nv_bfloat16 g_Wtl[4][(size_t)DDIM * DDIM];
__device__ __nv_bfloat16 g_Qh[(size_t)BH * SDIM * HD];    // [bh][s][hd]
__device__ __nv_bfloat16 g_Ql[(size_t)BH * SDIM * HD];
__device__ __nv_bfloat16 g_Kh[(size_t)BH * SDIM * HD];
__device__ __nv_bfloat16 g_Kl[(size_t)BH * SDIM * HD];
__device__ __nv_bfloat16 g_VTh[(size_t)BH * HD * SDIM];   // [bh][hd][s]
__device__ __nv_bfloat16 g_VTl[(size_t)BH * HD * SDIM];

// ---------------------------------------------------------------------------
// mma.sync m16n8k16 bf16 row.col, fp32 accumulate (portable, sm_80+)
// ---------------------------------------------------------------------------
__device__ __forceinline__ void mma16816(float* c, const uint32_t* a, const uint32_t* b)
{
    asm volatile(
        "mma.sync.aligned.m16n8k16.row.col.f32.bf16.bf16.f32 "
        "{%0,%1,%2,%3}, {%4,%5,%6,%7}, {%8,%9}, {%0,%1,%2,%3};"
        : "+f"(c[0]), "+f"(c[1]), "+f"(c[2]), "+f"(c[3])
        : "r"(a[0]), "r"(a[1]), "r"(a[2]), "r"(a[3]), "r"(b[0]), "r"(b[1]));
}

// pack two fp32 -> bf16x2 (lo -> low half, hi -> high half)
__device__ __forceinline__ uint32_t pack_bf16(float lo, float hi)
{
    uint32_t r;
    asm("cvt.rn.bf16x2.f32 %0, %1, %2;" : "=r"(r) : "f"(hi), "f"(lo));
    return r;
}

// ---------------------------------------------------------------------------
// Prep kernels
// ---------------------------------------------------------------------------
__global__ void convert_split(const float* __restrict__ src,
                              __nv_bfloat16* __restrict__ hi,
                              __nv_bfloat16* __restrict__ lo, int n)
{
    for (int i = blockIdx.x * blockDim.x + threadIdx.x; i < n;
         i += gridDim.x * blockDim.x) {
        float x = src[i];
        __nv_bfloat16 h = __float2bfloat16(x);
        hi[i] = h;
        lo[i] = __float2bfloat16(x - __bfloat162float(h));
    }
}

__global__ void transpose_split(const float* __restrict__ W,
                                __nv_bfloat16* __restrict__ Th,
                                __nv_bfloat16* __restrict__ Tl)
{
    __shared__ float tile[32][33];
    const int tx = threadIdx.x, ty = threadIdx.y;
    tile[ty][tx] = W[(size_t)(blockIdx.y * 32 + ty) * DDIM + blockIdx.x * 32 + tx];
    __syncthreads();
    const int on = blockIdx.x * 32 + ty;
    const int ok = blockIdx.y * 32 + tx;
    float v = tile[tx][ty];
    __nv_bfloat16 h = __float2bfloat16(v);
    Th[(size_t)on * DDIM + ok] = h;
    Tl[(size_t)on * DDIM + ok] = __float2bfloat16(v - __bfloat162float(h));
}

// ---------------------------------------------------------------------------
// HMMA GEMM, bf16 hi/lo 3-pass split. CTA tile 128x128, K-chunk 64, 8 warps.
// mode 0: fp32 out [row][D];  mode 1: bf16 hi/lo [b,h,s,hd];
// mode 2: bf16 hi/lo transposed [b,h,hd,s]
// ---------------------------------------------------------------------------
#define AKS 72
#define TILE_E (128 * AKS)
#define GEMM_SMEM (4 * TILE_E * 2)   // 73728 B (epilogue needs 128*133*4=68096)

__global__ __launch_bounds__(256) void gemm_mma(
    const __nv_bfloat16* __restrict__ Ah_g, const __nv_bfloat16* __restrict__ Al_g,
    const __nv_bfloat16* __restrict__ Bh_g, const __nv_bfloat16* __restrict__ Bl_g,
    const float* __restrict__ bias, float* __restrict__ outF,
    __nv_bfloat16* __restrict__ outH, __nv_bfloat16* __restrict__ outL, int mode)
{
    extern __shared__ char smem[];
    __nv_bfloat16* sAh = (__nv_bfloat16*)smem;
    __nv_bfloat16* sAl = sAh + TILE_E;
    __nv_bfloat16* sBh = sAl + TILE_E;
    __nv_bfloat16* sBl = sBh + TILE_E;

    const int t    = threadIdx.x;
    const int wid  = t >> 5;
    const int lane = t & 31;
    const int wr   = wid & 1;
    const int wc   = wid >> 1;
    const int lr   = lane >> 2;
    const int lc   = (lane & 3) << 1;
    const int bn = blockIdx.x * 128;
    const int bm = blockIdx.y * 128;

    float acc[4][4][4];
#pragma unroll
    for (int i = 0; i < 4; i++)
#pragma unroll
        for (int j = 0; j < 4; j++)
#pragma unroll
            for (int r = 0; r < 4; r++) acc[i][j][r] = 0.f;

    for (int c = 0; c < 16; c++) {
        const int k0g = c * 64;
        __syncthreads();
        for (int i = t; i < 1024; i += 256) {
            const int r = i >> 3, seg = i & 7;
            const size_t ga = (size_t)(bm + r) * DDIM + k0g + seg * 8;
            const size_t gb = (size_t)(bn + r) * DDIM + k0g + seg * 8;
            const int so = r * AKS + seg * 8;
            uint4 v;
            v = *(const uint4*)(Ah_g + ga);
            *(uint2*)(sAh + so) = make_uint2(v.x, v.y); *(uint2*)(sAh + so + 4) = make_uint2(v.z, v.w);
            v = *(const uint4*)(Al_g + ga);
            *(uint2*)(sAl + so) = make_uint2(v.x, v.y); *(uint2*)(sAl + so + 4) = make_uint2(v.z, v.w);
            v = *(const uint4*)(Bh_g + gb);
            *(uint2*)(sBh + so) = make_uint2(v.x, v.y); *(uint2*)(sBh + so + 4) = make_uint2(v.z, v.w);
            v = *(const uint4*)(Bl_g + gb);
            *(uint2*)(sBl + so) = make_uint2(v.x, v.y); *(uint2*)(sBl + so + 4) = make_uint2(v.z, v.w);
        }
        __syncthreads();

#pragma unroll
        for (int kk = 0; kk < 4; kk++) {
            const int k0 = kk * 16;
            uint32_t ah[4][4], al[4][4], bh[4][2], bl[4][2];
#pragma unroll
            for (int mi = 0; mi < 4; mi++) {
                const int r0 = (wr * 64 + mi * 16 + lr) * AKS + k0 + lc;
                const int r8 = r0 + 8 * AKS;
                ah[mi][0] = *(const uint32_t*)(sAh + r0);
                ah[mi][1] = *(const uint32_t*)(sAh + r8);
                ah[mi][2] = *(const uint32_t*)(sAh + r0 + 8);
                ah[mi][3] = *(const uint32_t*)(sAh + r8 + 8);
                al[mi][0] = *(const uint32_t*)(sAl + r0);
                al[mi][1] = *(const uint32_t*)(sAl + r8);
                al[mi][2] = *(const uint32_t*)(sAl + r0 + 8);
                al[mi][3] = *(const uint32_t*)(sAl + r8 + 8);
            }
#pragma unroll
            for (int ni = 0; ni < 4; ni++) {
                const int c0 = (wc * 32 + ni * 8 + lr) * AKS + k0 + lc;
                bh[ni][0] = *(const uint32_t*)(sBh + c0);
                bh[ni][1] = *(const uint32_t*)(sBh + c0 + 8);
                bl[ni][0] = *(const uint32_t*)(sBl + c0);
                bl[ni][1] = *(const uint32_t*)(sBl + c0 + 8);
            }
#pragma unroll
            for (int mi = 0; mi < 4; mi++)
#pragma unroll
                for (int ni = 0; ni < 4; ni++) {
                    mma16816(acc[mi][ni], ah[mi], bh[ni]);
                    mma16816(acc[mi][ni], ah[mi], bl[ni]);
                    mma16816(acc[mi][ni], al[mi], bh[ni]);
                }
        }
    }

    __syncthreads();
    float* Ds = (float*)smem;   // stride 133
#pragma unroll
    for (int mi = 0; mi < 4; mi++) {
        const int r = wr * 64 + mi * 16 + lr;
#pragma unroll
        for (int ni = 0; ni < 4; ni++) {
            const int cc = wc * 32 + ni * 8 + lc;
            Ds[r * 133 + cc]           = acc[mi][ni][0];
            Ds[r * 133 + cc + 1]       = acc[mi][ni][1];
            Ds[(r + 8) * 133 + cc]     = acc[mi][ni][2];
            Ds[(r + 8) * 133 + cc + 1] = acc[mi][ni][3];
        }
    }
    __syncthreads();

    if (mode == 0) {
        for (int idx = t; idx < 128 * 128; idx += 256) {
            const int r = idx >> 7, cc = idx & 127;
            outF[(size_t)(bm + r) * DDIM + bn + cc] = Ds[r * 133 + cc] + __ldg(bias + bn + cc);
        }
    } else if (mode == 1) {
        for (int idx = t; idx < 128 * 128; idx += 256) {
            const int r = idx >> 7, cc = idx & 127;
            const int row = bm + r, col = bn + cc;
            const float v = Ds[r * 133 + cc] + __ldg(bias + col);
            const int b = row >> 11, s = row & (SDIM - 1);
            const int h = col >> 6,  hd = col & (HD - 1);
            const size_t dst = (size_t)((b * HNUM + h) * SDIM + s) * HD + hd;
            __nv_bfloat16 hh = __float2bfloat16(v);
            outH[dst] = hh;
            outL[dst] = __float2bfloat16(v - __bfloat162float(hh));
        }
    } else {
        for (int idx = t; idx < 128 * 128; idx += 256) {
            const int r = idx & 127, cc = idx >> 7;   // consecutive threads -> consecutive s
            const int row = bm + r, col = bn + cc;
            const float v = Ds[r * 133 + cc] + __ldg(bias + col);
            const int b = row >> 11, s = row & (SDIM - 1);
            const int h = col >> 6,  hd = col & (HD - 1);
            const size_t dst = (size_t)((b * HNUM + h) * HD + hd) * SDIM + s;
            __nv_bfloat16 hh = __float2bfloat16(v);
            outH[dst] = hh;
            outL[dst] = __float2bfloat16(v - __bfloat162float(hh));
        }
    }
}

// ---------------------------------------------------------------------------
// Flash attention with mma.sync, hi/lo split for QK^T and PV.
// CTA: one (b,h) x 128 queries; 8 warps x 16 q-rows; key chunks of 64.
// Writes ctx directly as bf16 hi/lo into g_Xh/g_Xl ([b,s,D], head-merged).
// ---------------------------------------------------------------------------
#define ATS 72
// element offsets in smem
#define SQ_H 0
#define SQ_L (128 * ATS)
#define SK_H (2 * 128 * ATS)
#define SK_L (SK_H + 64 * ATS)
#define SV_H (SK_L + 64 * ATS)
#define SV_L (SV_H + 64 * ATS)
#define ATTN_SMEM ((SV_L + 64 * ATS) * 2)   // 73728 bytes

__global__ __launch_bounds__(256, 2) void attn_mma()
{
    extern __shared__ char smraw[];
    __nv_bfloat16* sm = (__nv_bfloat16*)smraw;

    const int t    = threadIdx.x;
    const int wid  = t >> 5;
    const int lane = t & 31;
    const int lr   = lane >> 2;
    const int lc   = (lane & 3) << 1;
    const int bh    = blockIdx.y;
    const int qbase = blockIdx.x * 128;
    const int qw    = wid * 16;          // warp's query offset within tile

    const __nv_bfloat16* Qh = g_Qh + (size_t)bh * SDIM * HD;
    const __nv_bfloat16* Ql = g_Ql + (size_t)bh * SDIM * HD;
    const __nv_bfloat16* Kh = g_Kh + (size_t)bh * SDIM * HD;
    const __nv_bfloat16* Kl = g_Kl + (size_t)bh * SDIM * HD;
    const __nv_bfloat16* Vh = g_VTh + (size_t)bh * HD * SDIM;
    const __nv_bfloat16* Vl = g_VTl + (size_t)bh * HD * SDIM;

    // Load Q tile (128 x 64) hi/lo into smem
    for (int i = t; i < 1024; i += 256) {
        const int r = i >> 3, seg = i & 7;
        const size_t g = (size_t)(qbase + r) * HD + seg * 8;
        const int so = r * ATS + seg * 8;
        uint4 v;
        v = *(const uint4*)(Qh + g);
        *(uint2*)(sm + SQ_H + so) = make_uint2(v.x, v.y);
        *(uint2*)(sm + SQ_H + so + 4) = make_uint2(v.z, v.w);
        v = *(const uint4*)(Ql + g);
        *(uint2*)(sm + SQ_L + so) = make_uint2(v.x, v.y);
        *(uint2*)(sm + SQ_L + so + 4) = make_uint2(v.z, v.w);
    }

    float o[8][4];
#pragma unroll
    for (int i = 0; i < 8; i++)
#pragma unroll
        for (int j = 0; j < 4; j++) o[i][j] = 0.f;
    float m0 = -1e30f, m1 = -1e30f, l0 = 0.f, l1 = 0.f;

    for (int kb = 0; kb < SDIM; kb += 64) {
        __syncthreads();   // prev chunk reads done (and Q store ordering on iter 0)

        // K chunk: [key 64][d 64] hi/lo ; V^T chunk: [d 64][s 64] hi/lo
        for (int i = t; i < 512; i += 256) {
            const int r = i >> 3, seg = i & 7;
            const int so = r * ATS + seg * 8;
            const size_t gk = (size_t)(kb + r) * HD + seg * 8;
            const size_t gv = (size_t)r * SDIM + kb + seg * 8;
            uint4 v;
            v = *(const uint4*)(Kh + gk);
            *(uint2*)(sm + SK_H + so) = make_uint2(v.x, v.y);
            *(uint2*)(sm + SK_H + so + 4) = make_uint2(v.z, v.w);
            v = *(const uint4*)(Kl + gk);
            *(uint2*)(sm + SK_L + so) = make_uint2(v.x, v.y);
            *(uint2*)(sm + SK_L + so + 4) = make_uint2(v.z, v.w);
            v = *(const uint4*)(Vh + gv);
            *(uint2*)(sm + SV_H + so) = make_uint2(v.x, v.y);
            *(uint2*)(sm + SV_H + so + 4) = make_uint2(v.z, v.w);
            v = *(const uint4*)(Vl + gv);
            *(uint2*)(sm + SV_L + so) = make_uint2(v.x, v.y);
            *(uint2*)(sm + SV_L + so + 4) = make_uint2(v.z, v.w);
        }
        __syncthreads();

        // S = Q K^T : 16 q x 64 keys per warp
        float s[8][4];
#pragma unroll
        for (int i = 0; i < 8; i++)
#pragma unroll
            for (int j = 0; j < 4; j++) s[i][j] = 0.f;

#pragma unroll
        for (int kk = 0; kk < 4; kk++) {
            const int k0 = kk * 16;
            uint32_t qa_h[4], qa_l[4];
            const int r0 = (qw + lr) * ATS + k0 + lc;
            const int r8 = r0 + 8 * ATS;
            qa_h[0] = *(const uint32_t*)(sm + SQ_H + r0);
            qa_h[1] = *(const uint32_t*)(sm + SQ_H + r8);
            qa_h[2] = *(const uint32_t*)(sm + SQ_H + r0 + 8);
            qa_h[3] = *(const uint32_t*)(sm + SQ_H + r8 + 8);
            qa_l[0] = *(const uint32_t*)(sm + SQ_L + r0);
            qa_l[1] = *(const uint32_t*)(sm + SQ_L + r8);
            qa_l[2] = *(const uint32_t*)(sm + SQ_L + r0 + 8);
            qa_l[3] = *(const uint32_t*)(sm + SQ_L + r8 + 8);
#pragma unroll
            for (int ni = 0; ni < 8; ni++) {
                const int c0 = (ni * 8 + lr) * ATS + k0 + lc;
                uint32_t kb_h[2], kb_l[2];
                kb_h[0] = *(const uint32_t*)(sm + SK_H + c0);
                kb_h[1] = *(const uint32_t*)(sm + SK_H + c0 + 8);
                kb_l[0] = *(const uint32_t*)(sm + SK_L + c0);
                kb_l[1] = *(const uint32_t*)(sm + SK_L + c0 + 8);
                mma16816(s[ni], qa_h, kb_h);
                mma16816(s[ni], qa_h, kb_l);
                mma16816(s[ni], qa_l, kb_h);
            }
        }

        // Online softmax (rows lr and lr+8 within warp's 16 q)
        float mx0 = -1e30f, mx1 = -1e30f;
#pragma unroll
        for (int ni = 0; ni < 8; ni++) {
#pragma unroll
            for (int j = 0; j < 4; j++) s[ni][j] *= 0.125f;
            mx0 = fmaxf(mx0, fmaxf(s[ni][0], s[ni][1]));
            mx1 = fmaxf(mx1, fmaxf(s[ni][2], s[ni][3]));
        }
#pragma unroll
        for (int off = 1; off < 4; off <<= 1) {
            mx0 = fmaxf(mx0, __shfl_xor_sync(0xffffffffu, mx0, off));
            mx1 = fmaxf(mx1, __shfl_xor_sync(0xffffffffu, mx1, off));
        }
        const float mn0 = fmaxf(m0, mx0);
        const float mn1 = fmaxf(m1, mx1);
        const float al0 = __expf(m0 - mn0);
        const float al1 = __expf(m1 - mn1);
        m0 = mn0; m1 = mn1;

        float ls0 = 0.f, ls1 = 0.f;
#pragma unroll
        for (int ni = 0; ni < 8; ni++) {
            s[ni][0] = __expf(s[ni][0] - mn0);
            s[ni][1] = __expf(s[ni][1] - mn0);
            s[ni][2] = __expf(s[ni][2] - mn1);
            s[ni][3] = __expf(s[ni][3] - mn1);
            ls0 += s[ni][0] + s[ni][1];
            ls1 += s[ni][2] + s[ni][3];
        }
#pragma unroll
        for (int off = 1; off < 4; off <<= 1) {
            ls0 += __shfl_xor_sync(0xffffffffu, ls0, off);
            ls1 += __shfl_xor_sync(0xffffffffu, ls1, off);
        }
        l0 = l0 * al0 + ls0;
        l1 = l1 * al1 + ls1;
#pragma unroll
        for (int ni = 0; ni < 8; ni++) {
            o[ni][0] *= al0; o[ni][1] *= al0;
            o[ni][2] *= al1; o[ni][3] *= al1;
        }

        // O += P V : repack P c-frags -> a-frags with hi/lo split
#pragma unroll
        for (int j = 0; j < 4; j++) {
            float p00 = s[2*j][0],   p01 = s[2*j][1],   p02 = s[2*j][2],   p03 = s[2*j][3];
            float p10 = s[2*j+1][0], p11 = s[2*j+1][1], p12 = s[2*j+1][2], p13 = s[2*j+1][3];
            float h00 = __bfloat162float(__float2bfloat16(p00));
            float h01 = __bfloat162float(__float2bfloat16(p01));
            float h02 = __bfloat162float(__float2bfloat16(p02));
            float h03 = __bfloat162float(__float2bfloat16(p03));
            float h10 = __bfloat162float(__float2bfloat16(p10));
            float h11 = __bfloat162float(__float2bfloat16(p11));
            float h12 = __bfloat162float(__float2bfloat16(p12));
            float h13 = __bfloat162float(__float2bfloat16(p13));
            uint32_t pa_h[4], pa_l[4];
            pa_h[0] = pack_bf16(p00, p01);
            pa_h[1] = pack_bf16(p02, p03);
            pa_h[2] = pack_bf16(p10, p11);
            pa_h[3] = pack_bf16(p12, p13);
            pa_l[0] = pack_bf16(p00 - h00, p01 - h01);
            pa_l[1] = pack_bf16(p02 - h02, p03 - h03);
            pa_l[2] = pack_bf16(p10 - h10, p11 - h11);
            pa_l[3] = pack_bf16(p12 - h12, p13 - h13);
#pragma unroll
            for (int ni = 0; ni < 8; ni++) {
                const int c0 = (ni * 8 + lr) * ATS + j * 16 + lc;
                uint32_t vb_h[2], vb_l[2];
                vb_h[0] = *(const uint32_t*)(sm + SV_H + c0);
                vb_h[1] = *(const uint32_t*)(sm + SV_H + c0 + 8);
                vb_l[0] = *(const uint32_t*)(sm + SV_L + c0);
                vb_l[1] = *(const uint32_t*)(sm + SV_L + c0 + 8);
                mma16816(o[ni], pa_h, vb_h);
                mma16816(o[ni], pa_h, vb_l);
                mma16816(o[ni], pa_l, vb_h);
            }
        }
    }

    // Epilogue: normalize, split to bf16 hi/lo, write ctx [b,s,D] head-merged
    const float inv0 = 1.f / l0;
    const float inv1 = 1.f / l1;
    const int b = bh >> 4;
    const int h = bh & (HNUM - 1);
    const int s0 = qbase + qw + lr;
    const int s1 = s0 + 8;
#pragma unroll
    for (int ni = 0; ni < 8; ni++) {
        const int col = h * HD + ni * 8 + lc;
        {
            const float v0 = o[ni][0] * inv0, v1 = o[ni][1] * inv0;
            const float h0 = __bfloat162float(__float2bfloat16(v0));
            const float h1 = __bfloat162float(__float2bfloat16(v1));
            const size_t d = (size_t)(b * SDIM + s0) * DDIM + col;
            *(uint32_t*)(g_Xh + d) = pack_bf16(v0, v1);
            *(uint32_t*)(g_Xl + d) = pack_bf16(v0 - h0, v1 - h1);
        }
        {
            const float v0 = o[ni][2] * inv1, v1 = o[ni][3] * inv1;
            const float h0 = __bfloat162float(__float2bfloat16(v0));
            const float h1 = __bfloat162float(__float2bfloat16(v1));
            const size_t d = (size_t)(b * SDIM + s1) * DDIM + col;
            *(uint32_t*)(g_Xh + d) = pack_bf16(v0, v1);
            *(uint32_t*)(g_Xl + d) = pack_bf16(v0 - h0, v1 - h1);
        }
    }
}

// ---------------------------------------------------------------------------
// Launch
// ---------------------------------------------------------------------------
extern "C" void kernel_launch(void* const* d_in, const int* in_sizes, int n_in,
                              void* d_out, int out_size)
{
    const float* x  = (const float*)d_in[0];
    const float* Wq = (const float*)d_in[1];
    const float* bq = (const float*)d_in[2];
    const float* Wk = (const float*)d_in[3];
    const float* bk = (const float*)d_in[4];
    const float* Wv = (const float*)d_in[5];
    const float* bv = (const float*)d_in[6];
    const float* Wo = (const float*)d_in[7];
    const float* bo = (const float*)d_in[8];

    __nv_bfloat16 *xh, *xl, *wth, *wtl, *qh, *ql, *kh, *kl, *vth, *vtl;
    cudaGetSymbolAddress((void**)&xh,  g_Xh);
    cudaGetSymbolAddress((void**)&xl,  g_Xl);
    cudaGetSymbolAddress((void**)&wth, g_Wth);
    cudaGetSymbolAddress((void**)&wtl, g_Wtl);
    cudaGetSymbolAddress((void**)&qh,  g_Qh);
    cudaGetSymbolAddress((void**)&ql,  g_Ql);
    cudaGetSymbolAddress((void**)&kh,  g_Kh);
    cudaGetSymbolAddress((void**)&kl,  g_Kl);
    cudaGetSymbolAddress((void**)&vth, g_VTh);
    cudaGetSymbolAddress((void**)&vtl, g_VTl);

    cudaFuncSetAttribute(gemm_mma, cudaFuncAttributeMaxDynamicSharedMemorySize, GEMM_SMEM);
    cudaFuncSetAttribute(attn_mma, cudaFuncAttributeMaxDynamicSharedMemorySize, ATTN_SMEM);

    const int N_ELEM = ROWS * DDIM;
    const size_t WSZ = (size_t)DDIM * DDIM;

    convert_split<<<2048, 256>>>(x, xh, xl, N_ELEM);
    dim3 tg(32, 32), tb(32, 32);
    transpose_split<<<tg, tb>>>(Wq, wth + 0 * WSZ, wtl + 0 * WSZ);
    transpose_split<<<tg, tb>>>(Wk, wth + 1 * WSZ, wtl + 1 * WSZ);
    transpose_split<<<tg, tb>>>(Wv, wth + 2 * WSZ, wtl + 2 * WSZ);
    transpose_split<<<tg, tb>>>(Wo, wth + 3 * WSZ, wtl + 3 * WSZ);

    dim3 gg(DDIM / 128, ROWS / 128);   // (8, 64)
    gemm_mma<<<gg, 256, GEMM_SMEM>>>(xh, xl, wth + 0 * WSZ, wtl + 0 * WSZ, bq, nullptr, qh,  ql,  1);
    gemm_mma<<<gg, 256, GEMM_SMEM>>>(xh, xl, wth + 1 * WSZ, wtl + 1 * WSZ, bk, nullptr, kh,  kl,  1);
    gemm_mma<<<gg, 256, GEMM_SMEM>>>(xh, xl, wth + 2 * WSZ, wtl + 2 * WSZ, bv, nullptr, vth, vtl, 2);

    attn_mma<<<dim3(SDIM / 128, BH), 256, ATTN_SMEM>>>();   // (16, 64)

    gemm_mma<<<gg, 256, GEMM_SMEM>>>(xh, xl, wth + 3 * WSZ, wtl + 3 * WSZ, bo, (float*)d_out, nullptr, nullptr, 0);
}

// round 7
// speedup vs baseline: 2.9565x; 1.2910x over previous
#include <cuda_runtime.h>
#include <cuda_bf16.h>
#include <math.h>
#include <cstdint>

#define BDIM 4
#define SDIM 2048
#define DDIM 1024
#define HNUM 16
#define HD   64
#define ROWS (BDIM * SDIM)   // 8192
#define BH   (BDIM * HNUM)   // 64

// ---------------------------------------------------------------------------
// Scratch
// ---------------------------------------------------------------------------
__device__ __nv_bfloat16 g_Xh[(size_t)ROWS * DDIM];
__device__ __nv_bfloat16 g_Xl[(size_t)ROWS * DDIM];
__device__ __nv_bfloat16 g_Wth[4][(size_t)DDIM * DDIM];   // W^T hi, [n][k]
__device__ __nv_bfloat16 g_Wtl[4][(size_t)DDIM * DDIM];
__device__ __nv_bfloat16 g_Qh[(size_t)BH * SDIM * HD];    // [bh][s][hd] (pre-scaled)
__device__ __nv_bfloat16 g_Ql[(size_t)BH * SDIM * HD];
__device__ __nv_bfloat16 g_Kh[(size_t)BH * SDIM * HD];
__device__ __nv_bfloat16 g_Kl[(size_t)BH * SDIM * HD];
__device__ __nv_bfloat16 g_VTh[(size_t)BH * HD * SDIM];   // [bh][hd][s]
__device__ __nv_bfloat16 g_VTl[(size_t)BH * HD * SDIM];

// ---------------------------------------------------------------------------
// Helpers: mma.sync m16n8k16 bf16 row.col, cp.async, packing
// ---------------------------------------------------------------------------
__device__ __forceinline__ void mma16816(float* c, const uint32_t* a, const uint32_t* b)
{
    asm volatile(
        "mma.sync.aligned.m16n8k16.row.col.f32.bf16.bf16.f32 "
        "{%0,%1,%2,%3}, {%4,%5,%6,%7}, {%8,%9}, {%0,%1,%2,%3};"
        : "+f"(c[0]), "+f"(c[1]), "+f"(c[2]), "+f"(c[3])
        : "r"(a[0]), "r"(a[1]), "r"(a[2]), "r"(a[3]), "r"(b[0]), "r"(b[1]));
}

__device__ __forceinline__ uint32_t pack_bf16(float lo, float hi)
{
    uint32_t r;
    asm("cvt.rn.bf16x2.f32 %0, %1, %2;" : "=r"(r) : "f"(hi), "f"(lo));
    return r;
}

__device__ __forceinline__ void cpa16(void* sptr, const void* gptr)
{
    uint32_t s = (uint32_t)__cvta_generic_to_shared(sptr);
    asm volatile("cp.async.cg.shared.global [%0], [%1], 16;" :: "r"(s), "l"(gptr));
}
#define CPA_COMMIT() asm volatile("cp.async.commit_group;" ::: "memory")
#define CPA_WAIT(n)  asm volatile("cp.async.wait_group %0;" :: "n"(n) : "memory")

// ---------------------------------------------------------------------------
// Prep kernels
// ---------------------------------------------------------------------------
__global__ void convert_split(const float* __restrict__ src,
                              __nv_bfloat16* __restrict__ hi,
                              __nv_bfloat16* __restrict__ lo, int n)
{
    for (int i = blockIdx.x * blockDim.x + threadIdx.x; i < n;
         i += gridDim.x * blockDim.x) {
        float x = src[i];
        __nv_bfloat16 h = __float2bfloat16(x);
        hi[i] = h;
        lo[i] = __float2bfloat16(x - __bfloat162float(h));
    }
}

__global__ void transpose_split4(
    const float* __restrict__ W0, const float* __restrict__ W1,
    const float* __restrict__ W2, const float* __restrict__ W3,
    __nv_bfloat16* __restrict__ ThB, __nv_bfloat16* __restrict__ TlB)
{
    __shared__ float tile[32][33];
    const int z = blockIdx.z;
    const float* W = (z == 0) ? W0 : (z == 1) ? W1 : (z == 2) ? W2 : W3;
    __nv_bfloat16* Th = ThB + (size_t)z * DDIM * DDIM;
    __nv_bfloat16* Tl = TlB + (size_t)z * DDIM * DDIM;
    const int tx = threadIdx.x, ty = threadIdx.y;
    tile[ty][tx] = W[(size_t)(blockIdx.y * 32 + ty) * DDIM + blockIdx.x * 32 + tx];
    __syncthreads();
    const int on = blockIdx.x * 32 + ty;
    const int ok = blockIdx.y * 32 + tx;
    float v = tile[tx][ty];
    __nv_bfloat16 h = __float2bfloat16(v);
    Th[(size_t)on * DDIM + ok] = h;
    Tl[(size_t)on * DDIM + ok] = __float2bfloat16(v - __bfloat162float(h));
}

// ---------------------------------------------------------------------------
// HMMA GEMM, bf16 hi/lo 3-pass split, cp.async 2-stage pipeline.
// CTA tile 128x128, K-chunk 64, 8 warps. Stage = Ah|Al|Bh|Bl tiles (73728 B).
// mode 0: fp32 out; mode 1: bf16 hi/lo [b,h,s,hd]; mode 2: hi/lo [b,h,hd,s]
// ---------------------------------------------------------------------------
#define AKS 72
#define TILE_E (128 * AKS)
#define STG_E  (4 * TILE_E)              // elements per stage
#define GEMM_SMEM (2 * STG_E * 2)        // 147456 bytes

__global__ __launch_bounds__(256) void gemm_mma(
    const __nv_bfloat16* __restrict__ Ah_g, const __nv_bfloat16* __restrict__ Al_g,
    const __nv_bfloat16* __restrict__ Bh_g, const __nv_bfloat16* __restrict__ Bl_g,
    const float* __restrict__ bias, float oscale, float* __restrict__ outF,
    __nv_bfloat16* __restrict__ outH, __nv_bfloat16* __restrict__ outL, int mode)
{
    extern __shared__ char smem[];
    __nv_bfloat16* sbase = (__nv_bfloat16*)smem;

    const int t    = threadIdx.x;
    const int wid  = t >> 5;
    const int lane = t & 31;
    const int wr   = wid & 1;
    const int wc   = wid >> 1;
    const int lr   = lane >> 2;
    const int lc   = (lane & 3) << 1;
    const int bn = blockIdx.x * 128;
    const int bm = blockIdx.y * 128;

    // issue cp.async loads of one 64-wide K chunk into stage buffer
    auto issue_chunk = [&](int c, int stg) {
        __nv_bfloat16* s0 = sbase + stg * STG_E;
        const int k0g = c * 64;
#pragma unroll
        for (int it = 0; it < 4; it++) {
            const int i = t + it * 256;
            const int r = i >> 3, seg = i & 7;
            const size_t ga = (size_t)(bm + r) * DDIM + k0g + seg * 8;
            const size_t gb = (size_t)(bn + r) * DDIM + k0g + seg * 8;
            const int so = r * AKS + seg * 8;
            cpa16(s0 + so,              Ah_g + ga);
            cpa16(s0 + TILE_E + so,     Al_g + ga);
            cpa16(s0 + 2 * TILE_E + so, Bh_g + gb);
            cpa16(s0 + 3 * TILE_E + so, Bl_g + gb);
        }
    };

    float acc[4][4][4];
#pragma unroll
    for (int i = 0; i < 4; i++)
#pragma unroll
        for (int j = 0; j < 4; j++)
#pragma unroll
            for (int r = 0; r < 4; r++) acc[i][j][r] = 0.f;

    issue_chunk(0, 0);
    CPA_COMMIT();

    for (int c = 0; c < 16; c++) {
        if (c < 15) { issue_chunk(c + 1, (c + 1) & 1); CPA_COMMIT(); }
        if (c < 15) { CPA_WAIT(1); } else { CPA_WAIT(0); }
        __syncthreads();

        const __nv_bfloat16* sAh = sbase + (c & 1) * STG_E;
        const __nv_bfloat16* sAl = sAh + TILE_E;
        const __nv_bfloat16* sBh = sAh + 2 * TILE_E;
        const __nv_bfloat16* sBl = sAh + 3 * TILE_E;

#pragma unroll
        for (int kk = 0; kk < 4; kk++) {
            const int k0 = kk * 16;
            uint32_t ah[4][4], al[4][4], bh[4][2], bl[4][2];
#pragma unroll
            for (int mi = 0; mi < 4; mi++) {
                const int r0 = (wr * 64 + mi * 16 + lr) * AKS + k0 + lc;
                const int r8 = r0 + 8 * AKS;
                ah[mi][0] = *(const uint32_t*)(sAh + r0);
                ah[mi][1] = *(const uint32_t*)(sAh + r8);
                ah[mi][2] = *(const uint32_t*)(sAh + r0 + 8);
                ah[mi][3] = *(const uint32_t*)(sAh + r8 + 8);
                al[mi][0] = *(const uint32_t*)(sAl + r0);
                al[mi][1] = *(const uint32_t*)(sAl + r8);
                al[mi][2] = *(const uint32_t*)(sAl + r0 + 8);
                al[mi][3] = *(const uint32_t*)(sAl + r8 + 8);
            }
#pragma unroll
            for (int ni = 0; ni < 4; ni++) {
                const int c0 = (wc * 32 + ni * 8 + lr) * AKS + k0 + lc;
                bh[ni][0] = *(const uint32_t*)(sBh + c0);
                bh[ni][1] = *(const uint32_t*)(sBh + c0 + 8);
                bl[ni][0] = *(const uint32_t*)(sBl + c0);
                bl[ni][1] = *(const uint32_t*)(sBl + c0 + 8);
            }
#pragma unroll
            for (int mi = 0; mi < 4; mi++)
#pragma unroll
                for (int ni = 0; ni < 4; ni++) {
                    mma16816(acc[mi][ni], ah[mi], bh[ni]);
                    mma16816(acc[mi][ni], ah[mi], bl[ni]);
                    mma16816(acc[mi][ni], al[mi], bh[ni]);
                }
        }
        __syncthreads();
    }

    // stage C through smem for coalesced writes
    float* Ds = (float*)smem;   // stride 133
#pragma unroll
    for (int mi = 0; mi < 4; mi++) {
        const int r = wr * 64 + mi * 16 + lr;
#pragma unroll
        for (int ni = 0; ni < 4; ni++) {
            const int cc = wc * 32 + ni * 8 + lc;
            Ds[r * 133 + cc]           = acc[mi][ni][0];
            Ds[r * 133 + cc + 1]       = acc[mi][ni][1];
            Ds[(r + 8) * 133 + cc]     = acc[mi][ni][2];
            Ds[(r + 8) * 133 + cc + 1] = acc[mi][ni][3];
        }
    }
    __syncthreads();

    if (mode == 0) {
        for (int idx = t; idx < 128 * 128; idx += 256) {
            const int r = idx >> 7, cc = idx & 127;
            outF[(size_t)(bm + r) * DDIM + bn + cc] =
                (Ds[r * 133 + cc] + __ldg(bias + bn + cc)) * oscale;
        }
    } else if (mode == 1) {
        for (int idx = t; idx < 128 * 128; idx += 256) {
            const int r = idx >> 7, cc = idx & 127;
            const int row = bm + r, col = bn + cc;
            const float v = (Ds[r * 133 + cc] + __ldg(bias + col)) * oscale;
            const int b = row >> 11, s = row & (SDIM - 1);
            const int h = col >> 6,  hd = col & (HD - 1);
            const size_t dst = (size_t)((b * HNUM + h) * SDIM + s) * HD + hd;
            __nv_bfloat16 hh = __float2bfloat16(v);
            outH[dst] = hh;
            outL[dst] = __float2bfloat16(v - __bfloat162float(hh));
        }
    } else {
        for (int idx = t; idx < 128 * 128; idx += 256) {
            const int r = idx & 127, cc = idx >> 7;
            const int row = bm + r, col = bn + cc;
            const float v = (Ds[r * 133 + cc] + __ldg(bias + col)) * oscale;
            const int b = row >> 11, s = row & (SDIM - 1);
            const int h = col >> 6,  hd = col & (HD - 1);
            const size_t dst = (size_t)((b * HNUM + h) * HD + hd) * SDIM + s;
            __nv_bfloat16 hh = __float2bfloat16(v);
            outH[dst] = hh;
            outL[dst] = __float2bfloat16(v - __bfloat162float(hh));
        }
    }
}

// ---------------------------------------------------------------------------
// Flash attention, mma.sync hi/lo split, cp.async 2-stage KV pipeline.
// CTA: one (b,h) x 128 queries; 8 warps x 16 q-rows; key chunks of 64.
// Q pre-scaled by 1/8 in projection. smem = Q(36864) + 2 KV stages(36864 ea).
// ---------------------------------------------------------------------------
#define ATS 72
#define QSZ_E   (2 * 128 * ATS)          // Q hi+lo elements
#define KVSTG_E (4 * 64 * ATS)           // K hi/lo + V hi/lo per stage
#define ATTN_SMEM ((QSZ_E + 2 * KVSTG_E) * 2)   // 110592 bytes

__global__ __launch_bounds__(256) void attn_mma()
{
    extern __shared__ char smraw[];
    __nv_bfloat16* sm = (__nv_bfloat16*)smraw;
    __nv_bfloat16* sQh = sm;
    __nv_bfloat16* sQl = sm + 128 * ATS;

    const int t    = threadIdx.x;
    const int wid  = t >> 5;
    const int lane = t & 31;
    const int lr   = lane >> 2;
    const int lc   = (lane & 3) << 1;
    const int bh    = blockIdx.y;
    const int qbase = blockIdx.x * 128;
    const int qw    = wid * 16;

    const __nv_bfloat16* Qh = g_Qh + (size_t)bh * SDIM * HD;
    const __nv_bfloat16* Ql = g_Ql + (size_t)bh * SDIM * HD;
    const __nv_bfloat16* Kh = g_Kh + (size_t)bh * SDIM * HD;
    const __nv_bfloat16* Kl = g_Kl + (size_t)bh * SDIM * HD;
    const __nv_bfloat16* Vh = g_VTh + (size_t)bh * HD * SDIM;
    const __nv_bfloat16* Vl = g_VTl + (size_t)bh * HD * SDIM;

    auto issue_kv = [&](int c, int stg) {
        __nv_bfloat16* s0 = sm + QSZ_E + stg * KVSTG_E;
        const int kb = c * 64;
#pragma unroll
        for (int it = 0; it < 2; it++) {
            const int i = t + it * 256;
            const int r = i >> 3, seg = i & 7;
            const int so = r * ATS + seg * 8;
            const size_t gk = (size_t)(kb + r) * HD + seg * 8;
            const size_t gv = (size_t)r * SDIM + kb + seg * 8;
            cpa16(s0 + so,               Kh + gk);
            cpa16(s0 + 64 * ATS + so,    Kl + gk);
            cpa16(s0 + 2 * 64 * ATS + so, Vh + gv);
            cpa16(s0 + 3 * 64 * ATS + so, Vl + gv);
        }
    };

    // Prologue: Q tile + KV chunk 0 in one cp.async group
#pragma unroll
    for (int it = 0; it < 4; it++) {
        const int i = t + it * 256;
        const int r = i >> 3, seg = i & 7;
        const size_t g = (size_t)(qbase + r) * HD + seg * 8;
        const int so = r * ATS + seg * 8;
        cpa16(sQh + so, Qh + g);
        cpa16(sQl + so, Ql + g);
    }
    issue_kv(0, 0);
    CPA_COMMIT();

    float o[8][4];
#pragma unroll
    for (int i = 0; i < 8; i++)
#pragma unroll
        for (int j = 0; j < 4; j++) o[i][j] = 0.f;
    float m0 = -1e30f, m1 = -1e30f, l0 = 0.f, l1 = 0.f;

    for (int c = 0; c < 32; c++) {
        if (c < 31) { issue_kv(c + 1, (c + 1) & 1); CPA_COMMIT(); }
        if (c < 31) { CPA_WAIT(1); } else { CPA_WAIT(0); }
        __syncthreads();

        const __nv_bfloat16* sKh = sm + QSZ_E + (c & 1) * KVSTG_E;
        const __nv_bfloat16* sKl = sKh + 64 * ATS;
        const __nv_bfloat16* sVh = sKh + 2 * 64 * ATS;
        const __nv_bfloat16* sVl = sKh + 3 * 64 * ATS;

        // S = Q K^T  (Q pre-scaled by 1/8)
        float s[8][4];
#pragma unroll
        for (int i = 0; i < 8; i++)
#pragma unroll
            for (int j = 0; j < 4; j++) s[i][j] = 0.f;

#pragma unroll
        for (int kk = 0; kk < 4; kk++) {
            const int k0 = kk * 16;
            uint32_t qa_h[4], qa_l[4];
            const int r0 = (qw + lr) * ATS + k0 + lc;
            const int r8 = r0 + 8 * ATS;
            qa_h[0] = *(const uint32_t*)(sQh + r0);
            qa_h[1] = *(const uint32_t*)(sQh + r8);
            qa_h[2] = *(const uint32_t*)(sQh + r0 + 8);
            qa_h[3] = *(const uint32_t*)(sQh + r8 + 8);
            qa_l[0] = *(const uint32_t*)(sQl + r0);
            qa_l[1] = *(const uint32_t*)(sQl + r8);
            qa_l[2] = *(const uint32_t*)(sQl + r0 + 8);
            qa_l[3] = *(const uint32_t*)(sQl + r8 + 8);
#pragma unroll
            for (int ni = 0; ni < 8; ni++) {
                const int c0 = (ni * 8 + lr) * ATS + k0 + lc;
                uint32_t kb_h[2], kb_l[2];
                kb_h[0] = *(const uint32_t*)(sKh + c0);
                kb_h[1] = *(const uint32_t*)(sKh + c0 + 8);
                kb_l[0] = *(const uint32_t*)(sKl + c0);
                kb_l[1] = *(const uint32_t*)(sKl + c0 + 8);
                mma16816(s[ni], qa_h, kb_h);
                mma16816(s[ni], qa_h, kb_l);
                mma16816(s[ni], qa_l, kb_h);
            }
        }

        // Online softmax (rows lr, lr+8)
        float mx0 = -1e30f, mx1 = -1e30f;
#pragma unroll
        for (int ni = 0; ni < 8; ni++) {
            mx0 = fmaxf(mx0, fmaxf(s[ni][0], s[ni][1]));
            mx1 = fmaxf(mx1, fmaxf(s[ni][2], s[ni][3]));
        }
#pragma unroll
        for (int off = 1; off < 4; off <<= 1) {
            mx0 = fmaxf(mx0, __shfl_xor_sync(0xffffffffu, mx0, off));
            mx1 = fmaxf(mx1, __shfl_xor_sync(0xffffffffu, mx1, off));
        }
        const float mn0 = fmaxf(m0, mx0);
        const float mn1 = fmaxf(m1, mx1);
        const float al0 = __expf(m0 - mn0);
        const float al1 = __expf(m1 - mn1);
        m0 = mn0; m1 = mn1;

        float ls0 = 0.f, ls1 = 0.f;
#pragma unroll
        for (int ni = 0; ni < 8; ni++) {
            s[ni][0] = __expf(s[ni][0] - mn0);
            s[ni][1] = __expf(s[ni][1] - mn0);
            s[ni][2] = __expf(s[ni][2] - mn1);
            s[ni][3] = __expf(s[ni][3] - mn1);
            ls0 += s[ni][0] + s[ni][1];
            ls1 += s[ni][2] + s[ni][3];
        }
#pragma unroll
        for (int off = 1; off < 4; off <<= 1) {
            ls0 += __shfl_xor_sync(0xffffffffu, ls0, off);
            ls1 += __shfl_xor_sync(0xffffffffu, ls1, off);
        }
        l0 = l0 * al0 + ls0;
        l1 = l1 * al1 + ls1;
#pragma unroll
        for (int ni = 0; ni < 8; ni++) {
            o[ni][0] *= al0; o[ni][1] *= al0;
            o[ni][2] *= al1; o[ni][3] *= al1;
        }

        // O += P V  (P repack c-frag -> a-frag, hi/lo split)
#pragma unroll
        for (int j = 0; j < 4; j++) {
            float p00 = s[2*j][0],   p01 = s[2*j][1],   p02 = s[2*j][2],   p03 = s[2*j][3];
            float p10 = s[2*j+1][0], p11 = s[2*j+1][1], p12 = s[2*j+1][2], p13 = s[2*j+1][3];
            float h00 = __bfloat162float(__float2bfloat16(p00));
            float h01 = __bfloat162float(__float2bfloat16(p01));
            float h02 = __bfloat162float(__float2bfloat16(p02));
            float h03 = __bfloat162float(__float2bfloat16(p03));
            float h10 = __bfloat162float(__float2bfloat16(p10));
            float h11 = __bfloat162float(__float2bfloat16(p11));
            float h12 = __bfloat162float(__float2bfloat16(p12));
            float h13 = __bfloat162float(__float2bfloat16(p13));
            uint32_t pa_h[4], pa_l[4];
            pa_h[0] = pack_bf16(p00, p01);
            pa_h[1] = pack_bf16(p02, p03);
            pa_h[2] = pack_bf16(p10, p11);
            pa_h[3] = pack_bf16(p12, p13);
            pa_l[0] = pack_bf16(p00 - h00, p01 - h01);
            pa_l[1] = pack_bf16(p02 - h02, p03 - h03);
            pa_l[2] = pack_bf16(p10 - h10, p11 - h11);
            pa_l[3] = pack_bf16(p12 - h12, p13 - h13);
#pragma unroll
            for (int ni = 0; ni < 8; ni++) {
                const int c0 = (ni * 8 + lr) * ATS + j * 16 + lc;
                uint32_t vb_h[2], vb_l[2];
                vb_h[0] = *(const uint32_t*)(sVh + c0);
                vb_h[1] = *(const uint32_t*)(sVh + c0 + 8);
                vb_l[0] = *(const uint32_t*)(sVl + c0);
                vb_l[1] = *(const uint32_t*)(sVl + c0 + 8);
                mma16816(o[ni], pa_h, vb_h);
                mma16816(o[ni], pa_h, vb_l);
                mma16816(o[ni], pa_l, vb_h);
            }
        }
        __syncthreads();
    }

    // Epilogue: normalize, split to bf16 hi/lo, write ctx [b,s,D]
    const float inv0 = 1.f / l0;
    const float inv1 = 1.f / l1;
    const int b = bh >> 4;
    const int h = bh & (HNUM - 1);
    const int s0 = qbase + qw + lr;
    const int s1 = s0 + 8;
#pragma unroll
    for (int ni = 0; ni < 8; ni++) {
        const int col = h * HD + ni * 8 + lc;
        {
            const float v0 = o[ni][0] * inv0, v1 = o[ni][1] * inv0;
            const float h0 = __bfloat162float(__float2bfloat16(v0));
            const float h1 = __bfloat162float(__float2bfloat16(v1));
            const size_t d = (size_t)(b * SDIM + s0) * DDIM + col;
            *(uint32_t*)(g_Xh + d) = pack_bf16(v0, v1);
            *(uint32_t*)(g_Xl + d) = pack_bf16(v0 - h0, v1 - h1);
        }
        {
            const float v0 = o[ni][2] * inv1, v1 = o[ni][3] * inv1;
            const float h0 = __bfloat162float(__float2bfloat16(v0));
            const float h1 = __bfloat162float(__float2bfloat16(v1));
            const size_t d = (size_t)(b * SDIM + s1) * DDIM + col;
            *(uint32_t*)(g_Xh + d) = pack_bf16(v0, v1);
            *(uint32_t*)(g_Xl + d) = pack_bf16(v0 - h0, v1 - h1);
        }
    }
}

// ---------------------------------------------------------------------------
// Launch
// ---------------------------------------------------------------------------
extern "C" void kernel_launch(void* const* d_in, const int* in_sizes, int n_in,
                              void* d_out, int out_size)
{
    const float* x  = (const float*)d_in[0];
    const float* Wq = (const float*)d_in[1];
    const float* bq = (const float*)d_in[2];
    const float* Wk = (const float*)d_in[3];
    const float* bk = (const float*)d_in[4];
    const float* Wv = (const float*)d_in[5];
    const float* bv = (const float*)d_in[6];
    const float* Wo = (const float*)d_in[7];
    const float* bo = (const float*)d_in[8];

    __nv_bfloat16 *xh, *xl, *wth, *wtl, *qh, *ql, *kh, *kl, *vth, *vtl;
    cudaGetSymbolAddress((void**)&xh,  g_Xh);
    cudaGetSymbolAddress((void**)&xl,  g_Xl);
    cudaGetSymbolAddress((void**)&wth, g_Wth);
    cudaGetSymbolAddress((void**)&wtl, g_Wtl);
    cudaGetSymbolAddress((void**)&qh,  g_Qh);
    cudaGetSymbolAddress((void**)&ql,  g_Ql);
    cudaGetSymbolAddress((void**)&kh,  g_Kh);
    cudaGetSymbolAddress((void**)&kl,  g_Kl);
    cudaGetSymbolAddress((void**)&vth, g_VTh);
    cudaGetSymbolAddress((void**)&vtl, g_VTl);

    cudaFuncSetAttribute(gemm_mma, cudaFuncAttributeMaxDynamicSharedMemorySize, GEMM_SMEM);
    cudaFuncSetAttribute(attn_mma, cudaFuncAttributeMaxDynamicSharedMemorySize, ATTN_SMEM);

    const int N_ELEM = ROWS * DDIM;
    const size_t WSZ = (size_t)DDIM * DDIM;

    convert_split<<<2048, 256>>>(x, xh, xl, N_ELEM);
    transpose_split4<<<dim3(32, 32, 4), dim3(32, 32)>>>(Wq, Wk, Wv, Wo, wth, wtl);

    dim3 gg(DDIM / 128, ROWS / 128);   // (8, 64)
    gemm_mma<<<gg, 256, GEMM_SMEM>>>(xh, xl, wth + 0 * WSZ, wtl + 0 * WSZ, bq, 0.125f, nullptr, qh,  ql,  1);
    gemm_mma<<<gg, 256, GEMM_SMEM>>>(xh, xl, wth + 1 * WSZ, wtl + 1 * WSZ, bk, 1.0f,   nullptr, kh,  kl,  1);
    gemm_mma<<<gg, 256, GEMM_SMEM>>>(xh, xl, wth + 2 * WSZ, wtl + 2 * WSZ, bv, 1.0f,   nullptr, vth, vtl, 2);

    attn_mma<<<dim3(SDIM / 128, BH), 256, ATTN_SMEM>>>();   // (16, 64)

    gemm_mma<<<gg, 256, GEMM_SMEM>>>(xh, xl, wth + 3 * WSZ, wtl + 3 * WSZ, bo, 1.0f, (float*)d_out, nullptr, nullptr, 0);
}

// round 9
// speedup vs baseline: 3.1274x; 1.0578x over previous
#include <cuda_runtime.h>
#include <cuda_bf16.h>
#include <math.h>
#include <cstdint>

#define BDIM 4
#define SDIM 2048
#define DDIM 1024
#define HNUM 16
#define HD   64
#define ROWS (BDIM * SDIM)   // 8192
#define BH   (BDIM * HNUM)   // 64

// ---------------------------------------------------------------------------
// Scratch
// ---------------------------------------------------------------------------
__device__ __nv_bfloat16 g_Xh[(size_t)ROWS * DDIM];
__device__ __nv_bfloat16 g_Xl[(size_t)ROWS * DDIM];
__device__ __nv_bfloat16 g_Wth[4][(size_t)DDIM * DDIM];   // W^T hi, [n][k]; QKVO contiguous
__device__ __nv_bfloat16 g_Wtl[4][(size_t)DDIM * DDIM];
__device__ __nv_bfloat16 g_Qh[(size_t)BH * SDIM * HD];    // [bh][s][hd] (pre-scaled 1/8)
__device__ __nv_bfloat16 g_Ql[(size_t)BH * SDIM * HD];
__device__ __nv_bfloat16 g_Kh[(size_t)BH * SDIM * HD];
__device__ __nv_bfloat16 g_Kl[(size_t)BH * SDIM * HD];
__device__ __nv_bfloat16 g_VTh[(size_t)BH * HD * SDIM];   // [bh][hd][s]
__device__ __nv_bfloat16 g_VTl[(size_t)BH * HD * SDIM];

// ---------------------------------------------------------------------------
// Helpers
// ---------------------------------------------------------------------------
__device__ __forceinline__ void mma16816(float* c, const uint32_t* a, const uint32_t* b)
{
    asm volatile(
        "mma.sync.aligned.m16n8k16.row.col.f32.bf16.bf16.f32 "
        "{%0,%1,%2,%3}, {%4,%5,%6,%7}, {%8,%9}, {%0,%1,%2,%3};"
        : "+f"(c[0]), "+f"(c[1]), "+f"(c[2]), "+f"(c[3])
        : "r"(a[0]), "r"(a[1]), "r"(a[2]), "r"(a[3]), "r"(b[0]), "r"(b[1]));
}

__device__ __forceinline__ uint32_t pack_bf16(float lo, float hi)
{
    uint32_t r;
    asm("cvt.rn.bf16x2.f32 %0, %1, %2;" : "=r"(r) : "f"(hi), "f"(lo));
    return r;
}

__device__ __forceinline__ void cpa16(void* sptr, const void* gptr)
{
    uint32_t s = (uint32_t)__cvta_generic_to_shared(sptr);
    asm volatile("cp.async.cg.shared.global [%0], [%1], 16;" :: "r"(s), "l"(gptr));
}
#define CPA_COMMIT() asm volatile("cp.async.commit_group;" ::: "memory")
#define CPA_WAIT(n)  asm volatile("cp.async.wait_group %0;" :: "n"(n) : "memory")

// ---------------------------------------------------------------------------
// Prep kernels
// ---------------------------------------------------------------------------
__global__ void convert_split(const float* __restrict__ src,
                              __nv_bfloat16* __restrict__ hi,
                              __nv_bfloat16* __restrict__ lo, int n)
{
    for (int i = blockIdx.x * blockDim.x + threadIdx.x; i < n;
         i += gridDim.x * blockDim.x) {
        float x = src[i];
        __nv_bfloat16 h = __float2bfloat16(x);
        hi[i] = h;
        lo[i] = __float2bfloat16(x - __bfloat162float(h));
    }
}

__global__ void transpose_split4(
    const float* __restrict__ W0, const float* __restrict__ W1,
    const float* __restrict__ W2, const float* __restrict__ W3,
    __nv_bfloat16* __restrict__ ThB, __nv_bfloat16* __restrict__ TlB)
{
    __shared__ float tile[32][33];
    const int z = blockIdx.z;
    const float* W = (z == 0) ? W0 : (z == 1) ? W1 : (z == 2) ? W2 : W3;
    __nv_bfloat16* Th = ThB + (size_t)z * DDIM * DDIM;
    __nv_bfloat16* Tl = TlB + (size_t)z * DDIM * DDIM;
    const int tx = threadIdx.x, ty = threadIdx.y;
    tile[ty][tx] = W[(size_t)(blockIdx.y * 32 + ty) * DDIM + blockIdx.x * 32 + tx];
    __syncthreads();
    const int on = blockIdx.x * 32 + ty;
    const int ok = blockIdx.y * 32 + tx;
    float v = tile[tx][ty];
    __nv_bfloat16 h = __float2bfloat16(v);
    Th[(size_t)on * DDIM + ok] = h;
    Tl[(size_t)on * DDIM + ok] = __float2bfloat16(v - __bfloat162float(h));
}

// ---------------------------------------------------------------------------
// Shared GEMM core: CTA tile 128x128, K-chunk 64, cp.async 2-stage, 8 warps.
// Pass-major mma ordering: 16 independent accumulators between reuse.
// B is indexed by rows (bn + r) — caller passes the BASE pointer.
// ---------------------------------------------------------------------------
#define AKS 72
#define TILE_E (128 * AKS)
#define STG_E  (4 * TILE_E)
#define GEMM_SMEM (2 * STG_E * 2)        // 147456 bytes

struct GemmCore {
    float acc[4][4][4];
};

__device__ __forceinline__ void gemm_core_run(
    char* smem, int t,
    const __nv_bfloat16* Ah_g, const __nv_bfloat16* Al_g,
    const __nv_bfloat16* Bh_g, const __nv_bfloat16* Bl_g,
    int bm, int bn, GemmCore& gc)
{
    __nv_bfloat16* sbase = (__nv_bfloat16*)smem;
    const int wid  = t >> 5;
    const int lane = t & 31;
    const int wr   = wid & 1;
    const int wc   = wid >> 1;
    const int lr   = lane >> 2;
    const int lc   = (lane & 3) << 1;

    auto issue_chunk = [&](int c, int stg) {
        __nv_bfloat16* s0 = sbase + stg * STG_E;
        const int k0g = c * 64;
#pragma unroll
        for (int it = 0; it < 4; it++) {
            const int i = t + it * 256;
            const int r = i >> 3, seg = i & 7;
            const size_t ga = (size_t)(bm + r) * DDIM + k0g + seg * 8;
            const size_t gb = (size_t)(bn + r) * DDIM + k0g + seg * 8;
            const int so = r * AKS + seg * 8;
            cpa16(s0 + so,              Ah_g + ga);
            cpa16(s0 + TILE_E + so,     Al_g + ga);
            cpa16(s0 + 2 * TILE_E + so, Bh_g + gb);
            cpa16(s0 + 3 * TILE_E + so, Bl_g + gb);
        }
    };

#pragma unroll
    for (int i = 0; i < 4; i++)
#pragma unroll
        for (int j = 0; j < 4; j++)
#pragma unroll
            for (int r = 0; r < 4; r++) gc.acc[i][j][r] = 0.f;

    issue_chunk(0, 0);
    CPA_COMMIT();

    for (int c = 0; c < 16; c++) {
        if (c < 15) { issue_chunk(c + 1, (c + 1) & 1); CPA_COMMIT(); CPA_WAIT(1); }
        else        { CPA_WAIT(0); }
        __syncthreads();

        const __nv_bfloat16* sAh = sbase + (c & 1) * STG_E;
        const __nv_bfloat16* sAl = sAh + TILE_E;
        const __nv_bfloat16* sBh = sAh + 2 * TILE_E;
        const __nv_bfloat16* sBl = sAh + 3 * TILE_E;

#pragma unroll
        for (int kk = 0; kk < 4; kk++) {
            const int k0 = kk * 16;
            uint32_t ah[4][4], al[4][4], bh[4][2], bl[4][2];
#pragma unroll
            for (int mi = 0; mi < 4; mi++) {
                const int r0 = (wr * 64 + mi * 16 + lr) * AKS + k0 + lc;
                const int r8 = r0 + 8 * AKS;
                ah[mi][0] = *(const uint32_t*)(sAh + r0);
                ah[mi][1] = *(const uint32_t*)(sAh + r8);
                ah[mi][2] = *(const uint32_t*)(sAh + r0 + 8);
                ah[mi][3] = *(const uint32_t*)(sAh + r8 + 8);
                al[mi][0] = *(const uint32_t*)(sAl + r0);
                al[mi][1] = *(const uint32_t*)(sAl + r8);
                al[mi][2] = *(const uint32_t*)(sAl + r0 + 8);
                al[mi][3] = *(const uint32_t*)(sAl + r8 + 8);
            }
#pragma unroll
            for (int ni = 0; ni < 4; ni++) {
                const int c0 = (wc * 32 + ni * 8 + lr) * AKS + k0 + lc;
                bh[ni][0] = *(const uint32_t*)(sBh + c0);
                bh[ni][1] = *(const uint32_t*)(sBh + c0 + 8);
                bl[ni][0] = *(const uint32_t*)(sBl + c0);
                bl[ni][1] = *(const uint32_t*)(sBl + c0 + 8);
            }
            // pass-major: consecutive mma hit distinct accumulators
#pragma unroll
            for (int mi = 0; mi < 4; mi++)
#pragma unroll
                for (int ni = 0; ni < 4; ni++)
                    mma16816(gc.acc[mi][ni], ah[mi], bh[ni]);
#pragma unroll
            for (int mi = 0; mi < 4; mi++)
#pragma unroll
                for (int ni = 0; ni < 4; ni++)
                    mma16816(gc.acc[mi][ni], ah[mi], bl[ni]);
#pragma unroll
            for (int mi = 0; mi < 4; mi++)
#pragma unroll
                for (int ni = 0; ni < 4; ni++)
                    mma16816(gc.acc[mi][ni], al[mi], bh[ni]);
        }
        __syncthreads();
    }

    // stage C through smem (stride 133) for coalesced epilogue
    float* Ds = (float*)smem;
#pragma unroll
    for (int mi = 0; mi < 4; mi++) {
        const int r = wr * 64 + mi * 16 + lr;
#pragma unroll
        for (int ni = 0; ni < 4; ni++) {
            const int cc = wc * 32 + ni * 8 + lc;
            Ds[r * 133 + cc]           = gc.acc[mi][ni][0];
            Ds[r * 133 + cc + 1]       = gc.acc[mi][ni][1];
            Ds[(r + 8) * 133 + cc]     = gc.acc[mi][ni][2];
            Ds[(r + 8) * 133 + cc + 1] = gc.acc[mi][ni][3];
        }
    }
    __syncthreads();
}

// ---------------------------------------------------------------------------
// Fused QKV projection: C[8192, 3072], weights QKV contiguous in g_Wth/g_Wtl.
// which = bn>>10: 0=Q (scale 1/8, [b,h,s,hd]), 1=K ([b,h,s,hd]), 2=V ([b,h,hd,s])
// ---------------------------------------------------------------------------
__global__ __launch_bounds__(256) void gemm_qkv(
    const __nv_bfloat16* __restrict__ Ah_g, const __nv_bfloat16* __restrict__ Al_g,
    const __nv_bfloat16* __restrict__ Wh_g, const __nv_bfloat16* __restrict__ Wl_g,
    const float* __restrict__ bq, const float* __restrict__ bk, const float* __restrict__ bv,
    __nv_bfloat16* __restrict__ qh, __nv_bfloat16* __restrict__ ql,
    __nv_bfloat16* __restrict__ kh, __nv_bfloat16* __restrict__ kl,
    __nv_bfloat16* __restrict__ vth, __nv_bfloat16* __restrict__ vtl)
{
    extern __shared__ char smem[];
    const int t  = threadIdx.x;
    const int bn = blockIdx.x * 128;     // 0..2944, indexes rows of contiguous QKV W^T
    const int bm = blockIdx.y * 128;
    const int which = bn >> 10;

    GemmCore gc;
    gemm_core_run(smem, t, Ah_g, Al_g, Wh_g, Wl_g, bm, bn, gc);

    const float* Ds = (const float*)smem;
    const float* bias = (which == 0) ? bq : (which == 1) ? bk : bv;
    const float oscale = (which == 0) ? 0.125f : 1.0f;
    const int colm_base = bn & 1023;

    if (which < 2) {
        __nv_bfloat16* oh = (which == 0) ? qh : kh;
        __nv_bfloat16* ol = (which == 0) ? ql : kl;
        for (int idx = t; idx < 128 * 128; idx += 256) {
            const int r = idx >> 7, cc = idx & 127;
            const int row = bm + r;
            const int colm = colm_base + cc;
            const float v = (Ds[r * 133 + cc] + bias[colm]) * oscale;
            const int b = row >> 11, s = row & (SDIM - 1);
            const int h = colm >> 6, hd = colm & (HD - 1);
            const size_t dst = (size_t)((b * HNUM + h) * SDIM + s) * HD + hd;
            __nv_bfloat16 hh = __float2bfloat16(v);
            oh[dst] = hh;
            ol[dst] = __float2bfloat16(v - __bfloat162float(hh));
        }
    } else {
        for (int idx = t; idx < 128 * 128; idx += 256) {
            const int r = idx & 127, cc = idx >> 7;
            const int row = bm + r;
            const int colm = colm_base + cc;
            const float v = Ds[r * 133 + cc] + bias[colm];
            const int b = row >> 11, s = row & (SDIM - 1);
            const int h = colm >> 6, hd = colm & (HD - 1);
            const size_t dst = (size_t)((b * HNUM + h) * HD + hd) * SDIM + s;
            __nv_bfloat16 hh = __float2bfloat16(v);
            vth[dst] = hh;
            vtl[dst] = __float2bfloat16(v - __bfloat162float(hh));
        }
    }
}

// O-projection: fp32 out, plain row-major
__global__ __launch_bounds__(256) void gemm_out(
    const __nv_bfloat16* __restrict__ Ah_g, const __nv_bfloat16* __restrict__ Al_g,
    const __nv_bfloat16* __restrict__ Bh_g, const __nv_bfloat16* __restrict__ Bl_g,
    const float* __restrict__ bias, float* __restrict__ outF)
{
    extern __shared__ char smem[];
    const int t  = threadIdx.x;
    const int bn = blockIdx.x * 128;
    const int bm = blockIdx.y * 128;

    GemmCore gc;
    gemm_core_run(smem, t, Ah_g, Al_g, Bh_g, Bl_g, bm, bn, gc);

    const float* Ds = (const float*)smem;
    for (int idx = t; idx < 128 * 128; idx += 256) {
        const int r = idx >> 7, cc = idx & 127;
        outF[(size_t)(bm + r) * DDIM + bn + cc] = Ds[r * 133 + cc] + bias[bn + cc];
    }
}

// ---------------------------------------------------------------------------
// Flash attention, mma.sync hi/lo split, cp.async 2-stage KV pipeline,
// pass-major mma ordering (8 independent accumulators between reuse).
// ---------------------------------------------------------------------------
#define ATS 72
#define QSZ_E   (2 * 128 * ATS)
#define KVSTG_E (4 * 64 * ATS)
#define ATTN_SMEM ((QSZ_E + 2 * KVSTG_E) * 2)   // 110592 bytes

__global__ __launch_bounds__(256) void attn_mma()
{
    extern __shared__ char smraw[];
    __nv_bfloat16* sm = (__nv_bfloat16*)smraw;
    __nv_bfloat16* sQh = sm;
    __nv_bfloat16* sQl = sm + 128 * ATS;

    const int t    = threadIdx.x;
    const int wid  = t >> 5;
    const int lane = t & 31;
    const int lr   = lane >> 2;
    const int lc   = (lane & 3) << 1;
    const int bh    = blockIdx.y;
    const int qbase = blockIdx.x * 128;
    const int qw    = wid * 16;

    const __nv_bfloat16* Qh = g_Qh + (size_t)bh * SDIM * HD;
    const __nv_bfloat16* Ql = g_Ql + (size_t)bh * SDIM * HD;
    const __nv_bfloat16* Kh = g_Kh + (size_t)bh * SDIM * HD;
    const __nv_bfloat16* Kl = g_Kl + (size_t)bh * SDIM * HD;
    const __nv_bfloat16* Vh = g_VTh + (size_t)bh * HD * SDIM;
    const __nv_bfloat16* Vl = g_VTl + (size_t)bh * HD * SDIM;

    auto issue_kv = [&](int c, int stg) {
        __nv_bfloat16* s0 = sm + QSZ_E + stg * KVSTG_E;
        const int kb = c * 64;
#pragma unroll
        for (int it = 0; it < 2; it++) {
            const int i = t + it * 256;
            const int r = i >> 3, seg = i & 7;
            const int so = r * ATS + seg * 8;
            const size_t gk = (size_t)(kb + r) * HD + seg * 8;
            const size_t gv = (size_t)r * SDIM + kb + seg * 8;
            cpa16(s0 + so,                Kh + gk);
            cpa16(s0 + 64 * ATS + so,     Kl + gk);
            cpa16(s0 + 2 * 64 * ATS + so, Vh + gv);
            cpa16(s0 + 3 * 64 * ATS + so, Vl + gv);
        }
    };

#pragma unroll
    for (int it = 0; it < 4; it++) {
        const int i = t + it * 256;
        const int r = i >> 3, seg = i & 7;
        const size_t g = (size_t)(qbase + r) * HD + seg * 8;
        const int so = r * ATS + seg * 8;
        cpa16(sQh + so, Qh + g);
        cpa16(sQl + so, Ql + g);
    }
    issue_kv(0, 0);
    CPA_COMMIT();

    float o[8][4];
#pragma unroll
    for (int i = 0; i < 8; i++)
#pragma unroll
        for (int j = 0; j < 4; j++) o[i][j] = 0.f;
    float m0 = -1e30f, m1 = -1e30f, l0 = 0.f, l1 = 0.f;

    for (int c = 0; c < 32; c++) {
        if (c < 31) { issue_kv(c + 1, (c + 1) & 1); CPA_COMMIT(); CPA_WAIT(1); }
        else        { CPA_WAIT(0); }
        __syncthreads();

        const __nv_bfloat16* sKh = sm + QSZ_E + (c & 1) * KVSTG_E;
        const __nv_bfloat16* sKl = sKh + 64 * ATS;
        const __nv_bfloat16* sVh = sKh + 2 * 64 * ATS;
        const __nv_bfloat16* sVl = sKh + 3 * 64 * ATS;

        // S = Q K^T (Q pre-scaled)
        float s[8][4];
#pragma unroll
        for (int i = 0; i < 8; i++)
#pragma unroll
            for (int j = 0; j < 4; j++) s[i][j] = 0.f;

#pragma unroll
        for (int kk = 0; kk < 4; kk++) {
            const int k0 = kk * 16;
            uint32_t qa_h[4], qa_l[4], kbh[8][2], kbl[8][2];
            const int r0 = (qw + lr) * ATS + k0 + lc;
            const int r8 = r0 + 8 * ATS;
            qa_h[0] = *(const uint32_t*)(sQh + r0);
            qa_h[1] = *(const uint32_t*)(sQh + r8);
            qa_h[2] = *(const uint32_t*)(sQh + r0 + 8);
            qa_h[3] = *(const uint32_t*)(sQh + r8 + 8);
            qa_l[0] = *(const uint32_t*)(sQl + r0);
            qa_l[1] = *(const uint32_t*)(sQl + r8);
            qa_l[2] = *(const uint32_t*)(sQl + r0 + 8);
            qa_l[3] = *(const uint32_t*)(sQl + r8 + 8);
#pragma unroll
            for (int ni = 0; ni < 8; ni++) {
                const int c0 = (ni * 8 + lr) * ATS + k0 + lc;
                kbh[ni][0] = *(const uint32_t*)(sKh + c0);
                kbh[ni][1] = *(const uint32_t*)(sKh + c0 + 8);
                kbl[ni][0] = *(const uint32_t*)(sKl + c0);
                kbl[ni][1] = *(const uint32_t*)(sKl + c0 + 8);
            }
#pragma unroll
            for (int ni = 0; ni < 8; ni++) mma16816(s[ni], qa_h, kbh[ni]);
#pragma unroll
            for (int ni = 0; ni < 8; ni++) mma16816(s[ni], qa_h, kbl[ni]);
#pragma unroll
            for (int ni = 0; ni < 8; ni++) mma16816(s[ni], qa_l, kbh[ni]);
        }

        // Online softmax
        float mx0 = -1e30f, mx1 = -1e30f;
#pragma unroll
        for (int ni = 0; ni < 8; ni++) {
            mx0 = fmaxf(mx0, fmaxf(s[ni][0], s[ni][1]));
            mx1 = fmaxf(mx1, fmaxf(s[ni][2], s[ni][3]));
        }
#pragma unroll
        for (int off = 1; off < 4; off <<= 1) {
            mx0 = fmaxf(mx0, __shfl_xor_sync(0xffffffffu, mx0, off));
            mx1 = fmaxf(mx1, __shfl_xor_sync(0xffffffffu, mx1, off));
        }
        const float mn0 = fmaxf(m0, mx0);
        const float mn1 = fmaxf(m1, mx1);
        const float al0 = __expf(m0 - mn0);
        const float al1 = __expf(m1 - mn1);
        m0 = mn0; m1 = mn1;

        float ls0 = 0.f, ls1 = 0.f;
#pragma unroll
        for (int ni = 0; ni < 8; ni++) {
            s[ni][0] = __expf(s[ni][0] - mn0);
            s[ni][1] = __expf(s[ni][1] - mn0);
            s[ni][2] = __expf(s[ni][2] - mn1);
            s[ni][3] = __expf(s[ni][3] - mn1);
            ls0 += s[ni][0] + s[ni][1];
            ls1 += s[ni][2] + s[ni][3];
        }
#pragma unroll
        for (int off = 1; off < 4; off <<= 1) {
            ls0 += __shfl_xor_sync(0xffffffffu, ls0, off);
            ls1 += __shfl_xor_sync(0xffffffffu, ls1, off);
        }
        l0 = l0 * al0 + ls0;
        l1 = l1 * al1 + ls1;
#pragma unroll
        for (int ni = 0; ni < 8; ni++) {
            o[ni][0] *= al0; o[ni][1] *= al0;
            o[ni][2] *= al1; o[ni][3] *= al1;
        }

        // O += P V, pass-major
#pragma unroll
        for (int j = 0; j < 4; j++) {
            float p00 = s[2*j][0],   p01 = s[2*j][1],   p02 = s[2*j][2],   p03 = s[2*j][3];
            float p10 = s[2*j+1][0], p11 = s[2*j+1][1], p12 = s[2*j+1][2], p13 = s[2*j+1][3];
            float h00 = __bfloat162float(__float2bfloat16(p00));
            float h01 = __bfloat162float(__float2bfloat16(p01));
            float h02 = __bfloat162float(__float2bfloat16(p02));
            float h03 = __bfloat162float(__float2bfloat16(p03));
            float h10 = __bfloat162float(__float2bfloat16(p10));
            float h11 = __bfloat162float(__float2bfloat16(p11));
            float h12 = __bfloat162float(__float2bfloat16(p12));
            float h13 = __bfloat162float(__float2bfloat16(p13));
            uint32_t pa_h[4], pa_l[4], vbh[8][2], vbl[8][2];
            pa_h[0] = pack_bf16(p00, p01);
            pa_h[1] = pack_bf16(p02, p03);
            pa_h[2] = pack_bf16(p10, p11);
            pa_h[3] = pack_bf16(p12, p13);
            pa_l[0] = pack_bf16(p00 - h00, p01 - h01);
            pa_l[1] = pack_bf16(p02 - h02, p03 - h03);
            pa_l[2] = pack_bf16(p10 - h10, p11 - h11);
            pa_l[3] = pack_bf16(p12 - h12, p13 - h13);
#pragma unroll
            for (int ni = 0; ni < 8; ni++) {
                const int c0 = (ni * 8 + lr) * ATS + j * 16 + lc;
                vbh[ni][0] = *(const uint32_t*)(sVh + c0);
                vbh[ni][1] = *(const uint32_t*)(sVh + c0 + 8);
                vbl[ni][0] = *(const uint32_t*)(sVl + c0);
                vbl[ni][1] = *(const uint32_t*)(sVl + c0 + 8);
            }
#pragma unroll
            for (int ni = 0; ni < 8; ni++) mma16816(o[ni], pa_h, vbh[ni]);
#pragma unroll
            for (int ni = 0; ni < 8; ni++) mma16816(o[ni], pa_h, vbl[ni]);
#pragma unroll
            for (int ni = 0; ni < 8; ni++) mma16816(o[ni], pa_l, vbh[ni]);
        }
        __syncthreads();
    }

    // Epilogue: normalize, hi/lo split, write ctx [b,s,D]
    const float inv0 = 1.f / l0;
    const float inv1 = 1.f / l1;
    const int b = bh >> 4;
    const int h = bh & (HNUM - 1);
    const int s0 = qbase + qw + lr;
    const int s1 = s0 + 8;
#pragma unroll
    for (int ni = 0; ni < 8; ni++) {
        const int col = h * HD + ni * 8 + lc;
        {
            const float v0 = o[ni][0] * inv0, v1 = o[ni][1] * inv0;
            const float h0 = __bfloat162float(__float2bfloat16(v0));
            const float h1 = __bfloat162float(__float2bfloat16(v1));
            const size_t d = (size_t)(b * SDIM + s0) * DDIM + col;
            *(uint32_t*)(g_Xh + d) = pack_bf16(v0, v1);
            *(uint32_t*)(g_Xl + d) = pack_bf16(v0 - h0, v1 - h1);
        }
        {
            const float v0 = o[ni][2] * inv1, v1 = o[ni][3] * inv1;
            const float h0 = __bfloat162float(__float2bfloat16(v0));
            const float h1 = __bfloat162float(__float2bfloat16(v1));
            const size_t d = (size_t)(b * SDIM + s1) * DDIM + col;
            *(uint32_t*)(g_Xh + d) = pack_bf16(v0, v1);
            *(uint32_t*)(g_Xl + d) = pack_bf16(v0 - h0, v1 - h1);
        }
    }
}

// ---------------------------------------------------------------------------
// Launch
// ---------------------------------------------------------------------------
extern "C" void kernel_launch(void* const* d_in, const int* in_sizes, int n_in,
                              void* d_out, int out_size)
{
    const float* x  = (const float*)d_in[0];
    const float* Wq = (const float*)d_in[1];
    const float* bq = (const float*)d_in[2];
    const float* Wk = (const float*)d_in[3];
    const float* bk = (const float*)d_in[4];
    const float* Wv = (const float*)d_in[5];
    const float* bv = (const float*)d_in[6];
    const float* Wo = (const float*)d_in[7];
    const float* bo = (const float*)d_in[8];

    __nv_bfloat16 *xh, *xl, *wth, *wtl, *qh, *ql, *kh, *kl, *vth, *vtl;
    cudaGetSymbolAddress((void**)&xh,  g_Xh);
    cudaGetSymbolAddress((void**)&xl,  g_Xl);
    cudaGetSymbolAddress((void**)&wth, g_Wth);
    cudaGetSymbolAddress((void**)&wtl, g_Wtl);
    cudaGetSymbolAddress((void**)&qh,  g_Qh);
    cudaGetSymbolAddress((void**)&ql,  g_Ql);
    cudaGetSymbolAddress((void**)&kh,  g_Kh);
    cudaGetSymbolAddress((void**)&kl,  g_Kl);
    cudaGetSymbolAddress((void**)&vth, g_VTh);
    cudaGetSymbolAddress((void**)&vtl, g_VTl);

    cudaFuncSetAttribute(gemm_qkv, cudaFuncAttributeMaxDynamicSharedMemorySize, GEMM_SMEM);
    cudaFuncSetAttribute(gemm_out, cudaFuncAttributeMaxDynamicSharedMemorySize, GEMM_SMEM);
    cudaFuncSetAttribute(attn_mma, cudaFuncAttributeMaxDynamicSharedMemorySize, ATTN_SMEM);

    const int N_ELEM = ROWS * DDIM;
    const size_t WSZ = (size_t)DDIM * DDIM;

    convert_split<<<2048, 256>>>(x, xh, xl, N_ELEM);
    transpose_split4<<<dim3(32, 32, 4), dim3(32, 32)>>>(Wq, Wk, Wv, Wo, wth, wtl);

    // Fused QKV: N = 3072 (weights 0..2 contiguous in g_Wth/g_Wtl)
    gemm_qkv<<<dim3(3 * DDIM / 128, ROWS / 128), 256, GEMM_SMEM>>>(
        xh, xl, wth, wtl, bq, bk, bv, qh, ql, kh, kl, vth, vtl);

    attn_mma<<<dim3(SDIM / 128, BH), 256, ATTN_SMEM>>>();   // (16, 64)

    gemm_out<<<dim3(DDIM / 128, ROWS / 128), 256, GEMM_SMEM>>>(
        xh, xl, wth + 3 * WSZ, wtl + 3 * WSZ, bo, (float*)d_out);
}

// round 10
// speedup vs baseline: 3.1371x; 1.0031x over previous
#include <cuda_runtime.h>
#include <cuda_fp16.h>
#include <math.h>
#include <cstdint>

#define BDIM 4
#define SDIM 2048
#define DDIM 1024
#define HNUM 16
#define HD   64
#define ROWS (BDIM * SDIM)   // 8192
#define BH   (BDIM * HNUM)   // 64

// ---------------------------------------------------------------------------
// Scratch (fp16 hi/lo splits)
// ---------------------------------------------------------------------------
__device__ __half g_Xh[(size_t)ROWS * DDIM];
__device__ __half g_Xl[(size_t)ROWS * DDIM];
__device__ __half g_Wth[4][(size_t)DDIM * DDIM];   // W^T hi, [n][k]; QKVO contiguous
__device__ __half g_Wtl[4][(size_t)DDIM * DDIM];
__device__ __half g_Qh[(size_t)BH * SDIM * HD];    // [bh][s][hd] (pre-scaled 1/8)
__device__ __half g_Ql[(size_t)BH * SDIM * HD];
__device__ __half g_Kh[(size_t)BH * SDIM * HD];
__device__ __half g_Kl[(size_t)BH * SDIM * HD];
__device__ __half g_VTh[(size_t)BH * HD * SDIM];   // [bh][hd][s]
__device__ __half g_VTl[(size_t)BH * HD * SDIM];

// ---------------------------------------------------------------------------
// Helpers
// ---------------------------------------------------------------------------
__device__ __forceinline__ void mma16816(float* c, const uint32_t* a, const uint32_t* b)
{
    asm volatile(
        "mma.sync.aligned.m16n8k16.row.col.f32.f16.f16.f32 "
        "{%0,%1,%2,%3}, {%4,%5,%6,%7}, {%8,%9}, {%0,%1,%2,%3};"
        : "+f"(c[0]), "+f"(c[1]), "+f"(c[2]), "+f"(c[3])
        : "r"(a[0]), "r"(a[1]), "r"(a[2]), "r"(a[3]), "r"(b[0]), "r"(b[1]));
}

// pack two fp32 -> f16x2 (lo arg -> low half, hi arg -> high half)
__device__ __forceinline__ uint32_t pack_f16(float lo, float hi)
{
    uint32_t r;
    asm("cvt.rn.f16x2.f32 %0, %1, %2;" : "=r"(r) : "f"(hi), "f"(lo));
    return r;
}

__device__ __forceinline__ void cpa16(void* sptr, const void* gptr)
{
    uint32_t s = (uint32_t)__cvta_generic_to_shared(sptr);
    asm volatile("cp.async.cg.shared.global [%0], [%1], 16;" :: "r"(s), "l"(gptr));
}
#define CPA_COMMIT() asm volatile("cp.async.commit_group;" ::: "memory")
#define CPA_WAIT(n)  asm volatile("cp.async.wait_group %0;" :: "n"(n) : "memory")

// ---------------------------------------------------------------------------
// Prep kernels
// ---------------------------------------------------------------------------
__global__ void convert_split(const float* __restrict__ src,
                              __half* __restrict__ hi,
                              __half* __restrict__ lo, int n)
{
    for (int i = blockIdx.x * blockDim.x + threadIdx.x; i < n;
         i += gridDim.x * blockDim.x) {
        float x = src[i];
        __half h = __float2half(x);
        hi[i] = h;
        lo[i] = __float2half(x - __half2float(h));
    }
}

__global__ void transpose_split4(
    const float* __restrict__ W0, const float* __restrict__ W1,
    const float* __restrict__ W2, const float* __restrict__ W3,
    __half* __restrict__ ThB, __half* __restrict__ TlB)
{
    __shared__ float tile[32][33];
    const int z = blockIdx.z;
    const float* W = (z == 0) ? W0 : (z == 1) ? W1 : (z == 2) ? W2 : W3;
    __half* Th = ThB + (size_t)z * DDIM * DDIM;
    __half* Tl = TlB + (size_t)z * DDIM * DDIM;
    const int tx = threadIdx.x, ty = threadIdx.y;
    tile[ty][tx] = W[(size_t)(blockIdx.y * 32 + ty) * DDIM + blockIdx.x * 32 + tx];
    __syncthreads();
    const int on = blockIdx.x * 32 + ty;
    const int ok = blockIdx.y * 32 + tx;
    float v = tile[tx][ty];
    __half h = __float2half(v);
    Th[(size_t)on * DDIM + ok] = h;
    Tl[(size_t)on * DDIM + ok] = __float2half(v - __half2float(h));
}

// ---------------------------------------------------------------------------
// Shared GEMM core: CTA tile 128x128, K-chunk 32, cp.async 2-stage, 8 warps.
// Stage = 4 tiles x 128 rows x 32 halfs (stride 40) = 40960 B -> 2 CTAs/SM.
// Pass-major mma ordering. B indexed by rows (bn + r) from BASE pointer.
// ---------------------------------------------------------------------------
#define AKS 40
#define TILE_E (128 * AKS)
#define STG_E  (4 * TILE_E)
#define GEMM_SMEM (2 * STG_E * 2)        // 81920 bytes (epilogue needs 68096)

struct GemmCore {
    float acc[4][4][4];
};

__device__ __forceinline__ void gemm_core_run(
    char* smem, int t,
    const __half* Ah_g, const __half* Al_g,
    const __half* Bh_g, const __half* Bl_g,
    int bm, int bn, GemmCore& gc)
{
    __half* sbase = (__half*)smem;
    const int wid  = t >> 5;
    const int lane = t & 31;
    const int wr   = wid & 1;
    const int wc   = wid >> 1;
    const int lr   = lane >> 2;
    const int lc   = (lane & 3) << 1;

    auto issue_chunk = [&](int c, int stg) {
        __half* s0 = sbase + stg * STG_E;
        const int k0g = c * 32;
#pragma unroll
        for (int it = 0; it < 2; it++) {
            const int i = t + it * 256;
            const int r = i >> 2, seg = i & 3;   // 512 cp16 per tile
            const size_t ga = (size_t)(bm + r) * DDIM + k0g + seg * 8;
            const size_t gb = (size_t)(bn + r) * DDIM + k0g + seg * 8;
            const int so = r * AKS + seg * 8;
            cpa16(s0 + so,              Ah_g + ga);
            cpa16(s0 + TILE_E + so,     Al_g + ga);
            cpa16(s0 + 2 * TILE_E + so, Bh_g + gb);
            cpa16(s0 + 3 * TILE_E + so, Bl_g + gb);
        }
    };

#pragma unroll
    for (int i = 0; i < 4; i++)
#pragma unroll
        for (int j = 0; j < 4; j++)
#pragma unroll
            for (int r = 0; r < 4; r++) gc.acc[i][j][r] = 0.f;

    issue_chunk(0, 0);
    CPA_COMMIT();

    for (int c = 0; c < 32; c++) {
        if (c < 31) { issue_chunk(c + 1, (c + 1) & 1); CPA_COMMIT(); CPA_WAIT(1); }
        else        { CPA_WAIT(0); }
        __syncthreads();

        const __half* sAh = sbase + (c & 1) * STG_E;
        const __half* sAl = sAh + TILE_E;
        const __half* sBh = sAh + 2 * TILE_E;
        const __half* sBl = sAh + 3 * TILE_E;

#pragma unroll
        for (int kk = 0; kk < 2; kk++) {
            const int k0 = kk * 16;
            uint32_t ah[4][4], al[4][4], bh[4][2], bl[4][2];
#pragma unroll
            for (int mi = 0; mi < 4; mi++) {
                const int r0 = (wr * 64 + mi * 16 + lr) * AKS + k0 + lc;
                const int r8 = r0 + 8 * AKS;
                ah[mi][0] = *(const uint32_t*)(sAh + r0);
                ah[mi][1] = *(const uint32_t*)(sAh + r8);
                ah[mi][2] = *(const uint32_t*)(sAh + r0 + 8);
                ah[mi][3] = *(const uint32_t*)(sAh + r8 + 8);
                al[mi][0] = *(const uint32_t*)(sAl + r0);
                al[mi][1] = *(const uint32_t*)(sAl + r8);
                al[mi][2] = *(const uint32_t*)(sAl + r0 + 8);
                al[mi][3] = *(const uint32_t*)(sAl + r8 + 8);
            }
#pragma unroll
            for (int ni = 0; ni < 4; ni++) {
                const int c0 = (wc * 32 + ni * 8 + lr) * AKS + k0 + lc;
                bh[ni][0] = *(const uint32_t*)(sBh + c0);
                bh[ni][1] = *(const uint32_t*)(sBh + c0 + 8);
                bl[ni][0] = *(const uint32_t*)(sBl + c0);
                bl[ni][1] = *(const uint32_t*)(sBl + c0 + 8);
            }
            // pass-major: consecutive mma hit distinct accumulators
#pragma unroll
            for (int mi = 0; mi < 4; mi++)
#pragma unroll
                for (int ni = 0; ni < 4; ni++)
                    mma16816(gc.acc[mi][ni], ah[mi], bh[ni]);
#pragma unroll
            for (int mi = 0; mi < 4; mi++)
#pragma unroll
                for (int ni = 0; ni < 4; ni++)
                    mma16816(gc.acc[mi][ni], ah[mi], bl[ni]);
#pragma unroll
            for (int mi = 0; mi < 4; mi++)
#pragma unroll
                for (int ni = 0; ni < 4; ni++)
                    mma16816(gc.acc[mi][ni], al[mi], bh[ni]);
        }
        __syncthreads();
    }

    // stage C through smem (stride 133) for coalesced epilogue
    float* Ds = (float*)smem;
#pragma unroll
    for (int mi = 0; mi < 4; mi++) {
        const int r = wr * 64 + mi * 16 + lr;
#pragma unroll
        for (int ni = 0; ni < 4; ni++) {
            const int cc = wc * 32 + ni * 8 + lc;
            Ds[r * 133 + cc]           = gc.acc[mi][ni][0];
            Ds[r * 133 + cc + 1]       = gc.acc[mi][ni][1];
            Ds[(r + 8) * 133 + cc]     = gc.acc[mi][ni][2];
            Ds[(r + 8) * 133 + cc + 1] = gc.acc[mi][ni][3];
        }
    }
    __syncthreads();
}

// ---------------------------------------------------------------------------
// Fused QKV projection: C[8192, 3072], QKV weights contiguous.
// which = bn>>10: 0=Q (scale 1/8, [b,h,s,hd]), 1=K ([b,h,s,hd]), 2=V ([b,h,hd,s])
// ---------------------------------------------------------------------------
__global__ __launch_bounds__(256) void gemm_qkv(
    const __half* __restrict__ Ah_g, const __half* __restrict__ Al_g,
    const __half* __restrict__ Wh_g, const __half* __restrict__ Wl_g,
    const float* __restrict__ bq, const float* __restrict__ bk, const float* __restrict__ bv,
    __half* __restrict__ qh, __half* __restrict__ ql,
    __half* __restrict__ kh, __half* __restrict__ kl,
    __half* __restrict__ vth, __half* __restrict__ vtl)
{
    extern __shared__ char smem[];
    const int t  = threadIdx.x;
    const int bn = blockIdx.x * 128;
    const int bm = blockIdx.y * 128;
    const int which = bn >> 10;

    GemmCore gc;
    gemm_core_run(smem, t, Ah_g, Al_g, Wh_g, Wl_g, bm, bn, gc);

    const float* Ds = (const float*)smem;
    const float* bias = (which == 0) ? bq : (which == 1) ? bk : bv;
    const float oscale = (which == 0) ? 0.125f : 1.0f;
    const int colm_base = bn & 1023;

    if (which < 2) {
        __half* oh = (which == 0) ? qh : kh;
        __half* ol = (which == 0) ? ql : kl;
        for (int idx = t; idx < 128 * 128; idx += 256) {
            const int r = idx >> 7, cc = idx & 127;
            const int row = bm + r;
            const int colm = colm_base + cc;
            const float v = (Ds[r * 133 + cc] + bias[colm]) * oscale;
            const int b = row >> 11, s = row & (SDIM - 1);
            const int h = colm >> 6, hd = colm & (HD - 1);
            const size_t dst = (size_t)((b * HNUM + h) * SDIM + s) * HD + hd;
            __half hh = __float2half(v);
            oh[dst] = hh;
            ol[dst] = __float2half(v - __half2float(hh));
        }
    } else {
        for (int idx = t; idx < 128 * 128; idx += 256) {
            const int r = idx & 127, cc = idx >> 7;
            const int row = bm + r;
            const int colm = colm_base + cc;
            const float v = Ds[r * 133 + cc] + bias[colm];
            const int b = row >> 11, s = row & (SDIM - 1);
            const int h = colm >> 6, hd = colm & (HD - 1);
            const size_t dst = (size_t)((b * HNUM + h) * HD + hd) * SDIM + s;
            __half hh = __float2half(v);
            vth[dst] = hh;
            vtl[dst] = __float2half(v - __half2float(hh));
        }
    }
}

// O-projection: fp32 out, plain row-major
__global__ __launch_bounds__(256) void gemm_out(
    const __half* __restrict__ Ah_g, const __half* __restrict__ Al_g,
    const __half* __restrict__ Bh_g, const __half* __restrict__ Bl_g,
    const float* __restrict__ bias, float* __restrict__ outF)
{
    extern __shared__ char smem[];
    const int t  = threadIdx.x;
    const int bn = blockIdx.x * 128;
    const int bm = blockIdx.y * 128;

    GemmCore gc;
    gemm_core_run(smem, t, Ah_g, Al_g, Bh_g, Bl_g, bm, bn, gc);

    const float* Ds = (const float*)smem;
    for (int idx = t; idx < 128 * 128; idx += 256) {
        const int r = idx >> 7, cc = idx & 127;
        outF[(size_t)(bm + r) * DDIM + bn + cc] = Ds[r * 133 + cc] + bias[bn + cc];
    }
}

// ---------------------------------------------------------------------------
// Flash attention, fp16 splits. QK^T: 3-pass hi/lo. PV: P single fp16 x
// V hi/lo = 2 passes. cp.async 2-stage KV pipeline, pass-major ordering.
// ---------------------------------------------------------------------------
#define ATS 72
#define QSZ_E   (2 * 128 * ATS)
#define KVSTG_E (4 * 64 * ATS)
#define ATTN_SMEM ((QSZ_E + 2 * KVSTG_E) * 2)   // 110592 bytes

__global__ __launch_bounds__(256) void attn_mma()
{
    extern __shared__ char smraw[];
    __half* sm = (__half*)smraw;
    __half* sQh = sm;
    __half* sQl = sm + 128 * ATS;

    const int t    = threadIdx.x;
    const int wid  = t >> 5;
    const int lane = t & 31;
    const int lr   = lane >> 2;
    const int lc   = (lane & 3) << 1;
    const int bh    = blockIdx.y;
    const int qbase = blockIdx.x * 128;
    const int qw    = wid * 16;

    const __half* Qh = g_Qh + (size_t)bh * SDIM * HD;
    const __half* Ql = g_Ql + (size_t)bh * SDIM * HD;
    const __half* Kh = g_Kh + (size_t)bh * SDIM * HD;
    const __half* Kl = g_Kl + (size_t)bh * SDIM * HD;
    const __half* Vh = g_VTh + (size_t)bh * HD * SDIM;
    const __half* Vl = g_VTl + (size_t)bh * HD * SDIM;

    auto issue_kv = [&](int c, int stg) {
        __half* s0 = sm + QSZ_E + stg * KVSTG_E;
        const int kb = c * 64;
#pragma unroll
        for (int it = 0; it < 2; it++) {
            const int i = t + it * 256;
            const int r = i >> 3, seg = i & 7;
            const int so = r * ATS + seg * 8;
            const size_t gk = (size_t)(kb + r) * HD + seg * 8;
            const size_t gv = (size_t)r * SDIM + kb + seg * 8;
            cpa16(s0 + so,                Kh + gk);
            cpa16(s0 + 64 * ATS + so,     Kl + gk);
            cpa16(s0 + 2 * 64 * ATS + so, Vh + gv);
            cpa16(s0 + 3 * 64 * ATS + so, Vl + gv);
        }
    };

#pragma unroll
    for (int it = 0; it < 4; it++) {
        const int i = t + it * 256;
        const int r = i >> 3, seg = i & 7;
        const size_t g = (size_t)(qbase + r) * HD + seg * 8;
        const int so = r * ATS + seg * 8;
        cpa16(sQh + so, Qh + g);
        cpa16(sQl + so, Ql + g);
    }
    issue_kv(0, 0);
    CPA_COMMIT();

    float o[8][4];
#pragma unroll
    for (int i = 0; i < 8; i++)
#pragma unroll
        for (int j = 0; j < 4; j++) o[i][j] = 0.f;
    float m0 = -1e30f, m1 = -1e30f, l0 = 0.f, l1 = 0.f;

    for (int c = 0; c < 32; c++) {
        if (c < 31) { issue_kv(c + 1, (c + 1) & 1); CPA_COMMIT(); CPA_WAIT(1); }
        else        { CPA_WAIT(0); }
        __syncthreads();

        const __half* sKh = sm + QSZ_E + (c & 1) * KVSTG_E;
        const __half* sKl = sKh + 64 * ATS;
        const __half* sVh = sKh + 2 * 64 * ATS;
        const __half* sVl = sKh + 3 * 64 * ATS;

        // S = Q K^T (Q pre-scaled by 1/8), 3-pass hi/lo
        float s[8][4];
#pragma unroll
        for (int i = 0; i < 8; i++)
#pragma unroll
            for (int j = 0; j < 4; j++) s[i][j] = 0.f;

#pragma unroll
        for (int kk = 0; kk < 4; kk++) {
            const int k0 = kk * 16;
            uint32_t qa_h[4], qa_l[4], kbh[8][2], kbl[8][2];
            const int r0 = (qw + lr) * ATS + k0 + lc;
            const int r8 = r0 + 8 * ATS;
            qa_h[0] = *(const uint32_t*)(sQh + r0);
            qa_h[1] = *(const uint32_t*)(sQh + r8);
            qa_h[2] = *(const uint32_t*)(sQh + r0 + 8);
            qa_h[3] = *(const uint32_t*)(sQh + r8 + 8);
            qa_l[0] = *(const uint32_t*)(sQl + r0);
            qa_l[1] = *(const uint32_t*)(sQl + r8);
            qa_l[2] = *(const uint32_t*)(sQl + r0 + 8);
            qa_l[3] = *(const uint32_t*)(sQl + r8 + 8);
#pragma unroll
            for (int ni = 0; ni < 8; ni++) {
                const int c0 = (ni * 8 + lr) * ATS + k0 + lc;
                kbh[ni][0] = *(const uint32_t*)(sKh + c0);
                kbh[ni][1] = *(const uint32_t*)(sKh + c0 + 8);
                kbl[ni][0] = *(const uint32_t*)(sKl + c0);
                kbl[ni][1] = *(const uint32_t*)(sKl + c0 + 8);
            }
#pragma unroll
            for (int ni = 0; ni < 8; ni++) mma16816(s[ni], qa_h, kbh[ni]);
#pragma unroll
            for (int ni = 0; ni < 8; ni++) mma16816(s[ni], qa_h, kbl[ni]);
#pragma unroll
            for (int ni = 0; ni < 8; ni++) mma16816(s[ni], qa_l, kbh[ni]);
        }

        // Online softmax
        float mx0 = -1e30f, mx1 = -1e30f;
#pragma unroll
        for (int ni = 0; ni < 8; ni++) {
            mx0 = fmaxf(mx0, fmaxf(s[ni][0], s[ni][1]));
            mx1 = fmaxf(mx1, fmaxf(s[ni][2], s[ni][3]));
        }
#pragma unroll
        for (int off = 1; off < 4; off <<= 1) {
            mx0 = fmaxf(mx0, __shfl_xor_sync(0xffffffffu, mx0, off));
            mx1 = fmaxf(mx1, __shfl_xor_sync(0xffffffffu, mx1, off));
        }
        const float mn0 = fmaxf(m0, mx0);
        const float mn1 = fmaxf(m1, mx1);
        const float al0 = __expf(m0 - mn0);
        const float al1 = __expf(m1 - mn1);
        m0 = mn0; m1 = mn1;

        float ls0 = 0.f, ls1 = 0.f;
#pragma unroll
        for (int ni = 0; ni < 8; ni++) {
            s[ni][0] = __expf(s[ni][0] - mn0);
            s[ni][1] = __expf(s[ni][1] - mn0);
            s[ni][2] = __expf(s[ni][2] - mn1);
            s[ni][3] = __expf(s[ni][3] - mn1);
            ls0 += s[ni][0] + s[ni][1];
            ls1 += s[ni][2] + s[ni][3];
        }
#pragma unroll
        for (int off = 1; off < 4; off <<= 1) {
            ls0 += __shfl_xor_sync(0xffffffffu, ls0, off);
            ls1 += __shfl_xor_sync(0xffffffffu, ls1, off);
        }
        l0 = l0 * al0 + ls0;
        l1 = l1 * al1 + ls1;
#pragma unroll
        for (int ni = 0; ni < 8; ni++) {
            o[ni][0] *= al0; o[ni][1] *= al0;
            o[ni][2] *= al1; o[ni][3] *= al1;
        }

        // O += P V : P single fp16 (rel err ~2^-13), V hi/lo -> 2 passes
#pragma unroll
        for (int j = 0; j < 4; j++) {
            uint32_t pa[4], vbh[8][2], vbl[8][2];
            pa[0] = pack_f16(s[2*j][0],   s[2*j][1]);
            pa[1] = pack_f16(s[2*j][2],   s[2*j][3]);
            pa[2] = pack_f16(s[2*j+1][0], s[2*j+1][1]);
            pa[3] = pack_f16(s[2*j+1][2], s[2*j+1][3]);
#pragma unroll
            for (int ni = 0; ni < 8; ni++) {
                const int c0 = (ni * 8 + lr) * ATS + j * 16 + lc;
                vbh[ni][0] = *(const uint32_t*)(sVh + c0);
                vbh[ni][1] = *(const uint32_t*)(sVh + c0 + 8);
                vbl[ni][0] = *(const uint32_t*)(sVl + c0);
                vbl[ni][1] = *(const uint32_t*)(sVl + c0 + 8);
            }
#pragma unroll
            for (int ni = 0; ni < 8; ni++) mma16816(o[ni], pa, vbh[ni]);
#pragma unroll
            for (int ni = 0; ni < 8; ni++) mma16816(o[ni], pa, vbl[ni]);
        }
        __syncthreads();
    }

    // Epilogue: normalize, fp16 hi/lo split, write ctx [b,s,D]
    const float inv0 = 1.f / l0;
    const float inv1 = 1.f / l1;
    const int b = bh >> 4;
    const int h = bh & (HNUM - 1);
    const int s0 = qbase + qw + lr;
    const int s1 = s0 + 8;
#pragma unroll
    for (int ni = 0; ni < 8; ni++) {
        const int col = h * HD + ni * 8 + lc;
        {
            const float v0 = o[ni][0] * inv0, v1 = o[ni][1] * inv0;
            const float h0 = __half2float(__float2half(v0));
            const float h1 = __half2float(__float2half(v1));
            const size_t d = (size_t)(b * SDIM + s0) * DDIM + col;
            *(uint32_t*)(g_Xh + d) = pack_f16(v0, v1);
            *(uint32_t*)(g_Xl + d) = pack_f16(v0 - h0, v1 - h1);
        }
        {
            const float v0 = o[ni][2] * inv1, v1 = o[ni][3] * inv1;
            const float h0 = __half2float(__float2half(v0));
            const float h1 = __half2float(__float2half(v1));
            const size_t d = (size_t)(b * SDIM + s1) * DDIM + col;
            *(uint32_t*)(g_Xh + d) = pack_f16(v0, v1);
            *(uint32_t*)(g_Xl + d) = pack_f16(v0 - h0, v1 - h1);
        }
    }
}

// ---------------------------------------------------------------------------
// Launch
// ---------------------------------------------------------------------------
extern "C" void kernel_launch(void* const* d_in, const int* in_sizes, int n_in,
                              void* d_out, int out_size)
{
    const float* x  = (const float*)d_in[0];
    const float* Wq = (const float*)d_in[1];
    const float* bq = (const float*)d_in[2];
    const float* Wk = (const float*)d_in[3];
    const float* bk = (const float*)d_in[4];
    const float* Wv = (const float*)d_in[5];
    const float* bv = (const float*)d_in[6];
    const float* Wo = (const float*)d_in[7];
    const float* bo = (const float*)d_in[8];

    __half *xh, *xl, *wth, *wtl, *qh, *ql, *kh, *kl, *vth, *vtl;
    cudaGetSymbolAddress((void**)&xh,  g_Xh);
    cudaGetSymbolAddress((void**)&xl,  g_Xl);
    cudaGetSymbolAddress((void**)&wth, g_Wth);
    cudaGetSymbolAddress((void**)&wtl, g_Wtl);
    cudaGetSymbolAddress((void**)&qh,  g_Qh);
    cudaGetSymbolAddress((void**)&ql,  g_Ql);
    cudaGetSymbolAddress((void**)&kh,  g_Kh);
    cudaGetSymbolAddress((void**)&kl,  g_Kl);
    cudaGetSymbolAddress((void**)&vth, g_VTh);
    cudaGetSymbolAddress((void**)&vtl, g_VTl);

    cudaFuncSetAttribute(gemm_qkv, cudaFuncAttributeMaxDynamicSharedMemorySize, GEMM_SMEM);
    cudaFuncSetAttribute(gemm_out, cudaFuncAttributeMaxDynamicSharedMemorySize, GEMM_SMEM);
    cudaFuncSetAttribute(attn_mma, cudaFuncAttributeMaxDynamicSharedMemorySize, ATTN_SMEM);

    const int N_ELEM = ROWS * DDIM;
    const size_t WSZ = (size_t)DDIM * DDIM;

    convert_split<<<2048, 256>>>(x, xh, xl, N_ELEM);
    transpose_split4<<<dim3(32, 32, 4), dim3(32, 32)>>>(Wq, Wk, Wv, Wo, wth, wtl);

    gemm_qkv<<<dim3(3 * DDIM / 128, ROWS / 128), 256, GEMM_SMEM>>>(
        xh, xl, wth, wtl, bq, bk, bv, qh, ql, kh, kl, vth, vtl);

    attn_mma<<<dim3(SDIM / 128, BH), 256, ATTN_SMEM>>>();   // (16, 64)

    gemm_out<<<dim3(DDIM / 128, ROWS / 128), 256, GEMM_SMEM>>>(
        xh, xl, wth + 3 * WSZ, wtl + 3 * WSZ, bo, (float*)d_out);
}

// round 11
// speedup vs baseline: 3.3196x; 1.0582x over previous
#include <cuda_runtime.h>
#include <cuda_fp16.h>
#include <math.h>
#include <cstdint>

#define BDIM 4
#define SDIM 2048
#define DDIM 1024
#define HNUM 16
#define HD   64
#define ROWS (BDIM * SDIM)   // 8192
#define BH   (BDIM * HNUM)   // 64

// ---------------------------------------------------------------------------
// Scratch (fp16 hi/lo splits)
// ---------------------------------------------------------------------------
__device__ __half g_Xh[(size_t)ROWS * DDIM];
__device__ __half g_Xl[(size_t)ROWS * DDIM];
__device__ __half g_Wth[4][(size_t)DDIM * DDIM];   // W^T hi, [n][k]; QKVO contiguous
__device__ __half g_Wtl[4][(size_t)DDIM * DDIM];
__device__ __half g_Qh[(size_t)BH * SDIM * HD];    // [bh][s][hd] (pre-scaled 1/8)
__device__ __half g_Ql[(size_t)BH * SDIM * HD];
__device__ __half g_Kh[(size_t)BH * SDIM * HD];
__device__ __half g_Kl[(size_t)BH * SDIM * HD];
__device__ __half g_VTh[(size_t)BH * HD * SDIM];   // [bh][hd][s]
__device__ __half g_VTl[(size_t)BH * HD * SDIM];

// ---------------------------------------------------------------------------
// Helpers
// ---------------------------------------------------------------------------
__device__ __forceinline__ void mma16816(float* c, const uint32_t* a, const uint32_t* b)
{
    asm volatile(
        "mma.sync.aligned.m16n8k16.row.col.f32.f16.f16.f32 "
        "{%0,%1,%2,%3}, {%4,%5,%6,%7}, {%8,%9}, {%0,%1,%2,%3};"
        : "+f"(c[0]), "+f"(c[1]), "+f"(c[2]), "+f"(c[3])
        : "r"(a[0]), "r"(a[1]), "r"(a[2]), "r"(a[3]), "r"(b[0]), "r"(b[1]));
}

// pack two fp32 -> f16x2 (lo arg -> low half, hi arg -> high half)
__device__ __forceinline__ uint32_t pack_f16(float lo, float hi)
{
    uint32_t r;
    asm("cvt.rn.f16x2.f32 %0, %1, %2;" : "=r"(r) : "f"(hi), "f"(lo));
    return r;
}

__device__ __forceinline__ void cpa16(void* sptr, const void* gptr)
{
    uint32_t s = (uint32_t)__cvta_generic_to_shared(sptr);
    asm volatile("cp.async.cg.shared.global [%0], [%1], 16;" :: "r"(s), "l"(gptr));
}
#define CPA_COMMIT() asm volatile("cp.async.commit_group;" ::: "memory")
#define CPA_WAIT(n)  asm volatile("cp.async.wait_group %0;" :: "n"(n) : "memory")

// ---------------------------------------------------------------------------
// Prep kernels
// ---------------------------------------------------------------------------
// Vectorized: float4 in, uint2 (4 halfs) out per array.
__global__ void convert_split(const float4* __restrict__ src,
                              uint2* __restrict__ hi,
                              uint2* __restrict__ lo, int n4)
{
    for (int i = blockIdx.x * blockDim.x + threadIdx.x; i < n4;
         i += gridDim.x * blockDim.x) {
        const float4 v = src[i];
        const float hx = __half2float(__float2half(v.x));
        const float hy = __half2float(__float2half(v.y));
        const float hz = __half2float(__float2half(v.z));
        const float hw = __half2float(__float2half(v.w));
        hi[i] = make_uint2(pack_f16(v.x, v.y), pack_f16(v.z, v.w));
        lo[i] = make_uint2(pack_f16(v.x - hx, v.y - hy), pack_f16(v.z - hz, v.w - hw));
    }
}

__global__ void transpose_split4(
    const float* __restrict__ W0, const float* __restrict__ W1,
    const float* __restrict__ W2, const float* __restrict__ W3,
    __half* __restrict__ ThB, __half* __restrict__ TlB)
{
    __shared__ float tile[32][33];
    const int z = blockIdx.z;
    const float* W = (z == 0) ? W0 : (z == 1) ? W1 : (z == 2) ? W2 : W3;
    __half* Th = ThB + (size_t)z * DDIM * DDIM;
    __half* Tl = TlB + (size_t)z * DDIM * DDIM;
    const int tx = threadIdx.x, ty = threadIdx.y;
    tile[ty][tx] = W[(size_t)(blockIdx.y * 32 + ty) * DDIM + blockIdx.x * 32 + tx];
    __syncthreads();
    const int on = blockIdx.x * 32 + ty;
    const int ok = blockIdx.y * 32 + tx;
    float v = tile[tx][ty];
    __half h = __float2half(v);
    Th[(size_t)on * DDIM + ok] = h;
    Tl[(size_t)on * DDIM + ok] = __float2half(v - __half2float(h));
}

// ---------------------------------------------------------------------------
// Shared GEMM core (R9-proven config): CTA tile 128x128, K-chunk 64,
// cp.async 2-stage (147456 B), 8 warps, pass-major mma ordering.
// B indexed by rows (bn + r) from BASE pointer.
// ---------------------------------------------------------------------------
#define AKS 72
#define TILE_E (128 * AKS)
#define STG_E  (4 * TILE_E)
#define GEMM_SMEM (2 * STG_E * 2)        // 147456 bytes (epilogue needs 68096)

struct GemmCore {
    float acc[4][4][4];
};

__device__ __forceinline__ void gemm_core_run(
    char* smem, int t,
    const __half* Ah_g, const __half* Al_g,
    const __half* Bh_g, const __half* Bl_g,
    int bm, int bn, GemmCore& gc)
{
    __half* sbase = (__half*)smem;
    const int wid  = t >> 5;
    const int lane = t & 31;
    const int wr   = wid & 1;
    const int wc   = wid >> 1;
    const int lr   = lane >> 2;
    const int lc   = (lane & 3) << 1;

    auto issue_chunk = [&](int c, int stg) {
        __half* s0 = sbase + stg * STG_E;
        const int k0g = c * 64;
#pragma unroll
        for (int it = 0; it < 4; it++) {
            const int i = t + it * 256;
            const int r = i >> 3, seg = i & 7;
            const size_t ga = (size_t)(bm + r) * DDIM + k0g + seg * 8;
            const size_t gb = (size_t)(bn + r) * DDIM + k0g + seg * 8;
            const int so = r * AKS + seg * 8;
            cpa16(s0 + so,              Ah_g + ga);
            cpa16(s0 + TILE_E + so,     Al_g + ga);
            cpa16(s0 + 2 * TILE_E + so, Bh_g + gb);
            cpa16(s0 + 3 * TILE_E + so, Bl_g + gb);
        }
    };

#pragma unroll
    for (int i = 0; i < 4; i++)
#pragma unroll
        for (int j = 0; j < 4; j++)
#pragma unroll
            for (int r = 0; r < 4; r++) gc.acc[i][j][r] = 0.f;

    issue_chunk(0, 0);
    CPA_COMMIT();

    for (int c = 0; c < 16; c++) {
        if (c < 15) { issue_chunk(c + 1, (c + 1) & 1); CPA_COMMIT(); CPA_WAIT(1); }
        else        { CPA_WAIT(0); }
        __syncthreads();

        const __half* sAh = sbase + (c & 1) * STG_E;
        const __half* sAl = sAh + TILE_E;
        const __half* sBh = sAh + 2 * TILE_E;
        const __half* sBl = sAh + 3 * TILE_E;

#pragma unroll
        for (int kk = 0; kk < 4; kk++) {
            const int k0 = kk * 16;
            uint32_t ah[4][4], al[4][4], bh[4][2], bl[4][2];
#pragma unroll
            for (int mi = 0; mi < 4; mi++) {
                const int r0 = (wr * 64 + mi * 16 + lr) * AKS + k0 + lc;
                const int r8 = r0 + 8 * AKS;
                ah[mi][0] = *(const uint32_t*)(sAh + r0);
                ah[mi][1] = *(const uint32_t*)(sAh + r8);
                ah[mi][2] = *(const uint32_t*)(sAh + r0 + 8);
                ah[mi][3] = *(const uint32_t*)(sAh + r8 + 8);
                al[mi][0] = *(const uint32_t*)(sAl + r0);
                al[mi][1] = *(const uint32_t*)(sAl + r8);
                al[mi][2] = *(const uint32_t*)(sAl + r0 + 8);
                al[mi][3] = *(const uint32_t*)(sAl + r8 + 8);
            }
#pragma unroll
            for (int ni = 0; ni < 4; ni++) {
                const int c0 = (wc * 32 + ni * 8 + lr) * AKS + k0 + lc;
                bh[ni][0] = *(const uint32_t*)(sBh + c0);
                bh[ni][1] = *(const uint32_t*)(sBh + c0 + 8);
                bl[ni][0] = *(const uint32_t*)(sBl + c0);
                bl[ni][1] = *(const uint32_t*)(sBl + c0 + 8);
            }
            // pass-major: consecutive mma hit distinct accumulators
#pragma unroll
            for (int mi = 0; mi < 4; mi++)
#pragma unroll
                for (int ni = 0; ni < 4; ni++)
                    mma16816(gc.acc[mi][ni], ah[mi], bh[ni]);
#pragma unroll
            for (int mi = 0; mi < 4; mi++)
#pragma unroll
                for (int ni = 0; ni < 4; ni++)
                    mma16816(gc.acc[mi][ni], ah[mi], bl[ni]);
#pragma unroll
            for (int mi = 0; mi < 4; mi++)
#pragma unroll
                for (int ni = 0; ni < 4; ni++)
                    mma16816(gc.acc[mi][ni], al[mi], bh[ni]);
        }
        __syncthreads();
    }

    // stage C through smem (stride 133) for coalesced epilogue
    float* Ds = (float*)smem;
#pragma unroll
    for (int mi = 0; mi < 4; mi++) {
        const int r = wr * 64 + mi * 16 + lr;
#pragma unroll
        for (int ni = 0; ni < 4; ni++) {
            const int cc = wc * 32 + ni * 8 + lc;
            Ds[r * 133 + cc]           = gc.acc[mi][ni][0];
            Ds[r * 133 + cc + 1]       = gc.acc[mi][ni][1];
            Ds[(r + 8) * 133 + cc]     = gc.acc[mi][ni][2];
            Ds[(r + 8) * 133 + cc + 1] = gc.acc[mi][ni][3];
        }
    }
    __syncthreads();
}

// ---------------------------------------------------------------------------
// Fused QKV projection: C[8192, 3072], QKV weights contiguous.
// which = bn>>10: 0=Q (scale 1/8, [b,h,s,hd]), 1=K ([b,h,s,hd]), 2=V ([b,h,hd,s])
// ---------------------------------------------------------------------------
__global__ __launch_bounds__(256) void gemm_qkv(
    const __half* __restrict__ Ah_g, const __half* __restrict__ Al_g,
    const __half* __restrict__ Wh_g, const __half* __restrict__ Wl_g,
    const float* __restrict__ bq, const float* __restrict__ bk, const float* __restrict__ bv,
    __half* __restrict__ qh, __half* __restrict__ ql,
    __half* __restrict__ kh, __half* __restrict__ kl,
    __half* __restrict__ vth, __half* __restrict__ vtl)
{
    extern __shared__ char smem[];
    const int t  = threadIdx.x;
    const int bn = blockIdx.x * 128;
    const int bm = blockIdx.y * 128;
    const int which = bn >> 10;

    GemmCore gc;
    gemm_core_run(smem, t, Ah_g, Al_g, Wh_g, Wl_g, bm, bn, gc);

    const float* Ds = (const float*)smem;
    const float* bias = (which == 0) ? bq : (which == 1) ? bk : bv;
    const float oscale = (which == 0) ? 0.125f : 1.0f;
    const int colm_base = bn & 1023;

    if (which < 2) {
        __half* oh = (which == 0) ? qh : kh;
        __half* ol = (which == 0) ? ql : kl;
        for (int idx = t; idx < 128 * 128; idx += 256) {
            const int r = idx >> 7, cc = idx & 127;
            const int row = bm + r;
            const int colm = colm_base + cc;
            const float v = (Ds[r * 133 + cc] + bias[colm]) * oscale;
            const int b = row >> 11, s = row & (SDIM - 1);
            const int h = colm >> 6, hd = colm & (HD - 1);
            const size_t dst = (size_t)((b * HNUM + h) * SDIM + s) * HD + hd;
            __half hh = __float2half(v);
            oh[dst] = hh;
            ol[dst] = __float2half(v - __half2float(hh));
        }
    } else {
        for (int idx = t; idx < 128 * 128; idx += 256) {
            const int r = idx & 127, cc = idx >> 7;
            const int row = bm + r;
            const int colm = colm_base + cc;
            const float v = Ds[r * 133 + cc] + bias[colm];
            const int b = row >> 11, s = row & (SDIM - 1);
            const int h = colm >> 6, hd = colm & (HD - 1);
            const size_t dst = (size_t)((b * HNUM + h) * HD + hd) * SDIM + s;
            __half hh = __float2half(v);
            vth[dst] = hh;
            vtl[dst] = __float2half(v - __half2float(hh));
        }
    }
}

// O-projection: fp32 out, plain row-major
__global__ __launch_bounds__(256) void gemm_out(
    const __half* __restrict__ Ah_g, const __half* __restrict__ Al_g,
    const __half* __restrict__ Bh_g, const __half* __restrict__ Bl_g,
    const float* __restrict__ bias, float* __restrict__ outF)
{
    extern __shared__ char smem[];
    const int t  = threadIdx.x;
    const int bn = blockIdx.x * 128;
    const int bm = blockIdx.y * 128;

    GemmCore gc;
    gemm_core_run(smem, t, Ah_g, Al_g, Bh_g, Bl_g, bm, bn, gc);

    const float* Ds = (const float*)smem;
    for (int idx = t; idx < 128 * 128; idx += 256) {
        const int r = idx >> 7, cc = idx & 127;
        outF[(size_t)(bm + r) * DDIM + bn + cc] = Ds[r * 133 + cc] + bias[bn + cc];
    }
}

// ---------------------------------------------------------------------------
// Flash attention, fp16 splits. QK^T: 3-pass hi/lo. PV: P single fp16 x
// V hi/lo = 2 passes. cp.async 2-stage KV pipeline, pass-major ordering.
// ---------------------------------------------------------------------------
#define ATS 72
#define QSZ_E   (2 * 128 * ATS)
#define KVSTG_E (4 * 64 * ATS)
#define ATTN_SMEM ((QSZ_E + 2 * KVSTG_E) * 2)   // 110592 bytes

__global__ __launch_bounds__(256) void attn_mma()
{
    extern __shared__ char smraw[];
    __half* sm = (__half*)smraw;
    __half* sQh = sm;
    __half* sQl = sm + 128 * ATS;

    const int t    = threadIdx.x;
    const int wid  = t >> 5;
    const int lane = t & 31;
    const int lr   = lane >> 2;
    const int lc   = (lane & 3) << 1;
    const int bh    = blockIdx.y;
    const int qbase = blockIdx.x * 128;
    const int qw    = wid * 16;

    const __half* Qh = g_Qh + (size_t)bh * SDIM * HD;
    const __half* Ql = g_Ql + (size_t)bh * SDIM * HD;
    const __half* Kh = g_Kh + (size_t)bh * SDIM * HD;
    const __half* Kl = g_Kl + (size_t)bh * SDIM * HD;
    const __half* Vh = g_VTh + (size_t)bh * HD * SDIM;
    const __half* Vl = g_VTl + (size_t)bh * HD * SDIM;

    auto issue_kv = [&](int c, int stg) {
        __half* s0 = sm + QSZ_E + stg * KVSTG_E;
        const int kb = c * 64;
#pragma unroll
        for (int it = 0; it < 2; it++) {
            const int i = t + it * 256;
            const int r = i >> 3, seg = i & 7;
            const int so = r * ATS + seg * 8;
            const size_t gk = (size_t)(kb + r) * HD + seg * 8;
            const size_t gv = (size_t)r * SDIM + kb + seg * 8;
            cpa16(s0 + so,                Kh + gk);
            cpa16(s0 + 64 * ATS + so,     Kl + gk);
            cpa16(s0 + 2 * 64 * ATS + so, Vh + gv);
            cpa16(s0 + 3 * 64 * ATS + so, Vl + gv);
        }
    };

#pragma unroll
    for (int it = 0; it < 4; it++) {
        const int i = t + it * 256;
        const int r = i >> 3, seg = i & 7;
        const size_t g = (size_t)(qbase + r) * HD + seg * 8;
        const int so = r * ATS + seg * 8;
        cpa16(sQh + so, Qh + g);
        cpa16(sQl + so, Ql + g);
    }
    issue_kv(0, 0);
    CPA_COMMIT();

    float o[8][4];
#pragma unroll
    for (int i = 0; i < 8; i++)
#pragma unroll
        for (int j = 0; j < 4; j++) o[i][j] = 0.f;
    float m0 = -1e30f, m1 = -1e30f, l0 = 0.f, l1 = 0.f;

    for (int c = 0; c < 32; c++) {
        if (c < 31) { issue_kv(c + 1, (c + 1) & 1); CPA_COMMIT(); CPA_WAIT(1); }
        else        { CPA_WAIT(0); }
        __syncthreads();

        const __half* sKh = sm + QSZ_E + (c & 1) * KVSTG_E;
        const __half* sKl = sKh + 64 * ATS;
        const __half* sVh = sKh + 2 * 64 * ATS;
        const __half* sVl = sKh + 3 * 64 * ATS;

        // S = Q K^T (Q pre-scaled by 1/8), 3-pass hi/lo
        float s[8][4];
#pragma unroll
        for (int i = 0; i < 8; i++)
#pragma unroll
            for (int j = 0; j < 4; j++) s[i][j] = 0.f;

#pragma unroll
        for (int kk = 0; kk < 4; kk++) {
            const int k0 = kk * 16;
            uint32_t qa_h[4], qa_l[4], kbh[8][2], kbl[8][2];
            const int r0 = (qw + lr) * ATS + k0 + lc;
            const int r8 = r0 + 8 * ATS;
            qa_h[0] = *(const uint32_t*)(sQh + r0);
            qa_h[1] = *(const uint32_t*)(sQh + r8);
            qa_h[2] = *(const uint32_t*)(sQh + r0 + 8);
            qa_h[3] = *(const uint32_t*)(sQh + r8 + 8);
            qa_l[0] = *(const uint32_t*)(sQl + r0);
            qa_l[1] = *(const uint32_t*)(sQl + r8);
            qa_l[2] = *(const uint32_t*)(sQl + r0 + 8);
            qa_l[3] = *(const uint32_t*)(sQl + r8 + 8);
#pragma unroll
            for (int ni = 0; ni < 8; ni++) {
                const int c0 = (ni * 8 + lr) * ATS + k0 + lc;
                kbh[ni][0] = *(const uint32_t*)(sKh + c0);
                kbh[ni][1] = *(const uint32_t*)(sKh + c0 + 8);
                kbl[ni][0] = *(const uint32_t*)(sKl + c0);
                kbl[ni][1] = *(const uint32_t*)(sKl + c0 + 8);
            }
#pragma unroll
            for (int ni = 0; ni < 8; ni++) mma16816(s[ni], qa_h, kbh[ni]);
#pragma unroll
            for (int ni = 0; ni < 8; ni++) mma16816(s[ni], qa_h, kbl[ni]);
#pragma unroll
            for (int ni = 0; ni < 8; ni++) mma16816(s[ni], qa_l, kbh[ni]);
        }

        // Online softmax
        float mx0 = -1e30f, mx1 = -1e30f;
#pragma unroll
        for (int ni = 0; ni < 8; ni++) {
            mx0 = fmaxf(mx0, fmaxf(s[ni][0], s[ni][1]));
            mx1 = fmaxf(mx1, fmaxf(s[ni][2], s[ni][3]));
        }
#pragma unroll
        for (int off = 1; off < 4; off <<= 1) {
            mx0 = fmaxf(mx0, __shfl_xor_sync(0xffffffffu, mx0, off));
            mx1 = fmaxf(mx1, __shfl_xor_sync(0xffffffffu, mx1, off));
        }
        const float mn0 = fmaxf(m0, mx0);
        const float mn1 = fmaxf(m1, mx1);
        const float al0 = __expf(m0 - mn0);
        const float al1 = __expf(m1 - mn1);
        m0 = mn0; m1 = mn1;

        float ls0 = 0.f, ls1 = 0.f;
#pragma unroll
        for (int ni = 0; ni < 8; ni++) {
            s[ni][0] = __expf(s[ni][0] - mn0);
            s[ni][1] = __expf(s[ni][1] - mn0);
            s[ni][2] = __expf(s[ni][2] - mn1);
            s[ni][3] = __expf(s[ni][3] - mn1);
            ls0 += s[ni][0] + s[ni][1];
            ls1 += s[ni][2] + s[ni][3];
        }
#pragma unroll
        for (int off = 1; off < 4; off <<= 1) {
            ls0 += __shfl_xor_sync(0xffffffffu, ls0, off);
            ls1 += __shfl_xor_sync(0xffffffffu, ls1, off);
        }
        l0 = l0 * al0 + ls0;
        l1 = l1 * al1 + ls1;
#pragma unroll
        for (int ni = 0; ni < 8; ni++) {
            o[ni][0] *= al0; o[ni][1] *= al0;
            o[ni][2] *= al1; o[ni][3] *= al1;
        }

        // O += P V : P single fp16 (rel err ~2^-13), V hi/lo -> 2 passes
#pragma unroll
        for (int j = 0; j < 4; j++) {
            uint32_t pa[4], vbh[8][2], vbl[8][2];
            pa[0] = pack_f16(s[2*j][0],   s[2*j][1]);
            pa[1] = pack_f16(s[2*j][2],   s[2*j][3]);
            pa[2] = pack_f16(s[2*j+1][0], s[2*j+1][1]);
            pa[3] = pack_f16(s[2*j+1][2], s[2*j+1][3]);
#pragma unroll
            for (int ni = 0; ni < 8; ni++) {
                const int c0 = (ni * 8 + lr) * ATS + j * 16 + lc;
                vbh[ni][0] = *(const uint32_t*)(sVh + c0);
                vbh[ni][1] = *(const uint32_t*)(sVh + c0 + 8);
                vbl[ni][0] = *(const uint32_t*)(sVl + c0);
                vbl[ni][1] = *(const uint32_t*)(sVl + c0 + 8);
            }
#pragma unroll
            for (int ni = 0; ni < 8; ni++) mma16816(o[ni], pa, vbh[ni]);
#pragma unroll
            for (int ni = 0; ni < 8; ni++) mma16816(o[ni], pa, vbl[ni]);
        }
        __syncthreads();
    }

    // Epilogue: normalize, fp16 hi/lo split, write ctx [b,s,D]
    const float inv0 = 1.f / l0;
    const float inv1 = 1.f / l1;
    const int b = bh >> 4;
    const int h = bh & (HNUM - 1);
    const int s0 = qbase + qw + lr;
    const int s1 = s0 + 8;
#pragma unroll
    for (int ni = 0; ni < 8; ni++) {
        const int col = h * HD + ni * 8 + lc;
        {
            const float v0 = o[ni][0] * inv0, v1 = o[ni][1] * inv0;
            const float h0 = __half2float(__float2half(v0));
            const float h1 = __half2float(__float2half(v1));
            const size_t d = (size_t)(b * SDIM + s0) * DDIM + col;
            *(uint32_t*)(g_Xh + d) = pack_f16(v0, v1);
            *(uint32_t*)(g_Xl + d) = pack_f16(v0 - h0, v1 - h1);
        }
        {
            const float v0 = o[ni][2] * inv1, v1 = o[ni][3] * inv1;
            const float h0 = __half2float(__float2half(v0));
            const float h1 = __half2float(__float2half(v1));
            const size_t d = (size_t)(b * SDIM + s1) * DDIM + col;
            *(uint32_t*)(g_Xh + d) = pack_f16(v0, v1);
            *(uint32_t*)(g_Xl + d) = pack_f16(v0 - h0, v1 - h1);
        }
    }
}

// ---------------------------------------------------------------------------
// Launch
// ---------------------------------------------------------------------------
extern "C" void kernel_launch(void* const* d_in, const int* in_sizes, int n_in,
                              void* d_out, int out_size)
{
    const float* x  = (const float*)d_in[0];
    const float* Wq = (const float*)d_in[1];
    const float* bq = (const float*)d_in[2];
    const float* Wk = (const float*)d_in[3];
    const float* bk = (const float*)d_in[4];
    const float* Wv = (const float*)d_in[5];
    const float* bv = (const float*)d_in[6];
    const float* Wo = (const float*)d_in[7];
    const float* bo = (const float*)d_in[8];

    __half *xh, *xl, *wth, *wtl, *qh, *ql, *kh, *kl, *vth, *vtl;
    cudaGetSymbolAddress((void**)&xh,  g_Xh);
    cudaGetSymbolAddress((void**)&xl,  g_Xl);
    cudaGetSymbolAddress((void**)&wth, g_Wth);
    cudaGetSymbolAddress((void**)&wtl, g_Wtl);
    cudaGetSymbolAddress((void**)&qh,  g_Qh);
    cudaGetSymbolAddress((void**)&ql,  g_Ql);
    cudaGetSymbolAddress((void**)&kh,  g_Kh);
    cudaGetSymbolAddress((void**)&kl,  g_Kl);
    cudaGetSymbolAddress((void**)&vth, g_VTh);
    cudaGetSymbolAddress((void**)&vtl, g_VTl);

    cudaFuncSetAttribute(gemm_qkv, cudaFuncAttributeMaxDynamicSharedMemorySize, GEMM_SMEM);
    cudaFuncSetAttribute(gemm_out, cudaFuncAttributeMaxDynamicSharedMemorySize, GEMM_SMEM);
    cudaFuncSetAttribute(attn_mma, cudaFuncAttributeMaxDynamicSharedMemorySize, ATTN_SMEM);

    const int N_ELEM = ROWS * DDIM;
    const size_t WSZ = (size_t)DDIM * DDIM;

    convert_split<<<1024, 256>>>((const float4*)x, (uint2*)xh, (uint2*)xl, N_ELEM / 4);
    transpose_split4<<<dim3(32, 32, 4), dim3(32, 32)>>>(Wq, Wk, Wv, Wo, wth, wtl);

    gemm_qkv<<<dim3(3 * DDIM / 128, ROWS / 128), 256, GEMM_SMEM>>>(
        xh, xl, wth, wtl, bq, bk, bv, qh, ql, kh, kl, vth, vtl);

    attn_mma<<<dim3(SDIM / 128, BH), 256, ATTN_SMEM>>>();   // (16, 64)

    gemm_out<<<dim3(DDIM / 128, ROWS / 128), 256, GEMM_SMEM>>>(
        xh, xl, wth + 3 * WSZ, wtl + 3 * WSZ, bo, (float*)d_out);
}

// round 12
// speedup vs baseline: 3.4748x; 1.0468x over previous
#include <cuda_runtime.h>
#include <cuda_fp16.h>
#include <math.h>
#include <cstdint>

#define BDIM 4
#define SDIM 2048
#define DDIM 1024
#define HNUM 16
#define HD   64
#define ROWS (BDIM * SDIM)   // 8192
#define BH   (BDIM * HNUM)   // 64

// ---------------------------------------------------------------------------
// Scratch (fp16 hi/lo splits)
// ---------------------------------------------------------------------------
__device__ __half g_Xh[(size_t)ROWS * DDIM];
__device__ __half g_Xl[(size_t)ROWS * DDIM];
__device__ __half g_Wth[4][(size_t)DDIM * DDIM];   // W^T hi, [n][k]; QKVO contiguous
__device__ __half g_Wtl[4][(size_t)DDIM * DDIM];
__device__ __half g_Qh[(size_t)BH * SDIM * HD];    // [bh][s][hd] (pre-scaled 1/8)
__device__ __half g_Ql[(size_t)BH * SDIM * HD];
__device__ __half g_Kh[(size_t)BH * SDIM * HD];
__device__ __half g_Kl[(size_t)BH * SDIM * HD];
__device__ __half g_VTh[(size_t)BH * HD * SDIM];   // [bh][hd][s]
__device__ __half g_VTl[(size_t)BH * HD * SDIM];
__device__ __half g_CTXh[(size_t)ROWS * DDIM];     // attention output, single fp16

// ---------------------------------------------------------------------------
// Helpers
// ---------------------------------------------------------------------------
__device__ __forceinline__ void mma16816(float* c, const uint32_t* a, const uint32_t* b)
{
    asm volatile(
        "mma.sync.aligned.m16n8k16.row.col.f32.f16.f16.f32 "
        "{%0,%1,%2,%3}, {%4,%5,%6,%7}, {%8,%9}, {%0,%1,%2,%3};"
        : "+f"(c[0]), "+f"(c[1]), "+f"(c[2]), "+f"(c[3])
        : "r"(a[0]), "r"(a[1]), "r"(a[2]), "r"(a[3]), "r"(b[0]), "r"(b[1]));
}

// pack two fp32 -> f16x2 (first arg -> low half, second arg -> high half)
__device__ __forceinline__ uint32_t pack_f16(float lo, float hi)
{
    uint32_t r;
    asm("cvt.rn.f16x2.f32 %0, %1, %2;" : "=r"(r) : "f"(hi), "f"(lo));
    return r;
}

__device__ __forceinline__ void cpa16(void* sptr, const void* gptr)
{
    uint32_t s = (uint32_t)__cvta_generic_to_shared(sptr);
    asm volatile("cp.async.cg.shared.global [%0], [%1], 16;" :: "r"(s), "l"(gptr));
}
#define CPA_COMMIT() asm volatile("cp.async.commit_group;" ::: "memory")
#define CPA_WAIT(n)  asm volatile("cp.async.wait_group %0;" :: "n"(n) : "memory")

// ---------------------------------------------------------------------------
// Fused prep: z<4 -> transpose+split W_z ; z==4 -> vectorized convert of x
// block (32,32); grid (32,32,5)
// ---------------------------------------------------------------------------
__global__ void prep_all(
    const float* __restrict__ x,
    const float* __restrict__ W0, const float* __restrict__ W1,
    const float* __restrict__ W2, const float* __restrict__ W3,
    __half* __restrict__ xh, __half* __restrict__ xl,
    __half* __restrict__ ThB, __half* __restrict__ TlB)
{
    const int z = blockIdx.z;
    if (z < 4) {
        __shared__ float tile[32][33];
        const float* W = (z == 0) ? W0 : (z == 1) ? W1 : (z == 2) ? W2 : W3;
        __half* Th = ThB + (size_t)z * DDIM * DDIM;
        __half* Tl = TlB + (size_t)z * DDIM * DDIM;
        const int tx = threadIdx.x, ty = threadIdx.y;
        tile[ty][tx] = W[(size_t)(blockIdx.y * 32 + ty) * DDIM + blockIdx.x * 32 + tx];
        __syncthreads();
        const int on = blockIdx.x * 32 + ty;
        const int ok = blockIdx.y * 32 + tx;
        float v = tile[tx][ty];
        __half h = __float2half(v);
        Th[(size_t)on * DDIM + ok] = h;
        Tl[(size_t)on * DDIM + ok] = __float2half(v - __half2float(h));
    } else {
        // convert x: 2M float4 across 1024 blocks x 1024 threads -> 2 iters
        const int tid = threadIdx.y * 32 + threadIdx.x;
        const int bid = blockIdx.y * 32 + blockIdx.x;
        const int n4 = ROWS * DDIM / 4;
        const float4* src = (const float4*)x;
        uint2* hi = (uint2*)xh;
        uint2* lo = (uint2*)xl;
        for (int i = bid * 1024 + tid; i < n4; i += 1024 * 1024) {
            const float4 v = src[i];
            const float hx = __half2float(__float2half(v.x));
            const float hy = __half2float(__float2half(v.y));
            const float hz = __half2float(__float2half(v.z));
            const float hw = __half2float(__float2half(v.w));
            hi[i] = make_uint2(pack_f16(v.x, v.y), pack_f16(v.z, v.w));
            lo[i] = make_uint2(pack_f16(v.x - hx, v.y - hy), pack_f16(v.z - hz, v.w - hw));
        }
    }
}

// ---------------------------------------------------------------------------
// Shared GEMM core: CTA tile 128x128, K-chunk 64, cp.async 2-stage,
// 8 warps, pass-major mma ordering. PASSES=3: Ah*Bh + Ah*Bl + Al*Bh.
// PASSES=2: Ah*Bh + Ah*Bl (Al unused). B indexed by rows (bn + r).
// ---------------------------------------------------------------------------
#define AKS 72
#define TILE_E (128 * AKS)
#define STG_E  (4 * TILE_E)
#define GEMM_SMEM (2 * STG_E * 2)        // 147456 bytes (epilogue needs 68096)

struct GemmCore {
    float acc[4][4][4];
};

template <int PASSES>
__device__ __forceinline__ void gemm_core_run(
    char* smem, int t,
    const __half* Ah_g, const __half* Al_g,
    const __half* Bh_g, const __half* Bl_g,
    int bm, int bn, GemmCore& gc)
{
    __half* sbase = (__half*)smem;
    const int wid  = t >> 5;
    const int lane = t & 31;
    const int wr   = wid & 1;
    const int wc   = wid >> 1;
    const int lr   = lane >> 2;
    const int lc   = (lane & 3) << 1;

    auto issue_chunk = [&](int c, int stg) {
        __half* s0 = sbase + stg * STG_E;
        const int k0g = c * 64;
#pragma unroll
        for (int it = 0; it < 4; it++) {
            const int i = t + it * 256;
            const int r = i >> 3, seg = i & 7;
            const size_t ga = (size_t)(bm + r) * DDIM + k0g + seg * 8;
            const size_t gb = (size_t)(bn + r) * DDIM + k0g + seg * 8;
            const int so = r * AKS + seg * 8;
            cpa16(s0 + so,              Ah_g + ga);
            if (PASSES == 3) cpa16(s0 + TILE_E + so, Al_g + ga);
            cpa16(s0 + 2 * TILE_E + so, Bh_g + gb);
            cpa16(s0 + 3 * TILE_E + so, Bl_g + gb);
        }
    };

#pragma unroll
    for (int i = 0; i < 4; i++)
#pragma unroll
        for (int j = 0; j < 4; j++)
#pragma unroll
            for (int r = 0; r < 4; r++) gc.acc[i][j][r] = 0.f;

    issue_chunk(0, 0);
    CPA_COMMIT();

    for (int c = 0; c < 16; c++) {
        if (c < 15) { issue_chunk(c + 1, (c + 1) & 1); CPA_COMMIT(); CPA_WAIT(1); }
        else        { CPA_WAIT(0); }
        __syncthreads();

        const __half* sAh = sbase + (c & 1) * STG_E;
        const __half* sAl = sAh + TILE_E;
        const __half* sBh = sAh + 2 * TILE_E;
        const __half* sBl = sAh + 3 * TILE_E;

#pragma unroll
        for (int kk = 0; kk < 4; kk++) {
            const int k0 = kk * 16;
            uint32_t ah[4][4], al[4][4], bh[4][2], bl[4][2];
#pragma unroll
            for (int mi = 0; mi < 4; mi++) {
                const int r0 = (wr * 64 + mi * 16 + lr) * AKS + k0 + lc;
                const int r8 = r0 + 8 * AKS;
                ah[mi][0] = *(const uint32_t*)(sAh + r0);
                ah[mi][1] = *(const uint32_t*)(sAh + r8);
                ah[mi][2] = *(const uint32_t*)(sAh + r0 + 8);
                ah[mi][3] = *(const uint32_t*)(sAh + r8 + 8);
                if (PASSES == 3) {
                    al[mi][0] = *(const uint32_t*)(sAl + r0);
                    al[mi][1] = *(const uint32_t*)(sAl + r8);
                    al[mi][2] = *(const uint32_t*)(sAl + r0 + 8);
                    al[mi][3] = *(const uint32_t*)(sAl + r8 + 8);
                }
            }
#pragma unroll
            for (int ni = 0; ni < 4; ni++) {
                const int c0 = (wc * 32 + ni * 8 + lr) * AKS + k0 + lc;
                bh[ni][0] = *(const uint32_t*)(sBh + c0);
                bh[ni][1] = *(const uint32_t*)(sBh + c0 + 8);
                bl[ni][0] = *(const uint32_t*)(sBl + c0);
                bl[ni][1] = *(const uint32_t*)(sBl + c0 + 8);
            }
            // pass-major: consecutive mma hit distinct accumulators
#pragma unroll
            for (int mi = 0; mi < 4; mi++)
#pragma unroll
                for (int ni = 0; ni < 4; ni++)
                    mma16816(gc.acc[mi][ni], ah[mi], bh[ni]);
#pragma unroll
            for (int mi = 0; mi < 4; mi++)
#pragma unroll
                for (int ni = 0; ni < 4; ni++)
                    mma16816(gc.acc[mi][ni], ah[mi], bl[ni]);
            if (PASSES == 3) {
#pragma unroll
                for (int mi = 0; mi < 4; mi++)
#pragma unroll
                    for (int ni = 0; ni < 4; ni++)
                        mma16816(gc.acc[mi][ni], al[mi], bh[ni]);
            }
        }
        __syncthreads();
    }

    // stage C through smem (stride 133) for coalesced epilogue
    float* Ds = (float*)smem;
#pragma unroll
    for (int mi = 0; mi < 4; mi++) {
        const int r = wr * 64 + mi * 16 + lr;
#pragma unroll
        for (int ni = 0; ni < 4; ni++) {
            const int cc = wc * 32 + ni * 8 + lc;
            Ds[r * 133 + cc]           = gc.acc[mi][ni][0];
            Ds[r * 133 + cc + 1]       = gc.acc[mi][ni][1];
            Ds[(r + 8) * 133 + cc]     = gc.acc[mi][ni][2];
            Ds[(r + 8) * 133 + cc + 1] = gc.acc[mi][ni][3];
        }
    }
    __syncthreads();
}

// ---------------------------------------------------------------------------
// Fused QKV projection: C[8192, 3072], QKV weights contiguous, 3-pass.
// which = bn>>10: 0=Q (scale 1/8, [b,h,s,hd]), 1=K ([b,h,s,hd]), 2=V ([b,h,hd,s])
// ---------------------------------------------------------------------------
__global__ __launch_bounds__(256) void gemm_qkv(
    const __half* __restrict__ Ah_g, const __half* __restrict__ Al_g,
    const __half* __restrict__ Wh_g, const __half* __restrict__ Wl_g,
    const float* __restrict__ bq, const float* __restrict__ bk, const float* __restrict__ bv,
    __half* __restrict__ qh, __half* __restrict__ ql,
    __half* __restrict__ kh, __half* __restrict__ kl,
    __half* __restrict__ vth, __half* __restrict__ vtl)
{
    extern __shared__ char smem[];
    const int t  = threadIdx.x;
    const int bn = blockIdx.x * 128;
    const int bm = blockIdx.y * 128;
    const int which = bn >> 10;

    GemmCore gc;
    gemm_core_run<3>(smem, t, Ah_g, Al_g, Wh_g, Wl_g, bm, bn, gc);

    const float* Ds = (const float*)smem;
    const float* bias = (which == 0) ? bq : (which == 1) ? bk : bv;
    const float oscale = (which == 0) ? 0.125f : 1.0f;
    const int colm_base = bn & 1023;

    if (which < 2) {
        __half* oh = (which == 0) ? qh : kh;
        __half* ol = (which == 0) ? ql : kl;
        for (int idx = t; idx < 128 * 128; idx += 256) {
            const int r = idx >> 7, cc = idx & 127;
            const int row = bm + r;
            const int colm = colm_base + cc;
            const float v = (Ds[r * 133 + cc] + bias[colm]) * oscale;
            const int b = row >> 11, s = row & (SDIM - 1);
            const int h = colm >> 6, hd = colm & (HD - 1);
            const size_t dst = (size_t)((b * HNUM + h) * SDIM + s) * HD + hd;
            __half hh = __float2half(v);
            oh[dst] = hh;
            ol[dst] = __float2half(v - __half2float(hh));
        }
    } else {
        for (int idx = t; idx < 128 * 128; idx += 256) {
            const int r = idx & 127, cc = idx >> 7;
            const int row = bm + r;
            const int colm = colm_base + cc;
            const float v = Ds[r * 133 + cc] + bias[colm];
            const int b = row >> 11, s = row & (SDIM - 1);
            const int h = colm >> 6, hd = colm & (HD - 1);
            const size_t dst = (size_t)((b * HNUM + h) * HD + hd) * SDIM + s;
            __half hh = __float2half(v);
            vth[dst] = hh;
            vtl[dst] = __float2half(v - __half2float(hh));
        }
    }
}

// O-projection: ctx single fp16 (2-pass), fp32 out, plain row-major
__global__ __launch_bounds__(256) void gemm_out(
    const __half* __restrict__ Ah_g,
    const __half* __restrict__ Bh_g, const __half* __restrict__ Bl_g,
    const float* __restrict__ bias, float* __restrict__ outF)
{
    extern __shared__ char smem[];
    const int t  = threadIdx.x;
    const int bn = blockIdx.x * 128;
    const int bm = blockIdx.y * 128;

    GemmCore gc;
    gemm_core_run<2>(smem, t, Ah_g, Ah_g, Bh_g, Bl_g, bm, bn, gc);

    const float* Ds = (const float*)smem;
    for (int idx = t; idx < 128 * 128; idx += 256) {
        const int r = idx >> 7, cc = idx & 127;
        outF[(size_t)(bm + r) * DDIM + bn + cc] = Ds[r * 133 + cc] + bias[bn + cc];
    }
}

// ---------------------------------------------------------------------------
// Flash attention, fp16 splits. QK^T: 3-pass hi/lo. PV: P single fp16 x
// V hi/lo = 2 passes. cp.async 2-stage KV pipeline, pass-major ordering.
// Writes ctx as single fp16 to g_CTXh.
// ---------------------------------------------------------------------------
#define ATS 72
#define QSZ_E   (2 * 128 * ATS)
#define KVSTG_E (4 * 64 * ATS)
#define ATTN_SMEM ((QSZ_E + 2 * KVSTG_E) * 2)   // 110592 bytes

__global__ __launch_bounds__(256) void attn_mma()
{
    extern __shared__ char smraw[];
    __half* sm = (__half*)smraw;
    __half* sQh = sm;
    __half* sQl = sm + 128 * ATS;

    const int t    = threadIdx.x;
    const int wid  = t >> 5;
    const int lane = t & 31;
    const int lr   = lane >> 2;
    const int lc   = (lane & 3) << 1;
    const int bh    = blockIdx.y;
    const int qbase = blockIdx.x * 128;
    const int qw    = wid * 16;

    const __half* Qh = g_Qh + (size_t)bh * SDIM * HD;
    const __half* Ql = g_Ql + (size_t)bh * SDIM * HD;
    const __half* Kh = g_Kh + (size_t)bh * SDIM * HD;
    const __half* Kl = g_Kl + (size_t)bh * SDIM * HD;
    const __half* Vh = g_VTh + (size_t)bh * HD * SDIM;
    const __half* Vl = g_VTl + (size_t)bh * HD * SDIM;

    auto issue_kv = [&](int c, int stg) {
        __half* s0 = sm + QSZ_E + stg * KVSTG_E;
        const int kb = c * 64;
#pragma unroll
        for (int it = 0; it < 2; it++) {
            const int i = t + it * 256;
            const int r = i >> 3, seg = i & 7;
            const int so = r * ATS + seg * 8;
            const size_t gk = (size_t)(kb + r) * HD + seg * 8;
            const size_t gv = (size_t)r * SDIM + kb + seg * 8;
            cpa16(s0 + so,                Kh + gk);
            cpa16(s0 + 64 * ATS + so,     Kl + gk);
            cpa16(s0 + 2 * 64 * ATS + so, Vh + gv);
            cpa16(s0 + 3 * 64 * ATS + so, Vl + gv);
        }
    };

#pragma unroll
    for (int it = 0; it < 4; it++) {
        const int i = t + it * 256;
        const int r = i >> 3, seg = i & 7;
        const size_t g = (size_t)(qbase + r) * HD + seg * 8;
        const int so = r * ATS + seg * 8;
        cpa16(sQh + so, Qh + g);
        cpa16(sQl + so, Ql + g);
    }
    issue_kv(0, 0);
    CPA_COMMIT();

    float o[8][4];
#pragma unroll
    for (int i = 0; i < 8; i++)
#pragma unroll
        for (int j = 0; j < 4; j++) o[i][j] = 0.f;
    float m0 = -1e30f, m1 = -1e30f, l0 = 0.f, l1 = 0.f;

    for (int c = 0; c < 32; c++) {
        if (c < 31) { issue_kv(c + 1, (c + 1) & 1); CPA_COMMIT(); CPA_WAIT(1); }
        else        { CPA_WAIT(0); }
        __syncthreads();

        const __half* sKh = sm + QSZ_E + (c & 1) * KVSTG_E;
        const __half* sKl = sKh + 64 * ATS;
        const __half* sVh = sKh + 2 * 64 * ATS;
        const __half* sVl = sKh + 3 * 64 * ATS;

        // S = Q K^T (Q pre-scaled by 1/8), 3-pass hi/lo
        float s[8][4];
#pragma unroll
        for (int i = 0; i < 8; i++)
#pragma unroll
            for (int j = 0; j < 4; j++) s[i][j] = 0.f;

#pragma unroll
        for (int kk = 0; kk < 4; kk++) {
            const int k0 = kk * 16;
            uint32_t qa_h[4], qa_l[4], kbh[8][2], kbl[8][2];
            const int r0 = (qw + lr) * ATS + k0 + lc;
            const int r8 = r0 + 8 * ATS;
            qa_h[0] = *(const uint32_t*)(sQh + r0);
            qa_h[1] = *(const uint32_t*)(sQh + r8);
            qa_h[2] = *(const uint32_t*)(sQh + r0 + 8);
            qa_h[3] = *(const uint32_t*)(sQh + r8 + 8);
            qa_l[0] = *(const uint32_t*)(sQl + r0);
            qa_l[1] = *(const uint32_t*)(sQl + r8);
            qa_l[2] = *(const uint32_t*)(sQl + r0 + 8);
            qa_l[3] = *(const uint32_t*)(sQl + r8 + 8);
#pragma unroll
            for (int ni = 0; ni < 8; ni++) {
                const int c0 = (ni * 8 + lr) * ATS + k0 + lc;
                kbh[ni][0] = *(const uint32_t*)(sKh + c0);
                kbh[ni][1] = *(const uint32_t*)(sKh + c0 + 8);
                kbl[ni][0] = *(const uint32_t*)(sKl + c0);
                kbl[ni][1] = *(const uint32_t*)(sKl + c0 + 8);
            }
#pragma unroll
            for (int ni = 0; ni < 8; ni++) mma16816(s[ni], qa_h, kbh[ni]);
#pragma unroll
            for (int ni = 0; ni < 8; ni++) mma16816(s[ni], qa_h, kbl[ni]);
#pragma unroll
            for (int ni = 0; ni < 8; ni++) mma16816(s[ni], qa_l, kbh[ni]);
        }

        // Online softmax
        float mx0 = -1e30f, mx1 = -1e30f;
#pragma unroll
        for (int ni = 0; ni < 8; ni++) {
            mx0 = fmaxf(mx0, fmaxf(s[ni][0], s[ni][1]));
            mx1 = fmaxf(mx1, fmaxf(s[ni][2], s[ni][3]));
        }
#pragma unroll
        for (int off = 1; off < 4; off <<= 1) {
            mx0 = fmaxf(mx0, __shfl_xor_sync(0xffffffffu, mx0, off));
            mx1 = fmaxf(mx1, __shfl_xor_sync(0xffffffffu, mx1, off));
        }
        const float mn0 = fmaxf(m0, mx0);
        const float mn1 = fmaxf(m1, mx1);
        const float al0 = __expf(m0 - mn0);
        const float al1 = __expf(m1 - mn1);
        m0 = mn0; m1 = mn1;

        float ls0 = 0.f, ls1 = 0.f;
#pragma unroll
        for (int ni = 0; ni < 8; ni++) {
            s[ni][0] = __expf(s[ni][0] - mn0);
            s[ni][1] = __expf(s[ni][1] - mn0);
            s[ni][2] = __expf(s[ni][2] - mn1);
            s[ni][3] = __expf(s[ni][3] - mn1);
            ls0 += s[ni][0] + s[ni][1];
            ls1 += s[ni][2] + s[ni][3];
        }
#pragma unroll
        for (int off = 1; off < 4; off <<= 1) {
            ls0 += __shfl_xor_sync(0xffffffffu, ls0, off);
            ls1 += __shfl_xor_sync(0xffffffffu, ls1, off);
        }
        l0 = l0 * al0 + ls0;
        l1 = l1 * al1 + ls1;
#pragma unroll
        for (int ni = 0; ni < 8; ni++) {
            o[ni][0] *= al0; o[ni][1] *= al0;
            o[ni][2] *= al1; o[ni][3] *= al1;
        }

        // O += P V : P single fp16, V hi/lo -> 2 passes
#pragma unroll
        for (int j = 0; j < 4; j++) {
            uint32_t pa[4], vbh[8][2], vbl[8][2];
            pa[0] = pack_f16(s[2*j][0],   s[2*j][1]);
            pa[1] = pack_f16(s[2*j][2],   s[2*j][3]);
            pa[2] = pack_f16(s[2*j+1][0], s[2*j+1][1]);
            pa[3] = pack_f16(s[2*j+1][2], s[2*j+1][3]);
#pragma unroll
            for (int ni = 0; ni < 8; ni++) {
                const int c0 = (ni * 8 + lr) * ATS + j * 16 + lc;
                vbh[ni][0] = *(const uint32_t*)(sVh + c0);
                vbh[ni][1] = *(const uint32_t*)(sVh + c0 + 8);
                vbl[ni][0] = *(const uint32_t*)(sVl + c0);
                vbl[ni][1] = *(const uint32_t*)(sVl + c0 + 8);
            }
#pragma unroll
            for (int ni = 0; ni < 8; ni++) mma16816(o[ni], pa, vbh[ni]);
#pragma unroll
            for (int ni = 0; ni < 8; ni++) mma16816(o[ni], pa, vbl[ni]);
        }
        __syncthreads();
    }

    // Epilogue: normalize, write ctx single fp16 [b,s,D]
    const float inv0 = 1.f / l0;
    const float inv1 = 1.f / l1;
    const int b = bh >> 4;
    const int h = bh & (HNUM - 1);
    const int s0 = qbase + qw + lr;
    const int s1 = s0 + 8;
#pragma unroll
    for (int ni = 0; ni < 8; ni++) {
        const int col = h * HD + ni * 8 + lc;
        *(uint32_t*)(g_CTXh + (size_t)(b * SDIM + s0) * DDIM + col) =
            pack_f16(o[ni][0] * inv0, o[ni][1] * inv0);
        *(uint32_t*)(g_CTXh + (size_t)(b * SDIM + s1) * DDIM + col) =
            pack_f16(o[ni][2] * inv1, o[ni][3] * inv1);
    }
}

// ---------------------------------------------------------------------------
// Launch
// ---------------------------------------------------------------------------
extern "C" void kernel_launch(void* const* d_in, const int* in_sizes, int n_in,
                              void* d_out, int out_size)
{
    const float* x  = (const float*)d_in[0];
    const float* Wq = (const float*)d_in[1];
    const float* bq = (const float*)d_in[2];
    const float* Wk = (const float*)d_in[3];
    const float* bk = (const float*)d_in[4];
    const float* Wv = (const float*)d_in[5];
    const float* bv = (const float*)d_in[6];
    const float* Wo = (const float*)d_in[7];
    const float* bo = (const float*)d_in[8];

    __half *xh, *xl, *wth, *wtl, *qh, *ql, *kh, *kl, *vth, *vtl, *ctxh;
    cudaGetSymbolAddress((void**)&xh,   g_Xh);
    cudaGetSymbolAddress((void**)&xl,   g_Xl);
    cudaGetSymbolAddress((void**)&wth,  g_Wth);
    cudaGetSymbolAddress((void**)&wtl,  g_Wtl);
    cudaGetSymbolAddress((void**)&qh,   g_Qh);
    cudaGetSymbolAddress((void**)&ql,   g_Ql);
    cudaGetSymbolAddress((void**)&kh,   g_Kh);
    cudaGetSymbolAddress((void**)&kl,   g_Kl);
    cudaGetSymbolAddress((void**)&vth,  g_VTh);
    cudaGetSymbolAddress((void**)&vtl,  g_VTl);
    cudaGetSymbolAddress((void**)&ctxh, g_CTXh);

    cudaFuncSetAttribute(gemm_qkv, cudaFuncAttributeMaxDynamicSharedMemorySize, GEMM_SMEM);
    cudaFuncSetAttribute(gemm_out, cudaFuncAttributeMaxDynamicSharedMemorySize, GEMM_SMEM);
    cudaFuncSetAttribute(attn_mma, cudaFuncAttributeMaxDynamicSharedMemorySize, ATTN_SMEM);

    const size_t WSZ = (size_t)DDIM * DDIM;

    prep_all<<<dim3(32, 32, 5), dim3(32, 32)>>>(x, Wq, Wk, Wv, Wo, xh, xl, wth, wtl);

    gemm_qkv<<<dim3(3 * DDIM / 128, ROWS / 128), 256, GEMM_SMEM>>>(
        xh, xl, wth, wtl, bq, bk, bv, qh, ql, kh, kl, vth, vtl);

    attn_mma<<<dim3(SDIM / 128, BH), 256, ATTN_SMEM>>>();   // (16, 64)

    gemm_out<<<dim3(DDIM / 128, ROWS / 128), 256, GEMM_SMEM>>>(
        ctxh, wth + 3 * WSZ, wtl + 3 * WSZ, bo, (float*)d_out);
}

// round 13
// speedup vs baseline: 3.7618x; 1.0826x over previous
#include <cuda_runtime.h>
#include <cuda_fp16.h>
#include <math.h>
#include <cstdint>

#define BDIM 4
#define SDIM 2048
#define DDIM 1024
#define HNUM 16
#define HD   64
#define ROWS (BDIM * SDIM)   // 8192
#define BH   (BDIM * HNUM)   // 64

// ---------------------------------------------------------------------------
// Scratch (fp16 hi/lo splits)
// ---------------------------------------------------------------------------
__device__ __half g_Xh[(size_t)ROWS * DDIM];
__device__ __half g_Xl[(size_t)ROWS * DDIM];
__device__ __half g_Wth[4][(size_t)DDIM * DDIM];   // W^T hi, [n][k]; QKVO contiguous
__device__ __half g_Wtl[4][(size_t)DDIM * DDIM];
__device__ __half g_Qh[(size_t)BH * SDIM * HD];    // [bh][s][hd] (pre-scaled 1/8)
__device__ __half g_Ql[(size_t)BH * SDIM * HD];
__device__ __half g_Kh[(size_t)BH * SDIM * HD];    // K single fp16 (hi only used)
__device__ __half g_VTh[(size_t)BH * HD * SDIM];   // [bh][hd][s]
__device__ __half g_VTl[(size_t)BH * HD * SDIM];
__device__ __half g_CTXh[(size_t)ROWS * DDIM];     // attention output, single fp16

// ---------------------------------------------------------------------------
// Helpers
// ---------------------------------------------------------------------------
__device__ __forceinline__ void mma16816(float* c, const uint32_t* a, const uint32_t* b)
{
    asm volatile(
        "mma.sync.aligned.m16n8k16.row.col.f32.f16.f16.f32 "
        "{%0,%1,%2,%3}, {%4,%5,%6,%7}, {%8,%9}, {%0,%1,%2,%3};"
        : "+f"(c[0]), "+f"(c[1]), "+f"(c[2]), "+f"(c[3])
        : "r"(a[0]), "r"(a[1]), "r"(a[2]), "r"(a[3]), "r"(b[0]), "r"(b[1]));
}

// pack two fp32 -> f16x2 (first arg -> low half, second arg -> high half)
__device__ __forceinline__ uint32_t pack_f16(float lo, float hi)
{
    uint32_t r;
    asm("cvt.rn.f16x2.f32 %0, %1, %2;" : "=r"(r) : "f"(hi), "f"(lo));
    return r;
}

__device__ __forceinline__ void cpa16(void* sptr, const void* gptr)
{
    uint32_t s = (uint32_t)__cvta_generic_to_shared(sptr);
    asm volatile("cp.async.cg.shared.global [%0], [%1], 16;" :: "r"(s), "l"(gptr));
}
#define CPA_COMMIT() asm volatile("cp.async.commit_group;" ::: "memory")
#define CPA_WAIT(n)  asm volatile("cp.async.wait_group %0;" :: "n"(n) : "memory")

// ---------------------------------------------------------------------------
// Fused prep: z<4 -> transpose+split W_z ; z==4 -> vectorized convert of x
// ---------------------------------------------------------------------------
__global__ void prep_all(
    const float* __restrict__ x,
    const float* __restrict__ W0, const float* __restrict__ W1,
    const float* __restrict__ W2, const float* __restrict__ W3,
    __half* __restrict__ xh, __half* __restrict__ xl,
    __half* __restrict__ ThB, __half* __restrict__ TlB)
{
    const int z = blockIdx.z;
    if (z < 4) {
        __shared__ float tile[32][33];
        const float* W = (z == 0) ? W0 : (z == 1) ? W1 : (z == 2) ? W2 : W3;
        __half* Th = ThB + (size_t)z * DDIM * DDIM;
        __half* Tl = TlB + (size_t)z * DDIM * DDIM;
        const int tx = threadIdx.x, ty = threadIdx.y;
        tile[ty][tx] = W[(size_t)(blockIdx.y * 32 + ty) * DDIM + blockIdx.x * 32 + tx];
        __syncthreads();
        const int on = blockIdx.x * 32 + ty;
        const int ok = blockIdx.y * 32 + tx;
        float v = tile[tx][ty];
        __half h = __float2half(v);
        Th[(size_t)on * DDIM + ok] = h;
        Tl[(size_t)on * DDIM + ok] = __float2half(v - __half2float(h));
    } else {
        const int tid = threadIdx.y * 32 + threadIdx.x;
        const int bid = blockIdx.y * 32 + blockIdx.x;
        const int n4 = ROWS * DDIM / 4;
        const float4* src = (const float4*)x;
        uint2* hi = (uint2*)xh;
        uint2* lo = (uint2*)xl;
        for (int i = bid * 1024 + tid; i < n4; i += 1024 * 1024) {
            const float4 v = src[i];
            const float hx = __half2float(__float2half(v.x));
            const float hy = __half2float(__float2half(v.y));
            const float hz = __half2float(__float2half(v.z));
            const float hw = __half2float(__float2half(v.w));
            hi[i] = make_uint2(pack_f16(v.x, v.y), pack_f16(v.z, v.w));
            lo[i] = make_uint2(pack_f16(v.x - hx, v.y - hy), pack_f16(v.z - hz, v.w - hw));
        }
    }
}

// ---------------------------------------------------------------------------
// Shared GEMM core: CTA tile 128x128, K-chunk 64, cp.async 2-stage,
// 8 warps, pass-major mma ordering. PASSES=3: Ah*Bh+Ah*Bl+Al*Bh.
// PASSES=2: Ah*Bh+Ah*Bl. B indexed by rows (bn + r).
// ---------------------------------------------------------------------------
#define AKS 72
#define TILE_E (128 * AKS)
#define STG_E  (4 * TILE_E)
#define GEMM_SMEM (2 * STG_E * 2)        // 147456 bytes

struct GemmCore {
    float acc[4][4][4];
};

template <int PASSES>
__device__ __forceinline__ void gemm_core_run(
    char* smem, int t,
    const __half* Ah_g, const __half* Al_g,
    const __half* Bh_g, const __half* Bl_g,
    int bm, int bn, GemmCore& gc)
{
    __half* sbase = (__half*)smem;
    const int wid  = t >> 5;
    const int lane = t & 31;
    const int wr   = wid & 1;
    const int wc   = wid >> 1;
    const int lr   = lane >> 2;
    const int lc   = (lane & 3) << 1;

    auto issue_chunk = [&](int c, int stg) {
        __half* s0 = sbase + stg * STG_E;
        const int k0g = c * 64;
#pragma unroll
        for (int it = 0; it < 4; it++) {
            const int i = t + it * 256;
            const int r = i >> 3, seg = i & 7;
            const size_t ga = (size_t)(bm + r) * DDIM + k0g + seg * 8;
            const size_t gb = (size_t)(bn + r) * DDIM + k0g + seg * 8;
            const int so = r * AKS + seg * 8;
            cpa16(s0 + so,              Ah_g + ga);
            if (PASSES == 3) cpa16(s0 + TILE_E + so, Al_g + ga);
            cpa16(s0 + 2 * TILE_E + so, Bh_g + gb);
            cpa16(s0 + 3 * TILE_E + so, Bl_g + gb);
        }
    };

#pragma unroll
    for (int i = 0; i < 4; i++)
#pragma unroll
        for (int j = 0; j < 4; j++)
#pragma unroll
            for (int r = 0; r < 4; r++) gc.acc[i][j][r] = 0.f;

    issue_chunk(0, 0);
    CPA_COMMIT();

    for (int c = 0; c < 16; c++) {
        if (c < 15) { issue_chunk(c + 1, (c + 1) & 1); CPA_COMMIT(); CPA_WAIT(1); }
        else        { CPA_WAIT(0); }
        __syncthreads();

        const __half* sAh = sbase + (c & 1) * STG_E;
        const __half* sAl = sAh + TILE_E;
        const __half* sBh = sAh + 2 * TILE_E;
        const __half* sBl = sAh + 3 * TILE_E;

#pragma unroll
        for (int kk = 0; kk < 4; kk++) {
            const int k0 = kk * 16;
            uint32_t ah[4][4], al[4][4], bh[4][2], bl[4][2];
#pragma unroll
            for (int mi = 0; mi < 4; mi++) {
                const int r0 = (wr * 64 + mi * 16 + lr) * AKS + k0 + lc;
                const int r8 = r0 + 8 * AKS;
                ah[mi][0] = *(const uint32_t*)(sAh + r0);
                ah[mi][1] = *(const uint32_t*)(sAh + r8);
                ah[mi][2] = *(const uint32_t*)(sAh + r0 + 8);
                ah[mi][3] = *(const uint32_t*)(sAh + r8 + 8);
                if (PASSES == 3) {
                    al[mi][0] = *(const uint32_t*)(sAl + r0);
                    al[mi][1] = *(const uint32_t*)(sAl + r8);
                    al[mi][2] = *(const uint32_t*)(sAl + r0 + 8);
                    al[mi][3] = *(const uint32_t*)(sAl + r8 + 8);
                }
            }
#pragma unroll
            for (int ni = 0; ni < 4; ni++) {
                const int c0 = (wc * 32 + ni * 8 + lr) * AKS + k0 + lc;
                bh[ni][0] = *(const uint32_t*)(sBh + c0);
                bh[ni][1] = *(const uint32_t*)(sBh + c0 + 8);
                bl[ni][0] = *(const uint32_t*)(sBl + c0);
                bl[ni][1] = *(const uint32_t*)(sBl + c0 + 8);
            }
#pragma unroll
            for (int mi = 0; mi < 4; mi++)
#pragma unroll
                for (int ni = 0; ni < 4; ni++)
                    mma16816(gc.acc[mi][ni], ah[mi], bh[ni]);
#pragma unroll
            for (int mi = 0; mi < 4; mi++)
#pragma unroll
                for (int ni = 0; ni < 4; ni++)
                    mma16816(gc.acc[mi][ni], ah[mi], bl[ni]);
            if (PASSES == 3) {
#pragma unroll
                for (int mi = 0; mi < 4; mi++)
#pragma unroll
                    for (int ni = 0; ni < 4; ni++)
                        mma16816(gc.acc[mi][ni], al[mi], bh[ni]);
            }
        }
        __syncthreads();
    }

    float* Ds = (float*)smem;
#pragma unroll
    for (int mi = 0; mi < 4; mi++) {
        const int r = wr * 64 + mi * 16 + lr;
#pragma unroll
        for (int ni = 0; ni < 4; ni++) {
            const int cc = wc * 32 + ni * 8 + lc;
            Ds[r * 133 + cc]           = gc.acc[mi][ni][0];
            Ds[r * 133 + cc + 1]       = gc.acc[mi][ni][1];
            Ds[(r + 8) * 133 + cc]     = gc.acc[mi][ni][2];
            Ds[(r + 8) * 133 + cc + 1] = gc.acc[mi][ni][3];
        }
    }
    __syncthreads();
}

// ---------------------------------------------------------------------------
// Fused QKV projection. which = bn>>10: 0=Q (1/8, hi/lo), 1=K (single fp16),
// 2=V ([b,h,hd,s] hi/lo)
// ---------------------------------------------------------------------------
__global__ __launch_bounds__(256) void gemm_qkv(
    const __half* __restrict__ Ah_g, const __half* __restrict__ Al_g,
    const __half* __restrict__ Wh_g, const __half* __restrict__ Wl_g,
    const float* __restrict__ bq, const float* __restrict__ bk, const float* __restrict__ bv,
    __half* __restrict__ qh, __half* __restrict__ ql,
    __half* __restrict__ kh,
    __half* __restrict__ vth, __half* __restrict__ vtl)
{
    extern __shared__ char smem[];
    const int t  = threadIdx.x;
    const int bn = blockIdx.x * 128;
    const int bm = blockIdx.y * 128;
    const int which = bn >> 10;

    GemmCore gc;
    gemm_core_run<3>(smem, t, Ah_g, Al_g, Wh_g, Wl_g, bm, bn, gc);

    const float* Ds = (const float*)smem;
    const float* bias = (which == 0) ? bq : (which == 1) ? bk : bv;
    const int colm_base = bn & 1023;

    if (which == 0) {
        for (int idx = t; idx < 128 * 128; idx += 256) {
            const int r = idx >> 7, cc = idx & 127;
            const int row = bm + r;
            const int colm = colm_base + cc;
            const float v = (Ds[r * 133 + cc] + bias[colm]) * 0.125f;
            const int b = row >> 11, s = row & (SDIM - 1);
            const int h = colm >> 6, hd = colm & (HD - 1);
            const size_t dst = (size_t)((b * HNUM + h) * SDIM + s) * HD + hd;
            __half hh = __float2half(v);
            qh[dst] = hh;
            ql[dst] = __float2half(v - __half2float(hh));
        }
    } else if (which == 1) {
        for (int idx = t; idx < 128 * 128; idx += 256) {
            const int r = idx >> 7, cc = idx & 127;
            const int row = bm + r;
            const int colm = colm_base + cc;
            const float v = Ds[r * 133 + cc] + bias[colm];
            const int b = row >> 11, s = row & (SDIM - 1);
            const int h = colm >> 6, hd = colm & (HD - 1);
            kh[(size_t)((b * HNUM + h) * SDIM + s) * HD + hd] = __float2half(v);
        }
    } else {
        for (int idx = t; idx < 128 * 128; idx += 256) {
            const int r = idx & 127, cc = idx >> 7;
            const int row = bm + r;
            const int colm = colm_base + cc;
            const float v = Ds[r * 133 + cc] + bias[colm];
            const int b = row >> 11, s = row & (SDIM - 1);
            const int h = colm >> 6, hd = colm & (HD - 1);
            const size_t dst = (size_t)((b * HNUM + h) * HD + hd) * SDIM + s;
            __half hh = __float2half(v);
            vth[dst] = hh;
            vtl[dst] = __float2half(v - __half2float(hh));
        }
    }
}

// O-projection: ctx single fp16 (2-pass), fp32 out
__global__ __launch_bounds__(256) void gemm_out(
    const __half* __restrict__ Ah_g,
    const __half* __restrict__ Bh_g, const __half* __restrict__ Bl_g,
    const float* __restrict__ bias, float* __restrict__ outF)
{
    extern __shared__ char smem[];
    const int t  = threadIdx.x;
    const int bn = blockIdx.x * 128;
    const int bm = blockIdx.y * 128;

    GemmCore gc;
    gemm_core_run<2>(smem, t, Ah_g, Ah_g, Bh_g, Bl_g, bm, bn, gc);

    const float* Ds = (const float*)smem;
    for (int idx = t; idx < 128 * 128; idx += 256) {
        const int r = idx >> 7, cc = idx & 127;
        outF[(size_t)(bm + r) * DDIM + bn + cc] = Ds[r * 133 + cc] + bias[bn + cc];
    }
}

// ---------------------------------------------------------------------------
// Flash attention. QK^T: 2-pass (Q hi/lo x K single). PV: 2-pass (P single x
// V hi/lo). cp.async 2-stage KV pipeline (3 tiles/stage), pass-major.
// ---------------------------------------------------------------------------
#define ATS 72
#define QSZ_E   (2 * 128 * ATS)            // Q hi+lo
#define KVT_E   (64 * ATS)                 // one 64-row tile
#define KVSTG_E (3 * KVT_E)                // Kh, Vh, Vl
#define ATTN_SMEM ((QSZ_E + 2 * KVSTG_E) * 2)   // 92160 bytes

__global__ __launch_bounds__(256) void attn_mma()
{
    extern __shared__ char smraw[];
    __half* sm = (__half*)smraw;
    __half* sQh = sm;
    __half* sQl = sm + 128 * ATS;

    const int t    = threadIdx.x;
    const int wid  = t >> 5;
    const int lane = t & 31;
    const int lr   = lane >> 2;
    const int lc   = (lane & 3) << 1;
    const int bh    = blockIdx.y;
    const int qbase = blockIdx.x * 128;
    const int qw    = wid * 16;

    const __half* Qh = g_Qh + (size_t)bh * SDIM * HD;
    const __half* Ql = g_Ql + (size_t)bh * SDIM * HD;
    const __half* Kh = g_Kh + (size_t)bh * SDIM * HD;
    const __half* Vh = g_VTh + (size_t)bh * HD * SDIM;
    const __half* Vl = g_VTl + (size_t)bh * HD * SDIM;

    auto issue_kv = [&](int c, int stg) {
        __half* s0 = sm + QSZ_E + stg * KVSTG_E;
        const int kb = c * 64;
#pragma unroll
        for (int it = 0; it < 2; it++) {
            const int i = t + it * 256;
            const int r = i >> 3, seg = i & 7;
            const int so = r * ATS + seg * 8;
            const size_t gk = (size_t)(kb + r) * HD + seg * 8;
            const size_t gv = (size_t)r * SDIM + kb + seg * 8;
            cpa16(s0 + so,             Kh + gk);
            cpa16(s0 + KVT_E + so,     Vh + gv);
            cpa16(s0 + 2 * KVT_E + so, Vl + gv);
        }
    };

#pragma unroll
    for (int it = 0; it < 4; it++) {
        const int i = t + it * 256;
        const int r = i >> 3, seg = i & 7;
        const size_t g = (size_t)(qbase + r) * HD + seg * 8;
        const int so = r * ATS + seg * 8;
        cpa16(sQh + so, Qh + g);
        cpa16(sQl + so, Ql + g);
    }
    issue_kv(0, 0);
    CPA_COMMIT();

    float o[8][4];
#pragma unroll
    for (int i = 0; i < 8; i++)
#pragma unroll
        for (int j = 0; j < 4; j++) o[i][j] = 0.f;
    float m0 = -1e30f, m1 = -1e30f, l0 = 0.f, l1 = 0.f;

    for (int c = 0; c < 32; c++) {
        if (c < 31) { issue_kv(c + 1, (c + 1) & 1); CPA_COMMIT(); CPA_WAIT(1); }
        else        { CPA_WAIT(0); }
        __syncthreads();

        const __half* sKh = sm + QSZ_E + (c & 1) * KVSTG_E;
        const __half* sVh = sKh + KVT_E;
        const __half* sVl = sKh + 2 * KVT_E;

        // S = Q K^T : 2-pass (qh + ql) x kh
        float s[8][4];
#pragma unroll
        for (int i = 0; i < 8; i++)
#pragma unroll
            for (int j = 0; j < 4; j++) s[i][j] = 0.f;

#pragma unroll
        for (int kk = 0; kk < 4; kk++) {
            const int k0 = kk * 16;
            uint32_t qa_h[4], qa_l[4], kbh[8][2];
            const int r0 = (qw + lr) * ATS + k0 + lc;
            const int r8 = r0 + 8 * ATS;
            qa_h[0] = *(const uint32_t*)(sQh + r0);
            qa_h[1] = *(const uint32_t*)(sQh + r8);
            qa_h[2] = *(const uint32_t*)(sQh + r0 + 8);
            qa_h[3] = *(const uint32_t*)(sQh + r8 + 8);
            qa_l[0] = *(const uint32_t*)(sQl + r0);
            qa_l[1] = *(const uint32_t*)(sQl + r8);
            qa_l[2] = *(const uint32_t*)(sQl + r0 + 8);
            qa_l[3] = *(const uint32_t*)(sQl + r8 + 8);
#pragma unroll
            for (int ni = 0; ni < 8; ni++) {
                const int c0 = (ni * 8 + lr) * ATS + k0 + lc;
                kbh[ni][0] = *(const uint32_t*)(sKh + c0);
                kbh[ni][1] = *(const uint32_t*)(sKh + c0 + 8);
            }
#pragma unroll
            for (int ni = 0; ni < 8; ni++) mma16816(s[ni], qa_h, kbh[ni]);
#pragma unroll
            for (int ni = 0; ni < 8; ni++) mma16816(s[ni], qa_l, kbh[ni]);
        }

        // Online softmax
        float mx0 = -1e30f, mx1 = -1e30f;
#pragma unroll
        for (int ni = 0; ni < 8; ni++) {
            mx0 = fmaxf(mx0, fmaxf(s[ni][0], s[ni][1]));
            mx1 = fmaxf(mx1, fmaxf(s[ni][2], s[ni][3]));
        }
#pragma unroll
        for (int off = 1; off < 4; off <<= 1) {
            mx0 = fmaxf(mx0, __shfl_xor_sync(0xffffffffu, mx0, off));
            mx1 = fmaxf(mx1, __shfl_xor_sync(0xffffffffu, mx1, off));
        }
        const float mn0 = fmaxf(m0, mx0);
        const float mn1 = fmaxf(m1, mx1);
        const float al0 = __expf(m0 - mn0);
        const float al1 = __expf(m1 - mn1);
        m0 = mn0; m1 = mn1;

        float ls0 = 0.f, ls1 = 0.f;
#pragma unroll
        for (int ni = 0; ni < 8; ni++) {
            s[ni][0] = __expf(s[ni][0] - mn0);
            s[ni][1] = __expf(s[ni][1] - mn0);
            s[ni][2] = __expf(s[ni][2] - mn1);
            s[ni][3] = __expf(s[ni][3] - mn1);
            ls0 += s[ni][0] + s[ni][1];
            ls1 += s[ni][2] + s[ni][3];
        }
#pragma unroll
        for (int off = 1; off < 4; off <<= 1) {
            ls0 += __shfl_xor_sync(0xffffffffu, ls0, off);
            ls1 += __shfl_xor_sync(0xffffffffu, ls1, off);
        }
        l0 = l0 * al0 + ls0;
        l1 = l1 * al1 + ls1;
#pragma unroll
        for (int ni = 0; ni < 8; ni++) {
            o[ni][0] *= al0; o[ni][1] *= al0;
            o[ni][2] *= al1; o[ni][3] *= al1;
        }

        // O += P V : P single fp16, V hi/lo -> 2 passes
#pragma unroll
        for (int j = 0; j < 4; j++) {
            uint32_t pa[4], vbh[8][2], vbl[8][2];
            pa[0] = pack_f16(s[2*j][0],   s[2*j][1]);
            pa[1] = pack_f16(s[2*j][2],   s[2*j][3]);
            pa[2] = pack_f16(s[2*j+1][0], s[2*j+1][1]);
            pa[3] = pack_f16(s[2*j+1][2], s[2*j+1][3]);
#pragma unroll
            for (int ni = 0; ni < 8; ni++) {
                const int c0 = (ni * 8 + lr) * ATS + j * 16 + lc;
                vbh[ni][0] = *(const uint32_t*)(sVh + c0);
                vbh[ni][1] = *(const uint32_t*)(sVh + c0 + 8);
                vbl[ni][0] = *(const uint32_t*)(sVl + c0);
                vbl[ni][1] = *(const uint32_t*)(sVl + c0 + 8);
            }
#pragma unroll
            for (int ni = 0; ni < 8; ni++) mma16816(o[ni], pa, vbh[ni]);
#pragma unroll
            for (int ni = 0; ni < 8; ni++) mma16816(o[ni], pa, vbl[ni]);
        }
        __syncthreads();
    }

    // Epilogue: normalize, write ctx single fp16 [b,s,D]
    const float inv0 = 1.f / l0;
    const float inv1 = 1.f / l1;
    const int b = bh >> 4;
    const int h = bh & (HNUM - 1);
    const int s0 = qbase + qw + lr;
    const int s1 = s0 + 8;
#pragma unroll
    for (int ni = 0; ni < 8; ni++) {
        const int col = h * HD + ni * 8 + lc;
        *(uint32_t*)(g_CTXh + (size_t)(b * SDIM + s0) * DDIM + col) =
            pack_f16(o[ni][0] * inv0, o[ni][1] * inv0);
        *(uint32_t*)(g_CTXh + (size_t)(b * SDIM + s1) * DDIM + col) =
            pack_f16(o[ni][2] * inv1, o[ni][3] * inv1);
    }
}

// ---------------------------------------------------------------------------
// Launch
// ---------------------------------------------------------------------------
extern "C" void kernel_launch(void* const* d_in, const int* in_sizes, int n_in,
                              void* d_out, int out_size)
{
    const float* x  = (const float*)d_in[0];
    const float* Wq = (const float*)d_in[1];
    const float* bq = (const float*)d_in[2];
    const float* Wk = (const float*)d_in[3];
    const float* bk = (const float*)d_in[4];
    const float* Wv = (const float*)d_in[5];
    const float* bv = (const float*)d_in[6];
    const float* Wo = (const float*)d_in[7];
    const float* bo = (const float*)d_in[8];

    __half *xh, *xl, *wth, *wtl, *qh, *ql, *kh, *vth, *vtl, *ctxh;
    cudaGetSymbolAddress((void**)&xh,   g_Xh);
    cudaGetSymbolAddress((void**)&xl,   g_Xl);
    cudaGetSymbolAddress((void**)&wth,  g_Wth);
    cudaGetSymbolAddress((void**)&wtl,  g_Wtl);
    cudaGetSymbolAddress((void**)&qh,   g_Qh);
    cudaGetSymbolAddress((void**)&ql,   g_Ql);
    cudaGetSymbolAddress((void**)&kh,   g_Kh);
    cudaGetSymbolAddress((void**)&vth,  g_VTh);
    cudaGetSymbolAddress((void**)&vtl,  g_VTl);
    cudaGetSymbolAddress((void**)&ctxh, g_CTXh);

    cudaFuncSetAttribute(gemm_qkv, cudaFuncAttributeMaxDynamicSharedMemorySize, GEMM_SMEM);
    cudaFuncSetAttribute(gemm_out, cudaFuncAttributeMaxDynamicSharedMemorySize, GEMM_SMEM);
    cudaFuncSetAttribute(attn_mma, cudaFuncAttributeMaxDynamicSharedMemorySize, ATTN_SMEM);

    const size_t WSZ = (size_t)DDIM * DDIM;

    prep_all<<<dim3(32, 32, 5), dim3(32, 32)>>>(x, Wq, Wk, Wv, Wo, xh, xl, wth, wtl);

    gemm_qkv<<<dim3(3 * DDIM / 128, ROWS / 128), 256, GEMM_SMEM>>>(
        xh, xl, wth, wtl, bq, bk, bv, qh, ql, kh, vth, vtl);

    attn_mma<<<dim3(SDIM / 128, BH), 256, ATTN_SMEM>>>();   // (16, 64)

    gemm_out<<<dim3(DDIM / 128, ROWS / 128), 256, GEMM_SMEM>>>(
        ctxh, wth + 3 * WSZ, wtl + 3 * WSZ, bo, (float*)d_out);
}

// round 14
// speedup vs baseline: 4.1353x; 1.0993x over previous
#include <cuda_runtime.h>
#include <cuda_fp16.h>
#include <math.h>
#include <cstdint>

#define BDIM 4
#define SDIM 2048
#define DDIM 1024
#define HNUM 16
#define HD   64
#define ROWS (BDIM * SDIM)   // 8192
#define BH   (BDIM * HNUM)   // 64

// ---------------------------------------------------------------------------
// Scratch (fp16 hi/lo splits)
// ---------------------------------------------------------------------------
__device__ __half g_Xh[(size_t)ROWS * DDIM];
__device__ __half g_Xl[(size_t)ROWS * DDIM];
__device__ __half g_Wth[4][(size_t)DDIM * DDIM];   // W^T hi, [n][k]; QKVO contiguous
__device__ __half g_Wtl[4][(size_t)DDIM * DDIM];
__device__ __half g_Qh[(size_t)BH * SDIM * HD];    // [bh][s][hd] (pre-scaled 1/8)
__device__ __half g_Ql[(size_t)BH * SDIM * HD];
__device__ __half g_Kh[(size_t)BH * SDIM * HD];    // K single fp16
__device__ __half g_VTh[(size_t)BH * HD * SDIM];   // [bh][hd][s], V single fp16
__device__ __half g_CTXh[(size_t)ROWS * DDIM];     // attention output, single fp16

// ---------------------------------------------------------------------------
// Helpers
// ---------------------------------------------------------------------------
__device__ __forceinline__ void mma16816(float* c, const uint32_t* a, const uint32_t* b)
{
    asm volatile(
        "mma.sync.aligned.m16n8k16.row.col.f32.f16.f16.f32 "
        "{%0,%1,%2,%3}, {%4,%5,%6,%7}, {%8,%9}, {%0,%1,%2,%3};"
        : "+f"(c[0]), "+f"(c[1]), "+f"(c[2]), "+f"(c[3])
        : "r"(a[0]), "r"(a[1]), "r"(a[2]), "r"(a[3]), "r"(b[0]), "r"(b[1]));
}

// pack two fp32 -> f16x2 (first arg -> low half, second arg -> high half)
__device__ __forceinline__ uint32_t pack_f16(float lo, float hi)
{
    uint32_t r;
    asm("cvt.rn.f16x2.f32 %0, %1, %2;" : "=r"(r) : "f"(hi), "f"(lo));
    return r;
}

__device__ __forceinline__ void cpa16(void* sptr, const void* gptr)
{
    uint32_t s = (uint32_t)__cvta_generic_to_shared(sptr);
    asm volatile("cp.async.cg.shared.global [%0], [%1], 16;" :: "r"(s), "l"(gptr));
}
#define CPA_COMMIT() asm volatile("cp.async.commit_group;" ::: "memory")
#define CPA_WAIT(n)  asm volatile("cp.async.wait_group %0;" :: "n"(n) : "memory")

// ---------------------------------------------------------------------------
// Fused prep: z<4 -> transpose+split W_z ; z==4 -> vectorized convert of x
// ---------------------------------------------------------------------------
__global__ void prep_all(
    const float* __restrict__ x,
    const float* __restrict__ W0, const float* __restrict__ W1,
    const float* __restrict__ W2, const float* __restrict__ W3,
    __half* __restrict__ xh, __half* __restrict__ xl,
    __half* __restrict__ ThB, __half* __restrict__ TlB)
{
    const int z = blockIdx.z;
    if (z < 4) {
        __shared__ float tile[32][33];
        const float* W = (z == 0) ? W0 : (z == 1) ? W1 : (z == 2) ? W2 : W3;
        __half* Th = ThB + (size_t)z * DDIM * DDIM;
        __half* Tl = TlB + (size_t)z * DDIM * DDIM;
        const int tx = threadIdx.x, ty = threadIdx.y;
        tile[ty][tx] = W[(size_t)(blockIdx.y * 32 + ty) * DDIM + blockIdx.x * 32 + tx];
        __syncthreads();
        const int on = blockIdx.x * 32 + ty;
        const int ok = blockIdx.y * 32 + tx;
        float v = tile[tx][ty];
        __half h = __float2half(v);
        Th[(size_t)on * DDIM + ok] = h;
        Tl[(size_t)on * DDIM + ok] = __float2half(v - __half2float(h));
    } else {
        const int tid = threadIdx.y * 32 + threadIdx.x;
        const int bid = blockIdx.y * 32 + blockIdx.x;
        const int n4 = ROWS * DDIM / 4;
        const float4* src = (const float4*)x;
        uint2* hi = (uint2*)xh;
        uint2* lo = (uint2*)xl;
        for (int i = bid * 1024 + tid; i < n4; i += 1024 * 1024) {
            const float4 v = src[i];
            const float hx = __half2float(__float2half(v.x));
            const float hy = __half2float(__float2half(v.y));
            const float hz = __half2float(__float2half(v.z));
            const float hw = __half2float(__float2half(v.w));
            hi[i] = make_uint2(pack_f16(v.x, v.y), pack_f16(v.z, v.w));
            lo[i] = make_uint2(pack_f16(v.x - hx, v.y - hy), pack_f16(v.z - hz, v.w - hw));
        }
    }
}

// ---------------------------------------------------------------------------
// Shared GEMM core: CTA tile 128x128, K-chunk 64, cp.async 2-stage,
// 8 warps, pass-major mma ordering. PASSES=3: Ah*Bh+Ah*Bl+Al*Bh.
// PASSES=2: Ah*Bh+Ah*Bl. B indexed by rows (bn + r).
// ---------------------------------------------------------------------------
#define AKS 72
#define TILE_E (128 * AKS)
#define STG_E  (4 * TILE_E)
#define GEMM_SMEM (2 * STG_E * 2)        // 147456 bytes

struct GemmCore {
    float acc[4][4][4];
};

template <int PASSES>
__device__ __forceinline__ void gemm_core_run(
    char* smem, int t,
    const __half* Ah_g, const __half* Al_g,
    const __half* Bh_g, const __half* Bl_g,
    int bm, int bn, GemmCore& gc)
{
    __half* sbase = (__half*)smem;
    const int wid  = t >> 5;
    const int lane = t & 31;
    const int wr   = wid & 1;
    const int wc   = wid >> 1;
    const int lr   = lane >> 2;
    const int lc   = (lane & 3) << 1;

    auto issue_chunk = [&](int c, int stg) {
        __half* s0 = sbase + stg * STG_E;
        const int k0g = c * 64;
#pragma unroll
        for (int it = 0; it < 4; it++) {
            const int i = t + it * 256;
            const int r = i >> 3, seg = i & 7;
            const size_t ga = (size_t)(bm + r) * DDIM + k0g + seg * 8;
            const size_t gb = (size_t)(bn + r) * DDIM + k0g + seg * 8;
            const int so = r * AKS + seg * 8;
            cpa16(s0 + so,              Ah_g + ga);
            if (PASSES == 3) cpa16(s0 + TILE_E + so, Al_g + ga);
            cpa16(s0 + 2 * TILE_E + so, Bh_g + gb);
            cpa16(s0 + 3 * TILE_E + so, Bl_g + gb);
        }
    };

#pragma unroll
    for (int i = 0; i < 4; i++)
#pragma unroll
        for (int j = 0; j < 4; j++)
#pragma unroll
            for (int r = 0; r < 4; r++) gc.acc[i][j][r] = 0.f;

    issue_chunk(0, 0);
    CPA_COMMIT();

    for (int c = 0; c < 16; c++) {
        if (c < 15) { issue_chunk(c + 1, (c + 1) & 1); CPA_COMMIT(); CPA_WAIT(1); }
        else        { CPA_WAIT(0); }
        __syncthreads();

        const __half* sAh = sbase + (c & 1) * STG_E;
        const __half* sAl = sAh + TILE_E;
        const __half* sBh = sAh + 2 * TILE_E;
        const __half* sBl = sAh + 3 * TILE_E;

#pragma unroll
        for (int kk = 0; kk < 4; kk++) {
            const int k0 = kk * 16;
            uint32_t ah[4][4], al[4][4], bh[4][2], bl[4][2];
#pragma unroll
            for (int mi = 0; mi < 4; mi++) {
                const int r0 = (wr * 64 + mi * 16 + lr) * AKS + k0 + lc;
                const int r8 = r0 + 8 * AKS;
                ah[mi][0] = *(const uint32_t*)(sAh + r0);
                ah[mi][1] = *(const uint32_t*)(sAh + r8);
                ah[mi][2] = *(const uint32_t*)(sAh + r0 + 8);
                ah[mi][3] = *(const uint32_t*)(sAh + r8 + 8);
                if (PASSES == 3) {
                    al[mi][0] = *(const uint32_t*)(sAl + r0);
                    al[mi][1] = *(const uint32_t*)(sAl + r8);
                    al[mi][2] = *(const uint32_t*)(sAl + r0 + 8);
                    al[mi][3] = *(const uint32_t*)(sAl + r8 + 8);
                }
            }
#pragma unroll
            for (int ni = 0; ni < 4; ni++) {
                const int c0 = (wc * 32 + ni * 8 + lr) * AKS + k0 + lc;
                bh[ni][0] = *(const uint32_t*)(sBh + c0);
                bh[ni][1] = *(const uint32_t*)(sBh + c0 + 8);
                bl[ni][0] = *(const uint32_t*)(sBl + c0);
                bl[ni][1] = *(const uint32_t*)(sBl + c0 + 8);
            }
#pragma unroll
            for (int mi = 0; mi < 4; mi++)
#pragma unroll
                for (int ni = 0; ni < 4; ni++)
                    mma16816(gc.acc[mi][ni], ah[mi], bh[ni]);
#pragma unroll
            for (int mi = 0; mi < 4; mi++)
#pragma unroll
                for (int ni = 0; ni < 4; ni++)
                    mma16816(gc.acc[mi][ni], ah[mi], bl[ni]);
            if (PASSES == 3) {
#pragma unroll
                for (int mi = 0; mi < 4; mi++)
#pragma unroll
                    for (int ni = 0; ni < 4; ni++)
                        mma16816(gc.acc[mi][ni], al[mi], bh[ni]);
            }
        }
        __syncthreads();
    }

    float* Ds = (float*)smem;
#pragma unroll
    for (int mi = 0; mi < 4; mi++) {
        const int r = wr * 64 + mi * 16 + lr;
#pragma unroll
        for (int ni = 0; ni < 4; ni++) {
            const int cc = wc * 32 + ni * 8 + lc;
            Ds[r * 133 + cc]           = gc.acc[mi][ni][0];
            Ds[r * 133 + cc + 1]       = gc.acc[mi][ni][1];
            Ds[(r + 8) * 133 + cc]     = gc.acc[mi][ni][2];
            Ds[(r + 8) * 133 + cc + 1] = gc.acc[mi][ni][3];
        }
    }
    __syncthreads();
}

// ---------------------------------------------------------------------------
// Fused QKV projection. which = bn>>10: 0=Q (1/8, hi/lo), 1=K (single fp16),
// 2=V ([b,h,hd,s] single fp16)
// ---------------------------------------------------------------------------
__global__ __launch_bounds__(256) void gemm_qkv(
    const __half* __restrict__ Ah_g, const __half* __restrict__ Al_g,
    const __half* __restrict__ Wh_g, const __half* __restrict__ Wl_g,
    const float* __restrict__ bq, const float* __restrict__ bk, const float* __restrict__ bv,
    __half* __restrict__ qh, __half* __restrict__ ql,
    __half* __restrict__ kh, __half* __restrict__ vth)
{
    extern __shared__ char smem[];
    const int t  = threadIdx.x;
    const int bn = blockIdx.x * 128;
    const int bm = blockIdx.y * 128;
    const int which = bn >> 10;

    GemmCore gc;
    gemm_core_run<3>(smem, t, Ah_g, Al_g, Wh_g, Wl_g, bm, bn, gc);

    const float* Ds = (const float*)smem;
    const float* bias = (which == 0) ? bq : (which == 1) ? bk : bv;
    const int colm_base = bn & 1023;

    if (which == 0) {
        for (int idx = t; idx < 128 * 128; idx += 256) {
            const int r = idx >> 7, cc = idx & 127;
            const int row = bm + r;
            const int colm = colm_base + cc;
            const float v = (Ds[r * 133 + cc] + bias[colm]) * 0.125f;
            const int b = row >> 11, s = row & (SDIM - 1);
            const int h = colm >> 6, hd = colm & (HD - 1);
            const size_t dst = (size_t)((b * HNUM + h) * SDIM + s) * HD + hd;
            __half hh = __float2half(v);
            qh[dst] = hh;
            ql[dst] = __float2half(v - __half2float(hh));
        }
    } else if (which == 1) {
        for (int idx = t; idx < 128 * 128; idx += 256) {
            const int r = idx >> 7, cc = idx & 127;
            const int row = bm + r;
            const int colm = colm_base + cc;
            const float v = Ds[r * 133 + cc] + bias[colm];
            const int b = row >> 11, s = row & (SDIM - 1);
            const int h = colm >> 6, hd = colm & (HD - 1);
            kh[(size_t)((b * HNUM + h) * SDIM + s) * HD + hd] = __float2half(v);
        }
    } else {
        for (int idx = t; idx < 128 * 128; idx += 256) {
            const int r = idx & 127, cc = idx >> 7;
            const int row = bm + r;
            const int colm = colm_base + cc;
            const float v = Ds[r * 133 + cc] + bias[colm];
            const int b = row >> 11, s = row & (SDIM - 1);
            const int h = colm >> 6, hd = colm & (HD - 1);
            vth[(size_t)((b * HNUM + h) * HD + hd) * SDIM + s] = __float2half(v);
        }
    }
}

// O-projection: ctx single fp16 (2-pass), fp32 out
__global__ __launch_bounds__(256) void gemm_out(
    const __half* __restrict__ Ah_g,
    const __half* __restrict__ Bh_g, const __half* __restrict__ Bl_g,
    const float* __restrict__ bias, float* __restrict__ outF)
{
    extern __shared__ char smem[];
    const int t  = threadIdx.x;
    const int bn = blockIdx.x * 128;
    const int bm = blockIdx.y * 128;

    GemmCore gc;
    gemm_core_run<2>(smem, t, Ah_g, Ah_g, Bh_g, Bl_g, bm, bn, gc);

    const float* Ds = (const float*)smem;
    for (int idx = t; idx < 128 * 128; idx += 256) {
        const int r = idx >> 7, cc = idx & 127;
        outF[(size_t)(bm + r) * DDIM + bn + cc] = Ds[r * 133 + cc] + bias[bn + cc];
    }
}

// ---------------------------------------------------------------------------
// Flash attention. QK^T: 2-pass (Q hi/lo x K single). PV: 1-pass (P single x
// V single). cp.async 2-stage KV pipeline (2 tiles/stage), pass-major.
// ---------------------------------------------------------------------------
#define ATS 72
#define QSZ_E   (2 * 128 * ATS)            // Q hi+lo
#define KVT_E   (64 * ATS)                 // one 64-row tile
#define KVSTG_E (2 * KVT_E)                // Kh, Vh
#define ATTN_SMEM ((QSZ_E + 2 * KVSTG_E) * 2)   // 73728 bytes

__global__ __launch_bounds__(256) void attn_mma()
{
    extern __shared__ char smraw[];
    __half* sm = (__half*)smraw;
    __half* sQh = sm;
    __half* sQl = sm + 128 * ATS;

    const int t    = threadIdx.x;
    const int wid  = t >> 5;
    const int lane = t & 31;
    const int lr   = lane >> 2;
    const int lc   = (lane & 3) << 1;
    const int bh    = blockIdx.y;
    const int qbase = blockIdx.x * 128;
    const int qw    = wid * 16;

    const __half* Qh = g_Qh + (size_t)bh * SDIM * HD;
    const __half* Ql = g_Ql + (size_t)bh * SDIM * HD;
    const __half* Kh = g_Kh + (size_t)bh * SDIM * HD;
    const __half* Vh = g_VTh + (size_t)bh * HD * SDIM;

    auto issue_kv = [&](int c, int stg) {
        __half* s0 = sm + QSZ_E + stg * KVSTG_E;
        const int kb = c * 64;
#pragma unroll
        for (int it = 0; it < 2; it++) {
            const int i = t + it * 256;
            const int r = i >> 3, seg = i & 7;
            const int so = r * ATS + seg * 8;
            const size_t gk = (size_t)(kb + r) * HD + seg * 8;
            const size_t gv = (size_t)r * SDIM + kb + seg * 8;
            cpa16(s0 + so,         Kh + gk);
            cpa16(s0 + KVT_E + so, Vh + gv);
        }
    };

#pragma unroll
    for (int it = 0; it < 4; it++) {
        const int i = t + it * 256;
        const int r = i >> 3, seg = i & 7;
        const size_t g = (size_t)(qbase + r) * HD + seg * 8;
        const int so = r * ATS + seg * 8;
        cpa16(sQh + so, Qh + g);
        cpa16(sQl + so, Ql + g);
    }
    issue_kv(0, 0);
    CPA_COMMIT();

    float o[8][4];
#pragma unroll
    for (int i = 0; i < 8; i++)
#pragma unroll
        for (int j = 0; j < 4; j++) o[i][j] = 0.f;
    float m0 = -1e30f, m1 = -1e30f, l0 = 0.f, l1 = 0.f;

    for (int c = 0; c < 32; c++) {
        if (c < 31) { issue_kv(c + 1, (c + 1) & 1); CPA_COMMIT(); CPA_WAIT(1); }
        else        { CPA_WAIT(0); }
        __syncthreads();

        const __half* sKh = sm + QSZ_E + (c & 1) * KVSTG_E;
        const __half* sVh = sKh + KVT_E;

        // S = Q K^T : 2-pass (qh + ql) x kh
        float s[8][4];
#pragma unroll
        for (int i = 0; i < 8; i++)
#pragma unroll
            for (int j = 0; j < 4; j++) s[i][j] = 0.f;

#pragma unroll
        for (int kk = 0; kk < 4; kk++) {
            const int k0 = kk * 16;
            uint32_t qa_h[4], qa_l[4], kbh[8][2];
            const int r0 = (qw + lr) * ATS + k0 + lc;
            const int r8 = r0 + 8 * ATS;
            qa_h[0] = *(const uint32_t*)(sQh + r0);
            qa_h[1] = *(const uint32_t*)(sQh + r8);
            qa_h[2] = *(const uint32_t*)(sQh + r0 + 8);
            qa_h[3] = *(const uint32_t*)(sQh + r8 + 8);
            qa_l[0] = *(const uint32_t*)(sQl + r0);
            qa_l[1] = *(const uint32_t*)(sQl + r8);
            qa_l[2] = *(const uint32_t*)(sQl + r0 + 8);
            qa_l[3] = *(const uint32_t*)(sQl + r8 + 8);
#pragma unroll
            for (int ni = 0; ni < 8; ni++) {
                const int c0 = (ni * 8 + lr) * ATS + k0 + lc;
                kbh[ni][0] = *(const uint32_t*)(sKh + c0);
                kbh[ni][1] = *(const uint32_t*)(sKh + c0 + 8);
            }
#pragma unroll
            for (int ni = 0; ni < 8; ni++) mma16816(s[ni], qa_h, kbh[ni]);
#pragma unroll
            for (int ni = 0; ni < 8; ni++) mma16816(s[ni], qa_l, kbh[ni]);
        }

        // Online softmax
        float mx0 = -1e30f, mx1 = -1e30f;
#pragma unroll
        for (int ni = 0; ni < 8; ni++) {
            mx0 = fmaxf(mx0, fmaxf(s[ni][0], s[ni][1]));
            mx1 = fmaxf(mx1, fmaxf(s[ni][2], s[ni][3]));
        }
#pragma unroll
        for (int off = 1; off < 4; off <<= 1) {
            mx0 = fmaxf(mx0, __shfl_xor_sync(0xffffffffu, mx0, off));
            mx1 = fmaxf(mx1, __shfl_xor_sync(0xffffffffu, mx1, off));
        }
        const float mn0 = fmaxf(m0, mx0);
        const float mn1 = fmaxf(m1, mx1);
        const float al0 = __expf(m0 - mn0);
        const float al1 = __expf(m1 - mn1);
        m0 = mn0; m1 = mn1;

        float ls0 = 0.f, ls1 = 0.f;
#pragma unroll
        for (int ni = 0; ni < 8; ni++) {
            s[ni][0] = __expf(s[ni][0] - mn0);
            s[ni][1] = __expf(s[ni][1] - mn0);
            s[ni][2] = __expf(s[ni][2] - mn1);
            s[ni][3] = __expf(s[ni][3] - mn1);
            ls0 += s[ni][0] + s[ni][1];
            ls1 += s[ni][2] + s[ni][3];
        }
#pragma unroll
        for (int off = 1; off < 4; off <<= 1) {
            ls0 += __shfl_xor_sync(0xffffffffu, ls0, off);
            ls1 += __shfl_xor_sync(0xffffffffu, ls1, off);
        }
        l0 = l0 * al0 + ls0;
        l1 = l1 * al1 + ls1;
#pragma unroll
        for (int ni = 0; ni < 8; ni++) {
            o[ni][0] *= al0; o[ni][1] *= al0;
            o[ni][2] *= al1; o[ni][3] *= al1;
        }

        // O += P V : P single fp16 x V single fp16 -> 1 pass
#pragma unroll
        for (int j = 0; j < 4; j++) {
            uint32_t pa[4], vbh[8][2];
            pa[0] = pack_f16(s[2*j][0],   s[2*j][1]);
            pa[1] = pack_f16(s[2*j][2],   s[2*j][3]);
            pa[2] = pack_f16(s[2*j+1][0], s[2*j+1][1]);
            pa[3] = pack_f16(s[2*j+1][2], s[2*j+1][3]);
#pragma unroll
            for (int ni = 0; ni < 8; ni++) {
                const int c0 = (ni * 8 + lr) * ATS + j * 16 + lc;
                vbh[ni][0] = *(const uint32_t*)(sVh + c0);
                vbh[ni][1] = *(const uint32_t*)(sVh + c0 + 8);
            }
#pragma unroll
            for (int ni = 0; ni < 8; ni++) mma16816(o[ni], pa, vbh[ni]);
        }
        __syncthreads();
    }

    // Epilogue: normalize, write ctx single fp16 [b,s,D]
    const float inv0 = 1.f / l0;
    const float inv1 = 1.f / l1;
    const int b = bh >> 4;
    const int h = bh & (HNUM - 1);
    const int s0 = qbase + qw + lr;
    const int s1 = s0 + 8;
#pragma unroll
    for (int ni = 0; ni < 8; ni++) {
        const int col = h * HD + ni * 8 + lc;
        *(uint32_t*)(g_CTXh + (size_t)(b * SDIM + s0) * DDIM + col) =
            pack_f16(o[ni][0] * inv0, o[ni][1] * inv0);
        *(uint32_t*)(g_CTXh + (size_t)(b * SDIM + s1) * DDIM + col) =
            pack_f16(o[ni][2] * inv1, o[ni][3] * inv1);
    }
}

// ---------------------------------------------------------------------------
// Launch
// ---------------------------------------------------------------------------
extern "C" void kernel_launch(void* const* d_in, const int* in_sizes, int n_in,
                              void* d_out, int out_size)
{
    const float* x  = (const float*)d_in[0];
    const float* Wq = (const float*)d_in[1];
    const float* bq = (const float*)d_in[2];
    const float* Wk = (const float*)d_in[3];
    const float* bk = (const float*)d_in[4];
    const float* Wv = (const float*)d_in[5];
    const float* bv = (const float*)d_in[6];
    const float* Wo = (const float*)d_in[7];
    const float* bo = (const float*)d_in[8];

    __half *xh, *xl, *wth, *wtl, *qh, *ql, *kh, *vth, *ctxh;
    cudaGetSymbolAddress((void**)&xh,   g_Xh);
    cudaGetSymbolAddress((void**)&xl,   g_Xl);
    cudaGetSymbolAddress((void**)&wth,  g_Wth);
    cudaGetSymbolAddress((void**)&wtl,  g_Wtl);
    cudaGetSymbolAddress((void**)&qh,   g_Qh);
    cudaGetSymbolAddress((void**)&ql,   g_Ql);
    cudaGetSymbolAddress((void**)&kh,   g_Kh);
    cudaGetSymbolAddress((void**)&vth,  g_VTh);
    cudaGetSymbolAddress((void**)&ctxh, g_CTXh);

    cudaFuncSetAttribute(gemm_qkv, cudaFuncAttributeMaxDynamicSharedMemorySize, GEMM_SMEM);
    cudaFuncSetAttribute(gemm_out, cudaFuncAttributeMaxDynamicSharedMemorySize, GEMM_SMEM);
    cudaFuncSetAttribute(attn_mma, cudaFuncAttributeMaxDynamicSharedMemorySize, ATTN_SMEM);

    const size_t WSZ = (size_t)DDIM * DDIM;

    prep_all<<<dim3(32, 32, 5), dim3(32, 32)>>>(x, Wq, Wk, Wv, Wo, xh, xl, wth, wtl);

    gemm_qkv<<<dim3(3 * DDIM / 128, ROWS / 128), 256, GEMM_SMEM>>>(
        xh, xl, wth, wtl, bq, bk, bv, qh, ql, kh, vth);

    attn_mma<<<dim3(SDIM / 128, BH), 256, ATTN_SMEM>>>();   // (16, 64)

    gemm_out<<<dim3(DDIM / 128, ROWS / 128), 256, GEMM_SMEM>>>(
        ctxh, wth + 3 * WSZ, wtl + 3 * WSZ, bo, (float*)d_out);
}

// round 15
// speedup vs baseline: 4.1874x; 1.0126x over previous
#include <cuda_runtime.h>
#include <cuda_fp16.h>
#include <math.h>
#include <cstdint>

#define BDIM 4
#define SDIM 2048
#define DDIM 1024
#define HNUM 16
#define HD   64
#define ROWS (BDIM * SDIM)   // 8192
#define BH   (BDIM * HNUM)   // 64

// ---------------------------------------------------------------------------
// Scratch (fp16 hi/lo splits)
// ---------------------------------------------------------------------------
__device__ __half g_Xh[(size_t)ROWS * DDIM];
__device__ __half g_Xl[(size_t)ROWS * DDIM];
__device__ __half g_Wth[4][(size_t)DDIM * DDIM];   // W^T hi, [n][k]; QKVO contiguous
__device__ __half g_Wtl[4][(size_t)DDIM * DDIM];
__device__ __half g_Qh[(size_t)BH * SDIM * HD];    // [bh][s][hd] (pre-scaled 1/8)
__device__ __half g_Ql[(size_t)BH * SDIM * HD];
__device__ __half g_Kh[(size_t)BH * SDIM * HD];    // K single fp16
__device__ __half g_VTh[(size_t)BH * HD * SDIM];   // [bh][hd][s], V single fp16
__device__ __half g_CTXh[(size_t)ROWS * DDIM];     // attention output, single fp16

// ---------------------------------------------------------------------------
// Helpers
// ---------------------------------------------------------------------------
__device__ __forceinline__ void mma16816(float* c, const uint32_t* a, const uint32_t* b)
{
    asm volatile(
        "mma.sync.aligned.m16n8k16.row.col.f32.f16.f16.f32 "
        "{%0,%1,%2,%3}, {%4,%5,%6,%7}, {%8,%9}, {%0,%1,%2,%3};"
        : "+f"(c[0]), "+f"(c[1]), "+f"(c[2]), "+f"(c[3])
        : "r"(a[0]), "r"(a[1]), "r"(a[2]), "r"(a[3]), "r"(b[0]), "r"(b[1]));
}

__device__ __forceinline__ void ldsm_x4(uint32_t* r, uint32_t saddr)
{
    asm volatile("ldmatrix.sync.aligned.m8n8.x4.shared.b16 {%0,%1,%2,%3}, [%4];"
        : "=r"(r[0]), "=r"(r[1]), "=r"(r[2]), "=r"(r[3]) : "r"(saddr));
}

// pack two fp32 -> f16x2 (first arg -> low half, second arg -> high half)
__device__ __forceinline__ uint32_t pack_f16(float lo, float hi)
{
    uint32_t r;
    asm("cvt.rn.f16x2.f32 %0, %1, %2;" : "=r"(r) : "f"(hi), "f"(lo));
    return r;
}

__device__ __forceinline__ void cpa16(void* sptr, const void* gptr)
{
    uint32_t s = (uint32_t)__cvta_generic_to_shared(sptr);
    asm volatile("cp.async.cg.shared.global [%0], [%1], 16;" :: "r"(s), "l"(gptr));
}
#define CPA_COMMIT() asm volatile("cp.async.commit_group;" ::: "memory")
#define CPA_WAIT(n)  asm volatile("cp.async.wait_group %0;" :: "n"(n) : "memory")

// ---------------------------------------------------------------------------
// Fused prep: z<4 -> transpose+split W_z ; z==4 -> vectorized convert of x
// ---------------------------------------------------------------------------
__global__ void prep_all(
    const float* __restrict__ x,
    const float* __restrict__ W0, const float* __restrict__ W1,
    const float* __restrict__ W2, const float* __restrict__ W3,
    __half* __restrict__ xh, __half* __restrict__ xl,
    __half* __restrict__ ThB, __half* __restrict__ TlB)
{
    const int z = blockIdx.z;
    if (z < 4) {
        __shared__ float tile[32][33];
        const float* W = (z == 0) ? W0 : (z == 1) ? W1 : (z == 2) ? W2 : W3;
        __half* Th = ThB + (size_t)z * DDIM * DDIM;
        __half* Tl = TlB + (size_t)z * DDIM * DDIM;
        const int tx = threadIdx.x, ty = threadIdx.y;
        tile[ty][tx] = W[(size_t)(blockIdx.y * 32 + ty) * DDIM + blockIdx.x * 32 + tx];
        __syncthreads();
        const int on = blockIdx.x * 32 + ty;
        const int ok = blockIdx.y * 32 + tx;
        float v = tile[tx][ty];
        __half h = __float2half(v);
        Th[(size_t)on * DDIM + ok] = h;
        Tl[(size_t)on * DDIM + ok] = __float2half(v - __half2float(h));
    } else {
        const int tid = threadIdx.y * 32 + threadIdx.x;
        const int bid = blockIdx.y * 32 + blockIdx.x;
        const int n4 = ROWS * DDIM / 4;
        const float4* src = (const float4*)x;
        uint2* hi = (uint2*)xh;
        uint2* lo = (uint2*)xl;
        for (int i = bid * 1024 + tid; i < n4; i += 1024 * 1024) {
            const float4 v = src[i];
            const float hx = __half2float(__float2half(v.x));
            const float hy = __half2float(__float2half(v.y));
            const float hz = __half2float(__float2half(v.z));
            const float hw = __half2float(__float2half(v.w));
            hi[i] = make_uint2(pack_f16(v.x, v.y), pack_f16(v.z, v.w));
            lo[i] = make_uint2(pack_f16(v.x - hx, v.y - hy), pack_f16(v.z - hz, v.w - hw));
        }
    }
}

// ---------------------------------------------------------------------------
// Shared GEMM core: CTA tile 128x128, K-chunk 64, cp.async 2-stage,
// 8 warps, pass-major mma ordering, ldmatrix fragment loads.
// PASSES=3: Ah*Bh+Ah*Bl+Al*Bh. PASSES=2: Ah*Bh+Ah*Bl.
// B indexed by rows (bn + r). Row stride AKS=72 halfs = 144 B (16B-aligned).
// ---------------------------------------------------------------------------
#define AKS 72
#define TILE_E (128 * AKS)
#define STG_E  (4 * TILE_E)
#define GEMM_SMEM (2 * STG_E * 2)        // 147456 bytes

struct GemmCore {
    float acc[4][4][4];
};

template <int PASSES>
__device__ __forceinline__ void gemm_core_run(
    char* smem, int t,
    const __half* Ah_g, const __half* Al_g,
    const __half* Bh_g, const __half* Bl_g,
    int bm, int bn, GemmCore& gc)
{
    __half* sbase = (__half*)smem;
    const int wid  = t >> 5;
    const int lane = t & 31;
    const int wr   = wid & 1;
    const int wc   = wid >> 1;
    const int lr   = lane >> 2;
    const int lc   = (lane & 3) << 1;

    // ldmatrix per-lane byte offsets (relative to tile base)
    // A (x4 -> a0..a3 of one m16 tile): lanes 0-15 rows, lanes 16-31 rows @ k+8
    const int aoff = ((wr * 64 + (lane & 15)) * AKS + ((lane >> 4) << 3)) * 2;
    // B (x4 -> b-frags of two adjacent n8 tiles)
    const int boff = ((wc * 32 + (lane & 7) + (((lane >> 4) & 1) << 3)) * AKS
                      + (((lane >> 3) & 1) << 3)) * 2;

    auto issue_chunk = [&](int c, int stg) {
        __half* s0 = sbase + stg * STG_E;
        const int k0g = c * 64;
#pragma unroll
        for (int it = 0; it < 4; it++) {
            const int i = t + it * 256;
            const int r = i >> 3, seg = i & 7;
            const size_t ga = (size_t)(bm + r) * DDIM + k0g + seg * 8;
            const size_t gb = (size_t)(bn + r) * DDIM + k0g + seg * 8;
            const int so = r * AKS + seg * 8;
            cpa16(s0 + so,              Ah_g + ga);
            if (PASSES == 3) cpa16(s0 + TILE_E + so, Al_g + ga);
            cpa16(s0 + 2 * TILE_E + so, Bh_g + gb);
            cpa16(s0 + 3 * TILE_E + so, Bl_g + gb);
        }
    };

#pragma unroll
    for (int i = 0; i < 4; i++)
#pragma unroll
        for (int j = 0; j < 4; j++)
#pragma unroll
            for (int r = 0; r < 4; r++) gc.acc[i][j][r] = 0.f;

    issue_chunk(0, 0);
    CPA_COMMIT();

    const uint32_t uBase = (uint32_t)__cvta_generic_to_shared(sbase);

    for (int c = 0; c < 16; c++) {
        if (c < 15) { issue_chunk(c + 1, (c + 1) & 1); CPA_COMMIT(); CPA_WAIT(1); }
        else        { CPA_WAIT(0); }
        __syncthreads();

        const uint32_t uS  = uBase + (c & 1) * (STG_E * 2);
        const uint32_t uAh = uS;
        const uint32_t uAl = uS + TILE_E * 2;
        const uint32_t uBh = uS + 2 * TILE_E * 2;
        const uint32_t uBl = uS + 3 * TILE_E * 2;

#pragma unroll
        for (int kk = 0; kk < 4; kk++) {
            const int kb = kk * 32;   // k0 * 2 bytes
            uint32_t ah[4][4], al[4][4], bh[2][4], bl[2][4];
#pragma unroll
            for (int mi = 0; mi < 4; mi++) {
                ldsm_x4(ah[mi], uAh + aoff + mi * (16 * AKS * 2) + kb);
                if (PASSES == 3)
                    ldsm_x4(al[mi], uAl + aoff + mi * (16 * AKS * 2) + kb);
            }
#pragma unroll
            for (int nip = 0; nip < 2; nip++) {
                ldsm_x4(bh[nip], uBh + boff + nip * (16 * AKS * 2) + kb);
                ldsm_x4(bl[nip], uBl + boff + nip * (16 * AKS * 2) + kb);
            }
            // pass-major: consecutive mma hit distinct accumulators
#pragma unroll
            for (int mi = 0; mi < 4; mi++)
#pragma unroll
                for (int ni = 0; ni < 4; ni++)
                    mma16816(gc.acc[mi][ni], ah[mi], &bh[ni >> 1][(ni & 1) * 2]);
#pragma unroll
            for (int mi = 0; mi < 4; mi++)
#pragma unroll
                for (int ni = 0; ni < 4; ni++)
                    mma16816(gc.acc[mi][ni], ah[mi], &bl[ni >> 1][(ni & 1) * 2]);
            if (PASSES == 3) {
#pragma unroll
                for (int mi = 0; mi < 4; mi++)
#pragma unroll
                    for (int ni = 0; ni < 4; ni++)
                        mma16816(gc.acc[mi][ni], al[mi], &bh[ni >> 1][(ni & 1) * 2]);
            }
        }
        __syncthreads();
    }

    float* Ds = (float*)smem;
#pragma unroll
    for (int mi = 0; mi < 4; mi++) {
        const int r = wr * 64 + mi * 16 + lr;
#pragma unroll
        for (int ni = 0; ni < 4; ni++) {
            const int cc = wc * 32 + ni * 8 + lc;
            Ds[r * 133 + cc]           = gc.acc[mi][ni][0];
            Ds[r * 133 + cc + 1]       = gc.acc[mi][ni][1];
            Ds[(r + 8) * 133 + cc]     = gc.acc[mi][ni][2];
            Ds[(r + 8) * 133 + cc + 1] = gc.acc[mi][ni][3];
        }
    }
    __syncthreads();
}

// ---------------------------------------------------------------------------
// Fused QKV projection. which = bn>>10: 0=Q (1/8, hi/lo), 1=K (single fp16),
// 2=V ([b,h,hd,s] single fp16)
// ---------------------------------------------------------------------------
__global__ __launch_bounds__(256) void gemm_qkv(
    const __half* __restrict__ Ah_g, const __half* __restrict__ Al_g,
    const __half* __restrict__ Wh_g, const __half* __restrict__ Wl_g,
    const float* __restrict__ bq, const float* __restrict__ bk, const float* __restrict__ bv,
    __half* __restrict__ qh, __half* __restrict__ ql,
    __half* __restrict__ kh, __half* __restrict__ vth)
{
    extern __shared__ char smem[];
    const int t  = threadIdx.x;
    const int bn = blockIdx.x * 128;
    const int bm = blockIdx.y * 128;
    const int which = bn >> 10;

    GemmCore gc;
    gemm_core_run<3>(smem, t, Ah_g, Al_g, Wh_g, Wl_g, bm, bn, gc);

    const float* Ds = (const float*)smem;
    const float* bias = (which == 0) ? bq : (which == 1) ? bk : bv;
    const int colm_base = bn & 1023;

    if (which == 0) {
        for (int idx = t; idx < 128 * 128; idx += 256) {
            const int r = idx >> 7, cc = idx & 127;
            const int row = bm + r;
            const int colm = colm_base + cc;
            const float v = (Ds[r * 133 + cc] + bias[colm]) * 0.125f;
            const int b = row >> 11, s = row & (SDIM - 1);
            const int h = colm >> 6, hd = colm & (HD - 1);
            const size_t dst = (size_t)((b * HNUM + h) * SDIM + s) * HD + hd;
            __half hh = __float2half(v);
            qh[dst] = hh;
            ql[dst] = __float2half(v - __half2float(hh));
        }
    } else if (which == 1) {
        for (int idx = t; idx < 128 * 128; idx += 256) {
            const int r = idx >> 7, cc = idx & 127;
            const int row = bm + r;
            const int colm = colm_base + cc;
            const float v = Ds[r * 133 + cc] + bias[colm];
            const int b = row >> 11, s = row & (SDIM - 1);
            const int h = colm >> 6, hd = colm & (HD - 1);
            kh[(size_t)((b * HNUM + h) * SDIM + s) * HD + hd] = __float2half(v);
        }
    } else {
        for (int idx = t; idx < 128 * 128; idx += 256) {
            const int r = idx & 127, cc = idx >> 7;
            const int row = bm + r;
            const int colm = colm_base + cc;
            const float v = Ds[r * 133 + cc] + bias[colm];
            const int b = row >> 11, s = row & (SDIM - 1);
            const int h = colm >> 6, hd = colm & (HD - 1);
            vth[(size_t)((b * HNUM + h) * HD + hd) * SDIM + s] = __float2half(v);
        }
    }
}

// O-projection: ctx single fp16 (2-pass), fp32 out
__global__ __launch_bounds__(256) void gemm_out(
    const __half* __restrict__ Ah_g,
    const __half* __restrict__ Bh_g, const __half* __restrict__ Bl_g,
    const float* __restrict__ bias, float* __restrict__ outF)
{
    extern __shared__ char smem[];
    const int t  = threadIdx.x;
    const int bn = blockIdx.x * 128;
    const int bm = blockIdx.y * 128;

    GemmCore gc;
    gemm_core_run<2>(smem, t, Ah_g, Ah_g, Bh_g, Bl_g, bm, bn, gc);

    const float* Ds = (const float*)smem;
    for (int idx = t; idx < 128 * 128; idx += 256) {
        const int r = idx >> 7, cc = idx & 127;
        outF[(size_t)(bm + r) * DDIM + bn + cc] = Ds[r * 133 + cc] + bias[bn + cc];
    }
}

// ---------------------------------------------------------------------------
// Flash attention (unchanged from R14). QK^T: 2-pass (Q hi/lo x K single).
// PV: 1-pass (P single x V single). cp.async 2-stage KV pipeline.
// ---------------------------------------------------------------------------
#define ATS 72
#define QSZ_E   (2 * 128 * ATS)
#define KVT_E   (64 * ATS)
#define KVSTG_E (2 * KVT_E)
#define ATTN_SMEM ((QSZ_E + 2 * KVSTG_E) * 2)   // 73728 bytes

__global__ __launch_bounds__(256) void attn_mma()
{
    extern __shared__ char smraw[];
    __half* sm = (__half*)smraw;
    __half* sQh = sm;
    __half* sQl = sm + 128 * ATS;

    const int t    = threadIdx.x;
    const int wid  = t >> 5;
    const int lane = t & 31;
    const int lr   = lane >> 2;
    const int lc   = (lane & 3) << 1;
    const int bh    = blockIdx.y;
    const int qbase = blockIdx.x * 128;
    const int qw    = wid * 16;

    const __half* Qh = g_Qh + (size_t)bh * SDIM * HD;
    const __half* Ql = g_Ql + (size_t)bh * SDIM * HD;
    const __half* Kh = g_Kh + (size_t)bh * SDIM * HD;
    const __half* Vh = g_VTh + (size_t)bh * HD * SDIM;

    auto issue_kv = [&](int c, int stg) {
        __half* s0 = sm + QSZ_E + stg * KVSTG_E;
        const int kb = c * 64;
#pragma unroll
        for (int it = 0; it < 2; it++) {
            const int i = t + it * 256;
            const int r = i >> 3, seg = i & 7;
            const int so = r * ATS + seg * 8;
            const size_t gk = (size_t)(kb + r) * HD + seg * 8;
            const size_t gv = (size_t)r * SDIM + kb + seg * 8;
            cpa16(s0 + so,         Kh + gk);
            cpa16(s0 + KVT_E + so, Vh + gv);
        }
    };

#pragma unroll
    for (int it = 0; it < 4; it++) {
        const int i = t + it * 256;
        const int r = i >> 3, seg = i & 7;
        const size_t g = (size_t)(qbase + r) * HD + seg * 8;
        const int so = r * ATS + seg * 8;
        cpa16(sQh + so, Qh + g);
        cpa16(sQl + so, Ql + g);
    }
    issue_kv(0, 0);
    CPA_COMMIT();

    float o[8][4];
#pragma unroll
    for (int i = 0; i < 8; i++)
#pragma unroll
        for (int j = 0; j < 4; j++) o[i][j] = 0.f;
    float m0 = -1e30f, m1 = -1e30f, l0 = 0.f, l1 = 0.f;

    for (int c = 0; c < 32; c++) {
        if (c < 31) { issue_kv(c + 1, (c + 1) & 1); CPA_COMMIT(); CPA_WAIT(1); }
        else        { CPA_WAIT(0); }
        __syncthreads();

        const __half* sKh = sm + QSZ_E + (c & 1) * KVSTG_E;
        const __half* sVh = sKh + KVT_E;

        // S = Q K^T : 2-pass (qh + ql) x kh
        float s[8][4];
#pragma unroll
        for (int i = 0; i < 8; i++)
#pragma unroll
            for (int j = 0; j < 4; j++) s[i][j] = 0.f;

#pragma unroll
        for (int kk = 0; kk < 4; kk++) {
            const int k0 = kk * 16;
            uint32_t qa_h[4], qa_l[4], kbh[8][2];
            const int r0 = (qw + lr) * ATS + k0 + lc;
            const int r8 = r0 + 8 * ATS;
            qa_h[0] = *(const uint32_t*)(sQh + r0);
            qa_h[1] = *(const uint32_t*)(sQh + r8);
            qa_h[2] = *(const uint32_t*)(sQh + r0 + 8);
            qa_h[3] = *(const uint32_t*)(sQh + r8 + 8);
            qa_l[0] = *(const uint32_t*)(sQl + r0);
            qa_l[1] = *(const uint32_t*)(sQl + r8);
            qa_l[2] = *(const uint32_t*)(sQl + r0 + 8);
            qa_l[3] = *(const uint32_t*)(sQl + r8 + 8);
#pragma unroll
            for (int ni = 0; ni < 8; ni++) {
                const int c0 = (ni * 8 + lr) * ATS + k0 + lc;
                kbh[ni][0] = *(const uint32_t*)(sKh + c0);
                kbh[ni][1] = *(const uint32_t*)(sKh + c0 + 8);
            }
#pragma unroll
            for (int ni = 0; ni < 8; ni++) mma16816(s[ni], qa_h, kbh[ni]);
#pragma unroll
            for (int ni = 0; ni < 8; ni++) mma16816(s[ni], qa_l, kbh[ni]);
        }

        // Online softmax
        float mx0 = -1e30f, mx1 = -1e30f;
#pragma unroll
        for (int ni = 0; ni < 8; ni++) {
            mx0 = fmaxf(mx0, fmaxf(s[ni][0], s[ni][1]));
            mx1 = fmaxf(mx1, fmaxf(s[ni][2], s[ni][3]));
        }
#pragma unroll
        for (int off = 1; off < 4; off <<= 1) {
            mx0 = fmaxf(mx0, __shfl_xor_sync(0xffffffffu, mx0, off));
            mx1 = fmaxf(mx1, __shfl_xor_sync(0xffffffffu, mx1, off));
        }
        const float mn0 = fmaxf(m0, mx0);
        const float mn1 = fmaxf(m1, mx1);
        const float al0 = __expf(m0 - mn0);
        const float al1 = __expf(m1 - mn1);
        m0 = mn0; m1 = mn1;

        float ls0 = 0.f, ls1 = 0.f;
#pragma unroll
        for (int ni = 0; ni < 8; ni++) {
            s[ni][0] = __expf(s[ni][0] - mn0);
            s[ni][1] = __expf(s[ni][1] - mn0);
            s[ni][2] = __expf(s[ni][2] - mn1);
            s[ni][3] = __expf(s[ni][3] - mn1);
            ls0 += s[ni][0] + s[ni][1];
            ls1 += s[ni][2] + s[ni][3];
        }
#pragma unroll
        for (int off = 1; off < 4; off <<= 1) {
            ls0 += __shfl_xor_sync(0xffffffffu, ls0, off);
            ls1 += __shfl_xor_sync(0xffffffffu, ls1, off);
        }
        l0 = l0 * al0 + ls0;
        l1 = l1 * al1 + ls1;
#pragma unroll
        for (int ni = 0; ni < 8; ni++) {
            o[ni][0] *= al0; o[ni][1] *= al0;
            o[ni][2] *= al1; o[ni][3] *= al1;
        }

        // O += P V : P single fp16 x V single fp16 -> 1 pass
#pragma unroll
        for (int j = 0; j < 4; j++) {
            uint32_t pa[4], vbh[8][2];
            pa[0] = pack_f16(s[2*j][0],   s[2*j][1]);
            pa[1] = pack_f16(s[2*j][2],   s[2*j][3]);
            pa[2] = pack_f16(s[2*j+1][0], s[2*j+1][1]);
            pa[3] = pack_f16(s[2*j+1][2], s[2*j+1][3]);
#pragma unroll
            for (int ni = 0; ni < 8; ni++) {
                const int c0 = (ni * 8 + lr) * ATS + j * 16 + lc;
                vbh[ni][0] = *(const uint32_t*)(sVh + c0);
                vbh[ni][1] = *(const uint32_t*)(sVh + c0 + 8);
            }
#pragma unroll
            for (int ni = 0; ni < 8; ni++) mma16816(o[ni], pa, vbh[ni]);
        }
        __syncthreads();
    }

    // Epilogue: normalize, write ctx single fp16 [b,s,D]
    const float inv0 = 1.f / l0;
    const float inv1 = 1.f / l1;
    const int b = bh >> 4;
    const int h = bh & (HNUM - 1);
    const int s0 = qbase + qw + lr;
    const int s1 = s0 + 8;
#pragma unroll
    for (int ni = 0; ni < 8; ni++) {
        const int col = h * HD + ni * 8 + lc;
        *(uint32_t*)(g_CTXh + (size_t)(b * SDIM + s0) * DDIM + col) =
            pack_f16(o[ni][0] * inv0, o[ni][1] * inv0);
        *(uint32_t*)(g_CTXh + (size_t)(b * SDIM + s1) * DDIM + col) =
            pack_f16(o[ni][2] * inv1, o[ni][3] * inv1);
    }
}

// ---------------------------------------------------------------------------
// Launch
// ---------------------------------------------------------------------------
extern "C" void kernel_launch(void* const* d_in, const int* in_sizes, int n_in,
                              void* d_out, int out_size)
{
    const float* x  = (const float*)d_in[0];
    const float* Wq = (const float*)d_in[1];
    const float* bq = (const float*)d_in[2];
    const float* Wk = (const float*)d_in[3];
    const float* bk = (const float*)d_in[4];
    const float* Wv = (const float*)d_in[5];
    const float* bv = (const float*)d_in[6];
    const float* Wo = (const float*)d_in[7];
    const float* bo = (const float*)d_in[8];

    __half *xh, *xl, *wth, *wtl, *qh, *ql, *kh, *vth, *ctxh;
    cudaGetSymbolAddress((void**)&xh,   g_Xh);
    cudaGetSymbolAddress((void**)&xl,   g_Xl);
    cudaGetSymbolAddress((void**)&wth,  g_Wth);
    cudaGetSymbolAddress((void**)&wtl,  g_Wtl);
    cudaGetSymbolAddress((void**)&qh,   g_Qh);
    cudaGetSymbolAddress((void**)&ql,   g_Ql);
    cudaGetSymbolAddress((void**)&kh,   g_Kh);
    cudaGetSymbolAddress((void**)&vth,  g_VTh);
    cudaGetSymbolAddress((void**)&ctxh, g_CTXh);

    cudaFuncSetAttribute(gemm_qkv, cudaFuncAttributeMaxDynamicSharedMemorySize, GEMM_SMEM);
    cudaFuncSetAttribute(gemm_out, cudaFuncAttributeMaxDynamicSharedMemorySize, GEMM_SMEM);
    cudaFuncSetAttribute(attn_mma, cudaFuncAttributeMaxDynamicSharedMemorySize, ATTN_SMEM);

    const size_t WSZ = (size_t)DDIM * DDIM;

    prep_all<<<dim3(32, 32, 5), dim3(32, 32)>>>(x, Wq, Wk, Wv, Wo, xh, xl, wth, wtl);

    gemm_qkv<<<dim3(3 * DDIM / 128, ROWS / 128), 256, GEMM_SMEM>>>(
        xh, xl, wth, wtl, bq, bk, bv, qh, ql, kh, vth);

    attn_mma<<<dim3(SDIM / 128, BH), 256, ATTN_SMEM>>>();   // (16, 64)

    gemm_out<<<dim3(DDIM / 128, ROWS / 128), 256, GEMM_SMEM>>>(
        ctxh, wth + 3 * WSZ, wtl + 3 * WSZ, bo, (float*)d_out);
}

// round 16
// speedup vs baseline: 4.2585x; 1.0170x over previous
#include <cuda_runtime.h>
#include <cuda_fp16.h>
#include <math.h>
#include <cstdint>

#define BDIM 4
#define SDIM 2048
#define DDIM 1024
#define HNUM 16
#define HD   64
#define ROWS (BDIM * SDIM)   // 8192
#define BH   (BDIM * HNUM)   // 64

// ---------------------------------------------------------------------------
// Scratch (fp16 hi/lo splits)
// ---------------------------------------------------------------------------
__device__ __half g_Xh[(size_t)ROWS * DDIM];
__device__ __half g_Xl[(size_t)ROWS * DDIM];
__device__ __half g_Wth[4][(size_t)DDIM * DDIM];   // W^T hi, [n][k]; QKVO contiguous
__device__ __half g_Wtl[4][(size_t)DDIM * DDIM];
__device__ __half g_Qh[(size_t)BH * SDIM * HD];    // [bh][s][hd] (pre-scaled 1/8)
__device__ __half g_Ql[(size_t)BH * SDIM * HD];
__device__ __half g_Kh[(size_t)BH * SDIM * HD];    // K single fp16
__device__ __half g_VTh[(size_t)BH * HD * SDIM];   // [bh][hd][s], V single fp16
__device__ __half g_CTXh[(size_t)ROWS * DDIM];     // attention output, single fp16

// ---------------------------------------------------------------------------
// Helpers
// ---------------------------------------------------------------------------
__device__ __forceinline__ void mma16816(float* c, const uint32_t* a, const uint32_t* b)
{
    asm volatile(
        "mma.sync.aligned.m16n8k16.row.col.f32.f16.f16.f32 "
        "{%0,%1,%2,%3}, {%4,%5,%6,%7}, {%8,%9}, {%0,%1,%2,%3};"
        : "+f"(c[0]), "+f"(c[1]), "+f"(c[2]), "+f"(c[3])
        : "r"(a[0]), "r"(a[1]), "r"(a[2]), "r"(a[3]), "r"(b[0]), "r"(b[1]));
}

__device__ __forceinline__ void ldsm_x4(uint32_t* r, uint32_t saddr)
{
    asm volatile("ldmatrix.sync.aligned.m8n8.x4.shared.b16 {%0,%1,%2,%3}, [%4];"
        : "=r"(r[0]), "=r"(r[1]), "=r"(r[2]), "=r"(r[3]) : "r"(saddr));
}

// pack two fp32 -> f16x2 (first arg -> low half, second arg -> high half)
__device__ __forceinline__ uint32_t pack_f16(float lo, float hi)
{
    uint32_t r;
    asm("cvt.rn.f16x2.f32 %0, %1, %2;" : "=r"(r) : "f"(hi), "f"(lo));
    return r;
}

__device__ __forceinline__ void cpa16(void* sptr, const void* gptr)
{
    uint32_t s = (uint32_t)__cvta_generic_to_shared(sptr);
    asm volatile("cp.async.cg.shared.global [%0], [%1], 16;" :: "r"(s), "l"(gptr));
}
#define CPA_COMMIT() asm volatile("cp.async.commit_group;" ::: "memory")
#define CPA_WAIT(n)  asm volatile("cp.async.wait_group %0;" :: "n"(n) : "memory")

// ---------------------------------------------------------------------------
// Fused prep: z<4 -> transpose+split W_z ; z==4 -> vectorized convert of x
// ---------------------------------------------------------------------------
__global__ void prep_all(
    const float* __restrict__ x,
    const float* __restrict__ W0, const float* __restrict__ W1,
    const float* __restrict__ W2, const float* __restrict__ W3,
    __half* __restrict__ xh, __half* __restrict__ xl,
    __half* __restrict__ ThB, __half* __restrict__ TlB)
{
    const int z = blockIdx.z;
    if (z < 4) {
        __shared__ float tile[32][33];
        const float* W = (z == 0) ? W0 : (z == 1) ? W1 : (z == 2) ? W2 : W3;
        __half* Th = ThB + (size_t)z * DDIM * DDIM;
        __half* Tl = TlB + (size_t)z * DDIM * DDIM;
        const int tx = threadIdx.x, ty = threadIdx.y;
        tile[ty][tx] = W[(size_t)(blockIdx.y * 32 + ty) * DDIM + blockIdx.x * 32 + tx];
        __syncthreads();
        const int on = blockIdx.x * 32 + ty;
        const int ok = blockIdx.y * 32 + tx;
        float v = tile[tx][ty];
        __half h = __float2half(v);
        Th[(size_t)on * DDIM + ok] = h;
        Tl[(size_t)on * DDIM + ok] = __float2half(v - __half2float(h));
    } else {
        const int tid = threadIdx.y * 32 + threadIdx.x;
        const int bid = blockIdx.y * 32 + blockIdx.x;
        const int n4 = ROWS * DDIM / 4;
        const float4* src = (const float4*)x;
        uint2* hi = (uint2*)xh;
        uint2* lo = (uint2*)xl;
        for (int i = bid * 1024 + tid; i < n4; i += 1024 * 1024) {
            const float4 v = src[i];
            const float hx = __half2float(__float2half(v.x));
            const float hy = __half2float(__float2half(v.y));
            const float hz = __half2float(__float2half(v.z));
            const float hw = __half2float(__float2half(v.w));
            hi[i] = make_uint2(pack_f16(v.x, v.y), pack_f16(v.z, v.w));
            lo[i] = make_uint2(pack_f16(v.x - hx, v.y - hy), pack_f16(v.z - hz, v.w - hw));
        }
    }
}

// ---------------------------------------------------------------------------
// GEMM core: CTA tile 128x128, K-chunk 64, cp.async 2-stage, 8 warps,
// ldmatrix loads, pass-major mma. PASSES=3 (4 smem tiles/stage) with
// kk-level fragment double-buffering (FPIPE); PASSES=2 (3 tiles/stage).
// ---------------------------------------------------------------------------
#define AKS 72
#define TILE_E (128 * AKS)

template <int PASSES>
struct StageCfg {
    static constexpr int NT = (PASSES == 3) ? 4 : 3;
    static constexpr int STG = NT * TILE_E;
};
#define GEMM_SMEM3 (2 * StageCfg<3>::STG * 2)   // 147456
#define GEMM_SMEM2 (2 * StageCfg<2>::STG * 2)   // 110592

struct GemmCore {
    float acc[4][4][4];
};

template <int PASSES, bool FPIPE>
__device__ __forceinline__ void gemm_core_run(
    char* smem, int t,
    const __half* Ah_g, const __half* Al_g,
    const __half* Bh_g, const __half* Bl_g,
    int bm, int bn, GemmCore& gc)
{
    constexpr int STG   = StageCfg<PASSES>::STG;
    constexpr int O_AL  = TILE_E;                              // PASSES==3 only
    constexpr int O_BH  = (PASSES == 3 ? 2 : 1) * TILE_E;
    constexpr int O_BL  = O_BH + TILE_E;

    __half* sbase = (__half*)smem;
    const int wid  = t >> 5;
    const int lane = t & 31;
    const int wr   = wid & 1;
    const int wc   = wid >> 1;
    const int lr   = lane >> 2;
    const int lc   = (lane & 3) << 1;

    const int aoff = ((wr * 64 + (lane & 15)) * AKS + ((lane >> 4) << 3)) * 2;
    const int boff = ((wc * 32 + (lane & 7) + (((lane >> 4) & 1) << 3)) * AKS
                      + (((lane >> 3) & 1) << 3)) * 2;

    auto issue_chunk = [&](int c, int stg) {
        __half* s0 = sbase + stg * STG;
        const int k0g = c * 64;
#pragma unroll
        for (int it = 0; it < 4; it++) {
            const int i = t + it * 256;
            const int r = i >> 3, seg = i & 7;
            const size_t ga = (size_t)(bm + r) * DDIM + k0g + seg * 8;
            const size_t gb = (size_t)(bn + r) * DDIM + k0g + seg * 8;
            const int so = r * AKS + seg * 8;
            cpa16(s0 + so,        Ah_g + ga);
            if (PASSES == 3) cpa16(s0 + O_AL + so, Al_g + ga);
            cpa16(s0 + O_BH + so, Bh_g + gb);
            cpa16(s0 + O_BL + so, Bl_g + gb);
        }
    };

#pragma unroll
    for (int i = 0; i < 4; i++)
#pragma unroll
        for (int j = 0; j < 4; j++)
#pragma unroll
            for (int r = 0; r < 4; r++) gc.acc[i][j][r] = 0.f;

    issue_chunk(0, 0);
    CPA_COMMIT();

    const uint32_t uBase = (uint32_t)__cvta_generic_to_shared(sbase);

    for (int c = 0; c < 16; c++) {
        if (c < 15) { issue_chunk(c + 1, (c + 1) & 1); CPA_COMMIT(); CPA_WAIT(1); }
        else        { CPA_WAIT(0); }
        __syncthreads();

        const uint32_t uS  = uBase + (c & 1) * (STG * 2);
        const uint32_t uAh = uS;
        const uint32_t uAl = uS + O_AL * 2;
        const uint32_t uBh = uS + O_BH * 2;
        const uint32_t uBl = uS + O_BL * 2;

        if (FPIPE) {
            // kk-level fragment double buffer: load kk+1 before mma(kk)
            uint32_t ah[2][4][4], al[2][4][4], bh[2][2][4], bl[2][2][4];
            auto load_frags = [&](int kk, int buf) {
                const int kb = kk * 32;
#pragma unroll
                for (int mi = 0; mi < 4; mi++) {
                    ldsm_x4(ah[buf][mi], uAh + aoff + mi * (16 * AKS * 2) + kb);
                    if (PASSES == 3)
                        ldsm_x4(al[buf][mi], uAl + aoff + mi * (16 * AKS * 2) + kb);
                }
#pragma unroll
                for (int nip = 0; nip < 2; nip++) {
                    ldsm_x4(bh[buf][nip], uBh + boff + nip * (16 * AKS * 2) + kb);
                    ldsm_x4(bl[buf][nip], uBl + boff + nip * (16 * AKS * 2) + kb);
                }
            };
            load_frags(0, 0);
#pragma unroll
            for (int kk = 0; kk < 4; kk++) {
                const int cur = kk & 1;
                if (kk < 3) load_frags(kk + 1, cur ^ 1);
#pragma unroll
                for (int mi = 0; mi < 4; mi++)
#pragma unroll
                    for (int ni = 0; ni < 4; ni++)
                        mma16816(gc.acc[mi][ni], ah[cur][mi], &bh[cur][ni >> 1][(ni & 1) * 2]);
#pragma unroll
                for (int mi = 0; mi < 4; mi++)
#pragma unroll
                    for (int ni = 0; ni < 4; ni++)
                        mma16816(gc.acc[mi][ni], ah[cur][mi], &bl[cur][ni >> 1][(ni & 1) * 2]);
                if (PASSES == 3) {
#pragma unroll
                    for (int mi = 0; mi < 4; mi++)
#pragma unroll
                        for (int ni = 0; ni < 4; ni++)
                            mma16816(gc.acc[mi][ni], al[cur][mi], &bh[cur][ni >> 1][(ni & 1) * 2]);
                }
            }
        } else {
#pragma unroll
            for (int kk = 0; kk < 4; kk++) {
                const int kb = kk * 32;
                uint32_t ah[4][4], al[4][4], bh[2][4], bl[2][4];
#pragma unroll
                for (int mi = 0; mi < 4; mi++) {
                    ldsm_x4(ah[mi], uAh + aoff + mi * (16 * AKS * 2) + kb);
                    if (PASSES == 3)
                        ldsm_x4(al[mi], uAl + aoff + mi * (16 * AKS * 2) + kb);
                }
#pragma unroll
                for (int nip = 0; nip < 2; nip++) {
                    ldsm_x4(bh[nip], uBh + boff + nip * (16 * AKS * 2) + kb);
                    ldsm_x4(bl[nip], uBl + boff + nip * (16 * AKS * 2) + kb);
                }
#pragma unroll
                for (int mi = 0; mi < 4; mi++)
#pragma unroll
                    for (int ni = 0; ni < 4; ni++)
                        mma16816(gc.acc[mi][ni], ah[mi], &bh[ni >> 1][(ni & 1) * 2]);
#pragma unroll
                for (int mi = 0; mi < 4; mi++)
#pragma unroll
                    for (int ni = 0; ni < 4; ni++)
                        mma16816(gc.acc[mi][ni], ah[mi], &bl[ni >> 1][(ni & 1) * 2]);
                if (PASSES == 3) {
#pragma unroll
                    for (int mi = 0; mi < 4; mi++)
#pragma unroll
                        for (int ni = 0; ni < 4; ni++)
                            mma16816(gc.acc[mi][ni], al[mi], &bh[ni >> 1][(ni & 1) * 2]);
                }
            }
        }
        __syncthreads();
    }

    float* Ds = (float*)smem;
#pragma unroll
    for (int mi = 0; mi < 4; mi++) {
        const int r = wr * 64 + mi * 16 + lr;
#pragma unroll
        for (int ni = 0; ni < 4; ni++) {
            const int cc = wc * 32 + ni * 8 + lc;
            Ds[r * 133 + cc]           = gc.acc[mi][ni][0];
            Ds[r * 133 + cc + 1]       = gc.acc[mi][ni][1];
            Ds[(r + 8) * 133 + cc]     = gc.acc[mi][ni][2];
            Ds[(r + 8) * 133 + cc + 1] = gc.acc[mi][ni][3];
        }
    }
    __syncthreads();
}

// ---------------------------------------------------------------------------
// Fused QKV projection. which = bn>>10: 0=Q (1/8, hi/lo), 1=K (single fp16),
// 2=V ([b,h,hd,s] single fp16). 3-pass, frag-pipelined, 1 CTA/SM.
// ---------------------------------------------------------------------------
__global__ __launch_bounds__(256) void gemm_qkv(
    const __half* __restrict__ Ah_g, const __half* __restrict__ Al_g,
    const __half* __restrict__ Wh_g, const __half* __restrict__ Wl_g,
    const float* __restrict__ bq, const float* __restrict__ bk, const float* __restrict__ bv,
    __half* __restrict__ qh, __half* __restrict__ ql,
    __half* __restrict__ kh, __half* __restrict__ vth)
{
    extern __shared__ char smem[];
    const int t  = threadIdx.x;
    const int bn = blockIdx.x * 128;
    const int bm = blockIdx.y * 128;
    const int which = bn >> 10;

    GemmCore gc;
    gemm_core_run<3, true>(smem, t, Ah_g, Al_g, Wh_g, Wl_g, bm, bn, gc);

    const float* Ds = (const float*)smem;
    const float* bias = (which == 0) ? bq : (which == 1) ? bk : bv;
    const int colm_base = bn & 1023;

    if (which == 0) {
        for (int idx = t; idx < 128 * 128; idx += 256) {
            const int r = idx >> 7, cc = idx & 127;
            const int row = bm + r;
            const int colm = colm_base + cc;
            const float v = (Ds[r * 133 + cc] + bias[colm]) * 0.125f;
            const int b = row >> 11, s = row & (SDIM - 1);
            const int h = colm >> 6, hd = colm & (HD - 1);
            const size_t dst = (size_t)((b * HNUM + h) * SDIM + s) * HD + hd;
            __half hh = __float2half(v);
            qh[dst] = hh;
            ql[dst] = __float2half(v - __half2float(hh));
        }
    } else if (which == 1) {
        for (int idx = t; idx < 128 * 128; idx += 256) {
            const int r = idx >> 7, cc = idx & 127;
            const int row = bm + r;
            const int colm = colm_base + cc;
            const float v = Ds[r * 133 + cc] + bias[colm];
            const int b = row >> 11, s = row & (SDIM - 1);
            const int h = colm >> 6, hd = colm & (HD - 1);
            kh[(size_t)((b * HNUM + h) * SDIM + s) * HD + hd] = __float2half(v);
        }
    } else {
        for (int idx = t; idx < 128 * 128; idx += 256) {
            const int r = idx & 127, cc = idx >> 7;
            const int row = bm + r;
            const int colm = colm_base + cc;
            const float v = Ds[r * 133 + cc] + bias[colm];
            const int b = row >> 11, s = row & (SDIM - 1);
            const int h = colm >> 6, hd = colm & (HD - 1);
            vth[(size_t)((b * HNUM + h) * HD + hd) * SDIM + s] = __float2half(v);
        }
    }
}

// O-projection: ctx single fp16 (2-pass), fp32 out. 3-tile stage, 2 CTAs/SM.
__global__ __launch_bounds__(256, 2) void gemm_out(
    const __half* __restrict__ Ah_g,
    const __half* __restrict__ Bh_g, const __half* __restrict__ Bl_g,
    const float* __restrict__ bias, float* __restrict__ outF)
{
    extern __shared__ char smem[];
    const int t  = threadIdx.x;
    const int bn = blockIdx.x * 128;
    const int bm = blockIdx.y * 128;

    GemmCore gc;
    gemm_core_run<2, false>(smem, t, Ah_g, Ah_g, Bh_g, Bl_g, bm, bn, gc);

    const float* Ds = (const float*)smem;
    for (int idx = t; idx < 128 * 128; idx += 256) {
        const int r = idx >> 7, cc = idx & 127;
        outF[(size_t)(bm + r) * DDIM + bn + cc] = Ds[r * 133 + cc] + bias[bn + cc];
    }
}

// ---------------------------------------------------------------------------
// Flash attention (unchanged). QK^T: 2-pass (Q hi/lo x K single). PV: 1-pass
// (P single x V single). cp.async 2-stage KV pipeline.
// ---------------------------------------------------------------------------
#define ATS 72
#define QSZ_E   (2 * 128 * ATS)
#define KVT_E   (64 * ATS)
#define KVSTG_E (2 * KVT_E)
#define ATTN_SMEM ((QSZ_E + 2 * KVSTG_E) * 2)   // 73728 bytes

__global__ __launch_bounds__(256) void attn_mma()
{
    extern __shared__ char smraw[];
    __half* sm = (__half*)smraw;
    __half* sQh = sm;
    __half* sQl = sm + 128 * ATS;

    const int t    = threadIdx.x;
    const int wid  = t >> 5;
    const int lane = t & 31;
    const int lr   = lane >> 2;
    const int lc   = (lane & 3) << 1;
    const int bh    = blockIdx.y;
    const int qbase = blockIdx.x * 128;
    const int qw    = wid * 16;

    const __half* Qh = g_Qh + (size_t)bh * SDIM * HD;
    const __half* Ql = g_Ql + (size_t)bh * SDIM * HD;
    const __half* Kh = g_Kh + (size_t)bh * SDIM * HD;
    const __half* Vh = g_VTh + (size_t)bh * HD * SDIM;

    auto issue_kv = [&](int c, int stg) {
        __half* s0 = sm + QSZ_E + stg * KVSTG_E;
        const int kb = c * 64;
#pragma unroll
        for (int it = 0; it < 2; it++) {
            const int i = t + it * 256;
            const int r = i >> 3, seg = i & 7;
            const int so = r * ATS + seg * 8;
            const size_t gk = (size_t)(kb + r) * HD + seg * 8;
            const size_t gv = (size_t)r * SDIM + kb + seg * 8;
            cpa16(s0 + so,         Kh + gk);
            cpa16(s0 + KVT_E + so, Vh + gv);
        }
    };

#pragma unroll
    for (int it = 0; it < 4; it++) {
        const int i = t + it * 256;
        const int r = i >> 3, seg = i & 7;
        const size_t g = (size_t)(qbase + r) * HD + seg * 8;
        const int so = r * ATS + seg * 8;
        cpa16(sQh + so, Qh + g);
        cpa16(sQl + so, Ql + g);
    }
    issue_kv(0, 0);
    CPA_COMMIT();

    float o[8][4];
#pragma unroll
    for (int i = 0; i < 8; i++)
#pragma unroll
        for (int j = 0; j < 4; j++) o[i][j] = 0.f;
    float m0 = -1e30f, m1 = -1e30f, l0 = 0.f, l1 = 0.f;

    for (int c = 0; c < 32; c++) {
        if (c < 31) { issue_kv(c + 1, (c + 1) & 1); CPA_COMMIT(); CPA_WAIT(1); }
        else        { CPA_WAIT(0); }
        __syncthreads();

        const __half* sKh = sm + QSZ_E + (c & 1) * KVSTG_E;
        const __half* sVh = sKh + KVT_E;

        float s[8][4];
#pragma unroll
        for (int i = 0; i < 8; i++)
#pragma unroll
            for (int j = 0; j < 4; j++) s[i][j] = 0.f;

#pragma unroll
        for (int kk = 0; kk < 4; kk++) {
            const int k0 = kk * 16;
            uint32_t qa_h[4], qa_l[4], kbh[8][2];
            const int r0 = (qw + lr) * ATS + k0 + lc;
            const int r8 = r0 + 8 * ATS;
            qa_h[0] = *(const uint32_t*)(sQh + r0);
            qa_h[1] = *(const uint32_t*)(sQh + r8);
            qa_h[2] = *(const uint32_t*)(sQh + r0 + 8);
            qa_h[3] = *(const uint32_t*)(sQh + r8 + 8);
            qa_l[0] = *(const uint32_t*)(sQl + r0);
            qa_l[1] = *(const uint32_t*)(sQl + r8);
            qa_l[2] = *(const uint32_t*)(sQl + r0 + 8);
            qa_l[3] = *(const uint32_t*)(sQl + r8 + 8);
#pragma unroll
            for (int ni = 0; ni < 8; ni++) {
                const int c0 = (ni * 8 + lr) * ATS + k0 + lc;
                kbh[ni][0] = *(const uint32_t*)(sKh + c0);
                kbh[ni][1] = *(const uint32_t*)(sKh + c0 + 8);
            }
#pragma unroll
            for (int ni = 0; ni < 8; ni++) mma16816(s[ni], qa_h, kbh[ni]);
#pragma unroll
            for (int ni = 0; ni < 8; ni++) mma16816(s[ni], qa_l, kbh[ni]);
        }

        float mx0 = -1e30f, mx1 = -1e30f;
#pragma unroll
        for (int ni = 0; ni < 8; ni++) {
            mx0 = fmaxf(mx0, fmaxf(s[ni][0], s[ni][1]));
            mx1 = fmaxf(mx1, fmaxf(s[ni][2], s[ni][3]));
        }
#pragma unroll
        for (int off = 1; off < 4; off <<= 1) {
            mx0 = fmaxf(mx0, __shfl_xor_sync(0xffffffffu, mx0, off));
            mx1 = fmaxf(mx1, __shfl_xor_sync(0xffffffffu, mx1, off));
        }
        const float mn0 = fmaxf(m0, mx0);
        const float mn1 = fmaxf(m1, mx1);
        const float al0 = __expf(m0 - mn0);
        const float al1 = __expf(m1 - mn1);
        m0 = mn0; m1 = mn1;

        float ls0 = 0.f, ls1 = 0.f;
#pragma unroll
        for (int ni = 0; ni < 8; ni++) {
            s[ni][0] = __expf(s[ni][0] - mn0);
            s[ni][1] = __expf(s[ni][1] - mn0);
            s[ni][2] = __expf(s[ni][2] - mn1);
            s[ni][3] = __expf(s[ni][3] - mn1);
            ls0 += s[ni][0] + s[ni][1];
            ls1 += s[ni][2] + s[ni][3];
        }
#pragma unroll
        for (int off = 1; off < 4; off <<= 1) {
            ls0 += __shfl_xor_sync(0xffffffffu, ls0, off);
            ls1 += __shfl_xor_sync(0xffffffffu, ls1, off);
        }
        l0 = l0 * al0 + ls0;
        l1 = l1 * al1 + ls1;
#pragma unroll
        for (int ni = 0; ni < 8; ni++) {
            o[ni][0] *= al0; o[ni][1] *= al0;
            o[ni][2] *= al1; o[ni][3] *= al1;
        }

#pragma unroll
        for (int j = 0; j < 4; j++) {
            uint32_t pa[4], vbh[8][2];
            pa[0] = pack_f16(s[2*j][0],   s[2*j][1]);
            pa[1] = pack_f16(s[2*j][2],   s[2*j][3]);
            pa[2] = pack_f16(s[2*j+1][0], s[2*j+1][1]);
            pa[3] = pack_f16(s[2*j+1][2], s[2*j+1][3]);
#pragma unroll
            for (int ni = 0; ni < 8; ni++) {
                const int c0 = (ni * 8 + lr) * ATS + j * 16 + lc;
                vbh[ni][0] = *(const uint32_t*)(sVh + c0);
                vbh[ni][1] = *(const uint32_t*)(sVh + c0 + 8);
            }
#pragma unroll
            for (int ni = 0; ni < 8; ni++) mma16816(o[ni], pa, vbh[ni]);
        }
        __syncthreads();
    }

    const float inv0 = 1.f / l0;
    const float inv1 = 1.f / l1;
    const int b = bh >> 4;
    const int h = bh & (HNUM - 1);
    const int s0 = qbase + qw + lr;
    const int s1 = s0 + 8;
#pragma unroll
    for (int ni = 0; ni < 8; ni++) {
        const int col = h * HD + ni * 8 + lc;
        *(uint32_t*)(g_CTXh + (size_t)(b * SDIM + s0) * DDIM + col) =
            pack_f16(o[ni][0] * inv0, o[ni][1] * inv0);
        *(uint32_t*)(g_CTXh + (size_t)(b * SDIM + s1) * DDIM + col) =
            pack_f16(o[ni][2] * inv1, o[ni][3] * inv1);
    }
}

// ---------------------------------------------------------------------------
// Launch
// ---------------------------------------------------------------------------
extern "C" void kernel_launch(void* const* d_in, const int* in_sizes, int n_in,
                              void* d_out, int out_size)
{
    const float* x  = (const float*)d_in[0];
    const float* Wq = (const float*)d_in[1];
    const float* bq = (const float*)d_in[2];
    const float* Wk = (const float*)d_in[3];
    const float* bk = (const float*)d_in[4];
    const float* Wv = (const float*)d_in[5];
    const float* bv = (const float*)d_in[6];
    const float* Wo = (const float*)d_in[7];
    const float* bo = (const float*)d_in[8];

    __half *xh, *xl, *wth, *wtl, *qh, *ql, *kh, *vth, *ctxh;
    cudaGetSymbolAddress((void**)&xh,   g_Xh);
    cudaGetSymbolAddress((void**)&xl,   g_Xl);
    cudaGetSymbolAddress((void**)&wth,  g_Wth);
    cudaGetSymbolAddress((void**)&wtl,  g_Wtl);
    cudaGetSymbolAddress((void**)&qh,   g_Qh);
    cudaGetSymbolAddress((void**)&ql,   g_Ql);
    cudaGetSymbolAddress((void**)&kh,   g_Kh);
    cudaGetSymbolAddress((void**)&vth,  g_VTh);
    cudaGetSymbolAddress((void**)&ctxh, g_CTXh);

    cudaFuncSetAttribute(gemm_qkv, cudaFuncAttributeMaxDynamicSharedMemorySize, GEMM_SMEM3);
    cudaFuncSetAttribute(gemm_out, cudaFuncAttributeMaxDynamicSharedMemorySize, GEMM_SMEM2);
    cudaFuncSetAttribute(attn_mma, cudaFuncAttributeMaxDynamicSharedMemorySize, ATTN_SMEM);

    const size_t WSZ = (size_t)DDIM * DDIM;

    prep_all<<<dim3(32, 32, 5), dim3(32, 32)>>>(x, Wq, Wk, Wv, Wo, xh, xl, wth, wtl);

    gemm_qkv<<<dim3(3 * DDIM / 128, ROWS / 128), 256, GEMM_SMEM3>>>(
        xh, xl, wth, wtl, bq, bk, bv, qh, ql, kh, vth);

    attn_mma<<<dim3(SDIM / 128, BH), 256, ATTN_SMEM>>>();   // (16, 64)

    gemm_out<<<dim3(DDIM / 128, ROWS / 128), 256, GEMM_SMEM2>>>(
        ctxh, wth + 3 * WSZ, wtl + 3 * WSZ, bo, (float*)d_out);
}

// round 17
// speedup vs baseline: 4.7085x; 1.1057x over previous
#include <cuda_runtime.h>
#include <cuda_fp16.h>
#include <math.h>
#include <cstdint>

#define BDIM 4
#define SDIM 2048
#define DDIM 1024
#define HNUM 16
#define HD   64
#define ROWS (BDIM * SDIM)   // 8192
#define BH   (BDIM * HNUM)   // 64

// ---------------------------------------------------------------------------
// Scratch (fp16 hi/lo splits)
// ---------------------------------------------------------------------------
__device__ __half g_Xh[(size_t)ROWS * DDIM];
__device__ __half g_Xl[(size_t)ROWS * DDIM];
__device__ __half g_Wth[4][(size_t)DDIM * DDIM];   // W^T hi, [n][k]; QKVO contiguous
__device__ __half g_Wtl[4][(size_t)DDIM * DDIM];
__device__ __half g_Qh[(size_t)BH * SDIM * HD];    // [bh][s][hd] (pre-scaled 1/8)
__device__ __half g_Ql[(size_t)BH * SDIM * HD];
__device__ __half g_Kh[(size_t)BH * SDIM * HD];    // K single fp16
__device__ __half g_VTh[(size_t)BH * HD * SDIM];   // [bh][hd][s], V single fp16
__device__ __half g_CTXh[(size_t)ROWS * DDIM];     // attention output, single fp16

// ---------------------------------------------------------------------------
// Helpers
// ---------------------------------------------------------------------------
__device__ __forceinline__ void mma16816(float* c, const uint32_t* a, const uint32_t* b)
{
    asm volatile(
        "mma.sync.aligned.m16n8k16.row.col.f32.f16.f16.f32 "
        "{%0,%1,%2,%3}, {%4,%5,%6,%7}, {%8,%9}, {%0,%1,%2,%3};"
        : "+f"(c[0]), "+f"(c[1]), "+f"(c[2]), "+f"(c[3])
        : "r"(a[0]), "r"(a[1]), "r"(a[2]), "r"(a[3]), "r"(b[0]), "r"(b[1]));
}

__device__ __forceinline__ void ldsm_x4(uint32_t* r, uint32_t saddr)
{
    asm volatile("ldmatrix.sync.aligned.m8n8.x4.shared.b16 {%0,%1,%2,%3}, [%4];"
        : "=r"(r[0]), "=r"(r[1]), "=r"(r[2]), "=r"(r[3]) : "r"(saddr));
}

// pack two fp32 -> f16x2 (first arg -> low half, second arg -> high half)
__device__ __forceinline__ uint32_t pack_f16(float lo, float hi)
{
    uint32_t r;
    asm("cvt.rn.f16x2.f32 %0, %1, %2;" : "=r"(r) : "f"(hi), "f"(lo));
    return r;
}

__device__ __forceinline__ void cpa16(void* sptr, const void* gptr)
{
    uint32_t s = (uint32_t)__cvta_generic_to_shared(sptr);
    asm volatile("cp.async.cg.shared.global [%0], [%1], 16;" :: "r"(s), "l"(gptr));
}
#define CPA_COMMIT() asm volatile("cp.async.commit_group;" ::: "memory")
#define CPA_WAIT(n)  asm volatile("cp.async.wait_group %0;" :: "n"(n) : "memory")

// ---------------------------------------------------------------------------
// Fused prep: z<4 -> transpose+split W_z ; z==4 -> vectorized convert of x
// ---------------------------------------------------------------------------
__global__ void prep_all(
    const float* __restrict__ x,
    const float* __restrict__ W0, const float* __restrict__ W1,
    const float* __restrict__ W2, const float* __restrict__ W3,
    __half* __restrict__ xh, __half* __restrict__ xl,
    __half* __restrict__ ThB, __half* __restrict__ TlB)
{
    const int z = blockIdx.z;
    if (z < 4) {
        __shared__ float tile[32][33];
        const float* W = (z == 0) ? W0 : (z == 1) ? W1 : (z == 2) ? W2 : W3;
        __half* Th = ThB + (size_t)z * DDIM * DDIM;
        __half* Tl = TlB + (size_t)z * DDIM * DDIM;
        const int tx = threadIdx.x, ty = threadIdx.y;
        tile[ty][tx] = W[(size_t)(blockIdx.y * 32 + ty) * DDIM + blockIdx.x * 32 + tx];
        __syncthreads();
        const int on = blockIdx.x * 32 + ty;
        const int ok = blockIdx.y * 32 + tx;
        float v = tile[tx][ty];
        __half h = __float2half(v);
        Th[(size_t)on * DDIM + ok] = h;
        Tl[(size_t)on * DDIM + ok] = __float2half(v - __half2float(h));
    } else {
        const int tid = threadIdx.y * 32 + threadIdx.x;
        const int bid = blockIdx.y * 32 + blockIdx.x;
        const int n4 = ROWS * DDIM / 4;
        const float4* src = (const float4*)x;
        uint2* hi = (uint2*)xh;
        uint2* lo = (uint2*)xl;
        for (int i = bid * 1024 + tid; i < n4; i += 1024 * 1024) {
            const float4 v = src[i];
            const float hx = __half2float(__float2half(v.x));
            const float hy = __half2float(__float2half(v.y));
            const float hz = __half2float(__float2half(v.z));
            const float hw = __half2float(__float2half(v.w));
            hi[i] = make_uint2(pack_f16(v.x, v.y), pack_f16(v.z, v.w));
            lo[i] = make_uint2(pack_f16(v.x - hx, v.y - hy), pack_f16(v.z - hz, v.w - hw));
        }
    }
}

// ---------------------------------------------------------------------------
// GEMM core: CTA tile 128x128, K-chunk 64, cp.async 2-stage, 8 warps,
// ldmatrix loads, pass-major mma. PASSES=3 (4 smem tiles/stage, Ah*Bh+Ah*Bl+
// Al*Bh); PASSES=2 (3 tiles/stage, Ah*Bh+Ah*Bl). FPIPE: kk-level fragment
// double buffering.
// ---------------------------------------------------------------------------
#define AKS 72
#define TILE_E (128 * AKS)

template <int PASSES>
struct StageCfg {
    static constexpr int NT = (PASSES == 3) ? 4 : 3;
    static constexpr int STG = NT * TILE_E;
};
#define GEMM_SMEM3 (2 * StageCfg<3>::STG * 2)   // 147456
#define GEMM_SMEM2 (2 * StageCfg<2>::STG * 2)   // 110592

struct GemmCore {
    float acc[4][4][4];
};

template <int PASSES, bool FPIPE>
__device__ __forceinline__ void gemm_core_run(
    char* smem, int t,
    const __half* Ah_g, const __half* Al_g,
    const __half* Bh_g, const __half* Bl_g,
    int bm, int bn, GemmCore& gc)
{
    constexpr int STG   = StageCfg<PASSES>::STG;
    constexpr int O_AL  = TILE_E;                              // PASSES==3 only
    constexpr int O_BH  = (PASSES == 3 ? 2 : 1) * TILE_E;
    constexpr int O_BL  = O_BH + TILE_E;

    __half* sbase = (__half*)smem;
    const int wid  = t >> 5;
    const int lane = t & 31;
    const int wr   = wid & 1;
    const int wc   = wid >> 1;
    const int lr   = lane >> 2;
    const int lc   = (lane & 3) << 1;

    const int aoff = ((wr * 64 + (lane & 15)) * AKS + ((lane >> 4) << 3)) * 2;
    const int boff = ((wc * 32 + (lane & 7) + (((lane >> 4) & 1) << 3)) * AKS
                      + (((lane >> 3) & 1) << 3)) * 2;

    auto issue_chunk = [&](int c, int stg) {
        __half* s0 = sbase + stg * STG;
        const int k0g = c * 64;
#pragma unroll
        for (int it = 0; it < 4; it++) {
            const int i = t + it * 256;
            const int r = i >> 3, seg = i & 7;
            const size_t ga = (size_t)(bm + r) * DDIM + k0g + seg * 8;
            const size_t gb = (size_t)(bn + r) * DDIM + k0g + seg * 8;
            const int so = r * AKS + seg * 8;
            cpa16(s0 + so,        Ah_g + ga);
            if (PASSES == 3) cpa16(s0 + O_AL + so, Al_g + ga);
            cpa16(s0 + O_BH + so, Bh_g + gb);
            cpa16(s0 + O_BL + so, Bl_g + gb);
        }
    };

#pragma unroll
    for (int i = 0; i < 4; i++)
#pragma unroll
        for (int j = 0; j < 4; j++)
#pragma unroll
            for (int r = 0; r < 4; r++) gc.acc[i][j][r] = 0.f;

    issue_chunk(0, 0);
    CPA_COMMIT();

    const uint32_t uBase = (uint32_t)__cvta_generic_to_shared(sbase);

    for (int c = 0; c < 16; c++) {
        if (c < 15) { issue_chunk(c + 1, (c + 1) & 1); CPA_COMMIT(); CPA_WAIT(1); }
        else        { CPA_WAIT(0); }
        __syncthreads();

        const uint32_t uS  = uBase + (c & 1) * (STG * 2);
        const uint32_t uAh = uS;
        const uint32_t uAl = uS + O_AL * 2;
        const uint32_t uBh = uS + O_BH * 2;
        const uint32_t uBl = uS + O_BL * 2;

        if (FPIPE) {
            uint32_t ah[2][4][4], al[2][4][4], bh[2][2][4], bl[2][2][4];
            auto load_frags = [&](int kk, int buf) {
                const int kb = kk * 32;
#pragma unroll
                for (int mi = 0; mi < 4; mi++) {
                    ldsm_x4(ah[buf][mi], uAh + aoff + mi * (16 * AKS * 2) + kb);
                    if (PASSES == 3)
                        ldsm_x4(al[buf][mi], uAl + aoff + mi * (16 * AKS * 2) + kb);
                }
#pragma unroll
                for (int nip = 0; nip < 2; nip++) {
                    ldsm_x4(bh[buf][nip], uBh + boff + nip * (16 * AKS * 2) + kb);
                    ldsm_x4(bl[buf][nip], uBl + boff + nip * (16 * AKS * 2) + kb);
                }
            };
            load_frags(0, 0);
#pragma unroll
            for (int kk = 0; kk < 4; kk++) {
                const int cur = kk & 1;
                if (kk < 3) load_frags(kk + 1, cur ^ 1);
#pragma unroll
                for (int mi = 0; mi < 4; mi++)
#pragma unroll
                    for (int ni = 0; ni < 4; ni++)
                        mma16816(gc.acc[mi][ni], ah[cur][mi], &bh[cur][ni >> 1][(ni & 1) * 2]);
#pragma unroll
                for (int mi = 0; mi < 4; mi++)
#pragma unroll
                    for (int ni = 0; ni < 4; ni++)
                        mma16816(gc.acc[mi][ni], ah[cur][mi], &bl[cur][ni >> 1][(ni & 1) * 2]);
                if (PASSES == 3) {
#pragma unroll
                    for (int mi = 0; mi < 4; mi++)
#pragma unroll
                        for (int ni = 0; ni < 4; ni++)
                            mma16816(gc.acc[mi][ni], al[cur][mi], &bh[cur][ni >> 1][(ni & 1) * 2]);
                }
            }
        } else {
#pragma unroll
            for (int kk = 0; kk < 4; kk++) {
                const int kb = kk * 32;
                uint32_t ah[4][4], al[4][4], bh[2][4], bl[2][4];
#pragma unroll
                for (int mi = 0; mi < 4; mi++) {
                    ldsm_x4(ah[mi], uAh + aoff + mi * (16 * AKS * 2) + kb);
                    if (PASSES == 3)
                        ldsm_x4(al[mi], uAl + aoff + mi * (16 * AKS * 2) + kb);
                }
#pragma unroll
                for (int nip = 0; nip < 2; nip++) {
                    ldsm_x4(bh[nip], uBh + boff + nip * (16 * AKS * 2) + kb);
                    ldsm_x4(bl[nip], uBl + boff + nip * (16 * AKS * 2) + kb);
                }
#pragma unroll
                for (int mi = 0; mi < 4; mi++)
#pragma unroll
                    for (int ni = 0; ni < 4; ni++)
                        mma16816(gc.acc[mi][ni], ah[mi], &bh[ni >> 1][(ni & 1) * 2]);
#pragma unroll
                for (int mi = 0; mi < 4; mi++)
#pragma unroll
                    for (int ni = 0; ni < 4; ni++)
                        mma16816(gc.acc[mi][ni], ah[mi], &bl[ni >> 1][(ni & 1) * 2]);
                if (PASSES == 3) {
#pragma unroll
                    for (int mi = 0; mi < 4; mi++)
#pragma unroll
                        for (int ni = 0; ni < 4; ni++)
                            mma16816(gc.acc[mi][ni], al[mi], &bh[ni >> 1][(ni & 1) * 2]);
                }
            }
        }
        __syncthreads();
    }

    float* Ds = (float*)smem;
#pragma unroll
    for (int mi = 0; mi < 4; mi++) {
        const int r = wr * 64 + mi * 16 + lr;
#pragma unroll
        for (int ni = 0; ni < 4; ni++) {
            const int cc = wc * 32 + ni * 8 + lc;
            Ds[r * 133 + cc]           = gc.acc[mi][ni][0];
            Ds[r * 133 + cc + 1]       = gc.acc[mi][ni][1];
            Ds[(r + 8) * 133 + cc]     = gc.acc[mi][ni][2];
            Ds[(r + 8) * 133 + cc + 1] = gc.acc[mi][ni][3];
        }
    }
    __syncthreads();
}

// ---------------------------------------------------------------------------
// Fused QKV projection. which = bn>>10: 0=Q (3-pass, 1/8, hi/lo out),
// 1=K (2-pass, single fp16), 2=V (2-pass, [b,h,hd,s] single fp16).
// K/V 2-pass drops x_lo*W: ~2e-4 rel err, same scale as their fp16 rounding.
// ---------------------------------------------------------------------------
__global__ __launch_bounds__(256) void gemm_qkv(
    const __half* __restrict__ Ah_g, const __half* __restrict__ Al_g,
    const __half* __restrict__ Wh_g, const __half* __restrict__ Wl_g,
    const float* __restrict__ bq, const float* __restrict__ bk, const float* __restrict__ bv,
    __half* __restrict__ qh, __half* __restrict__ ql,
    __half* __restrict__ kh, __half* __restrict__ vth)
{
    extern __shared__ char smem[];
    const int t  = threadIdx.x;
    const int bn = blockIdx.x * 128;
    const int bm = blockIdx.y * 128;
    const int which = bn >> 10;

    GemmCore gc;
    if (which == 0)
        gemm_core_run<3, true>(smem, t, Ah_g, Al_g, Wh_g, Wl_g, bm, bn, gc);
    else
        gemm_core_run<2, true>(smem, t, Ah_g, Ah_g, Wh_g, Wl_g, bm, bn, gc);

    const float* Ds = (const float*)smem;
    const float* bias = (which == 0) ? bq : (which == 1) ? bk : bv;
    const int colm_base = bn & 1023;

    if (which == 0) {
        for (int idx = t; idx < 128 * 128; idx += 256) {
            const int r = idx >> 7, cc = idx & 127;
            const int row = bm + r;
            const int colm = colm_base + cc;
            const float v = (Ds[r * 133 + cc] + bias[colm]) * 0.125f;
            const int b = row >> 11, s = row & (SDIM - 1);
            const int h = colm >> 6, hd = colm & (HD - 1);
            const size_t dst = (size_t)((b * HNUM + h) * SDIM + s) * HD + hd;
            __half hh = __float2half(v);
            qh[dst] = hh;
            ql[dst] = __float2half(v - __half2float(hh));
        }
    } else if (which == 1) {
        for (int idx = t; idx < 128 * 128; idx += 256) {
            const int r = idx >> 7, cc = idx & 127;
            const int row = bm + r;
            const int colm = colm_base + cc;
            const float v = Ds[r * 133 + cc] + bias[colm];
            const int b = row >> 11, s = row & (SDIM - 1);
            const int h = colm >> 6, hd = colm & (HD - 1);
            kh[(size_t)((b * HNUM + h) * SDIM + s) * HD + hd] = __float2half(v);
        }
    } else {
        for (int idx = t; idx < 128 * 128; idx += 256) {
            const int r = idx & 127, cc = idx >> 7;
            const int row = bm + r;
            const int colm = colm_base + cc;
            const float v = Ds[r * 133 + cc] + bias[colm];
            const int b = row >> 11, s = row & (SDIM - 1);
            const int h = colm >> 6, hd = colm & (HD - 1);
            vth[(size_t)((b * HNUM + h) * HD + hd) * SDIM + s] = __float2half(v);
        }
    }
}

// O-projection: ctx single fp16 (2-pass), fp32 out. 3-tile stage, 2 CTAs/SM.
__global__ __launch_bounds__(256, 2) void gemm_out(
    const __half* __restrict__ Ah_g,
    const __half* __restrict__ Bh_g, const __half* __restrict__ Bl_g,
    const float* __restrict__ bias, float* __restrict__ outF)
{
    extern __shared__ char smem[];
    const int t  = threadIdx.x;
    const int bn = blockIdx.x * 128;
    const int bm = blockIdx.y * 128;

    GemmCore gc;
    gemm_core_run<2, false>(smem, t, Ah_g, Ah_g, Bh_g, Bl_g, bm, bn, gc);

    const float* Ds = (const float*)smem;
    for (int idx = t; idx < 128 * 128; idx += 256) {
        const int r = idx >> 7, cc = idx & 127;
        outF[(size_t)(bm + r) * DDIM + bn + cc] = Ds[r * 133 + cc] + bias[bn + cc];
    }
}

// ---------------------------------------------------------------------------
// Flash attention (unchanged). QK^T: 2-pass (Q hi/lo x K single). PV: 1-pass
// (P single x V single). cp.async 2-stage KV pipeline.
// ---------------------------------------------------------------------------
#define ATS 72
#define QSZ_E   (2 * 128 * ATS)
#define KVT_E   (64 * ATS)
#define KVSTG_E (2 * KVT_E)
#define ATTN_SMEM ((QSZ_E + 2 * KVSTG_E) * 2)   // 73728 bytes

__global__ __launch_bounds__(256) void attn_mma()
{
    extern __shared__ char smraw[];
    __half* sm = (__half*)smraw;
    __half* sQh = sm;
    __half* sQl = sm + 128 * ATS;

    const int t    = threadIdx.x;
    const int wid  = t >> 5;
    const int lane = t & 31;
    const int lr   = lane >> 2;
    const int lc   = (lane & 3) << 1;
    const int bh    = blockIdx.y;
    const int qbase = blockIdx.x * 128;
    const int qw    = wid * 16;

    const __half* Qh = g_Qh + (size_t)bh * SDIM * HD;
    const __half* Ql = g_Ql + (size_t)bh * SDIM * HD;
    const __half* Kh = g_Kh + (size_t)bh * SDIM * HD;
    const __half* Vh = g_VTh + (size_t)bh * HD * SDIM;

    auto issue_kv = [&](int c, int stg) {
        __half* s0 = sm + QSZ_E + stg * KVSTG_E;
        const int kb = c * 64;
#pragma unroll
        for (int it = 0; it < 2; it++) {
            const int i = t + it * 256;
            const int r = i >> 3, seg = i & 7;
            const int so = r * ATS + seg * 8;
            const size_t gk = (size_t)(kb + r) * HD + seg * 8;
            const size_t gv = (size_t)r * SDIM + kb + seg * 8;
            cpa16(s0 + so,         Kh + gk);
            cpa16(s0 + KVT_E + so, Vh + gv);
        }
    };

#pragma unroll
    for (int it = 0; it < 4; it++) {
        const int i = t + it * 256;
        const int r = i >> 3, seg = i & 7;
        const size_t g = (size_t)(qbase + r) * HD + seg * 8;
        const int so = r * ATS + seg * 8;
        cpa16(sQh + so, Qh + g);
        cpa16(sQl + so, Ql + g);
    }
    issue_kv(0, 0);
    CPA_COMMIT();

    float o[8][4];
#pragma unroll
    for (int i = 0; i < 8; i++)
#pragma unroll
        for (int j = 0; j < 4; j++) o[i][j] = 0.f;
    float m0 = -1e30f, m1 = -1e30f, l0 = 0.f, l1 = 0.f;

    for (int c = 0; c < 32; c++) {
        if (c < 31) { issue_kv(c + 1, (c + 1) & 1); CPA_COMMIT(); CPA_WAIT(1); }
        else        { CPA_WAIT(0); }
        __syncthreads();

        const __half* sKh = sm + QSZ_E + (c & 1) * KVSTG_E;
        const __half* sVh = sKh + KVT_E;

        float s[8][4];
#pragma unroll
        for (int i = 0; i < 8; i++)
#pragma unroll
            for (int j = 0; j < 4; j++) s[i][j] = 0.f;

#pragma unroll
        for (int kk = 0; kk < 4; kk++) {
            const int k0 = kk * 16;
            uint32_t qa_h[4], qa_l[4], kbh[8][2];
            const int r0 = (qw + lr) * ATS + k0 + lc;
            const int r8 = r0 + 8 * ATS;
            qa_h[0] = *(const uint32_t*)(sQh + r0);
            qa_h[1] = *(const uint32_t*)(sQh + r8);
            qa_h[2] = *(const uint32_t*)(sQh + r0 + 8);
            qa_h[3] = *(const uint32_t*)(sQh + r8 + 8);
            qa_l[0] = *(const uint32_t*)(sQl + r0);
            qa_l[1] = *(const uint32_t*)(sQl + r8);
            qa_l[2] = *(const uint32_t*)(sQl + r0 + 8);
            qa_l[3] = *(const uint32_t*)(sQl + r8 + 8);
#pragma unroll
            for (int ni = 0; ni < 8; ni++) {
                const int c0 = (ni * 8 + lr) * ATS + k0 + lc;
                kbh[ni][0] = *(const uint32_t*)(sKh + c0);
                kbh[ni][1] = *(const uint32_t*)(sKh + c0 + 8);
            }
#pragma unroll
            for (int ni = 0; ni < 8; ni++) mma16816(s[ni], qa_h, kbh[ni]);
#pragma unroll
            for (int ni = 0; ni < 8; ni++) mma16816(s[ni], qa_l, kbh[ni]);
        }

        float mx0 = -1e30f, mx1 = -1e30f;
#pragma unroll
        for (int ni = 0; ni < 8; ni++) {
            mx0 = fmaxf(mx0, fmaxf(s[ni][0], s[ni][1]));
            mx1 = fmaxf(mx1, fmaxf(s[ni][2], s[ni][3]));
        }
#pragma unroll
        for (int off = 1; off < 4; off <<= 1) {
            mx0 = fmaxf(mx0, __shfl_xor_sync(0xffffffffu, mx0, off));
            mx1 = fmaxf(mx1, __shfl_xor_sync(0xffffffffu, mx1, off));
        }
        const float mn0 = fmaxf(m0, mx0);
        const float mn1 = fmaxf(m1, mx1);
        const float al0 = __expf(m0 - mn0);
        const float al1 = __expf(m1 - mn1);
        m0 = mn0; m1 = mn1;

        float ls0 = 0.f, ls1 = 0.f;
#pragma unroll
        for (int ni = 0; ni < 8; ni++) {
            s[ni][0] = __expf(s[ni][0] - mn0);
            s[ni][1] = __expf(s[ni][1] - mn0);
            s[ni][2] = __expf(s[ni][2] - mn1);
            s[ni][3] = __expf(s[ni][3] - mn1);
            ls0 += s[ni][0] + s[ni][1];
            ls1 += s[ni][2] + s[ni][3];
        }
#pragma unroll
        for (int off = 1; off < 4; off <<= 1) {
            ls0 += __shfl_xor_sync(0xffffffffu, ls0, off);
            ls1 += __shfl_xor_sync(0xffffffffu, ls1, off);
        }
        l0 = l0 * al0 + ls0;
        l1 = l1 * al1 + ls1;
#pragma unroll
        for (int ni = 0; ni < 8; ni++) {
            o[ni][0] *= al0; o[ni][1] *= al0;
            o[ni][2] *= al1; o[ni][3] *= al1;
        }

#pragma unroll
        for (int j = 0; j < 4; j++) {
            uint32_t pa[4], vbh[8][2];
            pa[0] = pack_f16(s[2*j][0],   s[2*j][1]);
            pa[1] = pack_f16(s[2*j][2],   s[2*j][3]);
            pa[2] = pack_f16(s[2*j+1][0], s[2*j+1][1]);
            pa[3] = pack_f16(s[2*j+1][2], s[2*j+1][3]);
#pragma unroll
            for (int ni = 0; ni < 8; ni++) {
                const int c0 = (ni * 8 + lr) * ATS + j * 16 + lc;
                vbh[ni][0] = *(const uint32_t*)(sVh + c0);
                vbh[ni][1] = *(const uint32_t*)(sVh + c0 + 8);
            }
#pragma unroll
            for (int ni = 0; ni < 8; ni++) mma16816(o[ni], pa, vbh[ni]);
        }
        __syncthreads();
    }

    const float inv0 = 1.f / l0;
    const float inv1 = 1.f / l1;
    const int b = bh >> 4;
    const int h = bh & (HNUM - 1);
    const int s0 = qbase + qw + lr;
    const int s1 = s0 + 8;
#pragma unroll
    for (int ni = 0; ni < 8; ni++) {
        const int col = h * HD + ni * 8 + lc;
        *(uint32_t*)(g_CTXh + (size_t)(b * SDIM + s0) * DDIM + col) =
            pack_f16(o[ni][0] * inv0, o[ni][1] * inv0);
        *(uint32_t*)(g_CTXh + (size_t)(b * SDIM + s1) * DDIM + col) =
            pack_f16(o[ni][2] * inv1, o[ni][3] * inv1);
    }
}

// ---------------------------------------------------------------------------
// Launch
// ---------------------------------------------------------------------------
extern "C" void kernel_launch(void* const* d_in, const int* in_sizes, int n_in,
                              void* d_out, int out_size)
{
    const float* x  = (const float*)d_in[0];
    const float* Wq = (const float*)d_in[1];
    const float* bq = (const float*)d_in[2];
    const float* Wk = (const float*)d_in[3];
    const float* bk = (const float*)d_in[4];
    const float* Wv = (const float*)d_in[5];
    const float* bv = (const float*)d_in[6];
    const float* Wo = (const float*)d_in[7];
    const float* bo = (const float*)d_in[8];

    __half *xh, *xl, *wth, *wtl, *qh, *ql, *kh, *vth, *ctxh;
    cudaGetSymbolAddress((void**)&xh,   g_Xh);
    cudaGetSymbolAddress((void**)&xl,   g_Xl);
    cudaGetSymbolAddress((void**)&wth,  g_Wth);
    cudaGetSymbolAddress((void**)&wtl,  g_Wtl);
    cudaGetSymbolAddress((void**)&qh,   g_Qh);
    cudaGetSymbolAddress((void**)&ql,   g_Ql);
    cudaGetSymbolAddress((void**)&kh,   g_Kh);
    cudaGetSymbolAddress((void**)&vth,  g_VTh);
    cudaGetSymbolAddress((void**)&ctxh, g_CTXh);

    cudaFuncSetAttribute(gemm_qkv, cudaFuncAttributeMaxDynamicSharedMemorySize, GEMM_SMEM3);
    cudaFuncSetAttribute(gemm_out, cudaFuncAttributeMaxDynamicSharedMemorySize, GEMM_SMEM2);
    cudaFuncSetAttribute(attn_mma, cudaFuncAttributeMaxDynamicSharedMemorySize, ATTN_SMEM);

    const size_t WSZ = (size_t)DDIM * DDIM;

    prep_all<<<dim3(32, 32, 5), dim3(32, 32)>>>(x, Wq, Wk, Wv, Wo, xh, xl, wth, wtl);

    gemm_qkv<<<dim3(3 * DDIM / 128, ROWS / 128), 256, GEMM_SMEM3>>>(
        xh, xl, wth, wtl, bq, bk, bv, qh, ql, kh, vth);

    attn_mma<<<dim3(SDIM / 128, BH), 256, ATTN_SMEM>>>();   // (16, 64)

    gemm_out<<<dim3(DDIM / 128, ROWS / 128), 256, GEMM_SMEM2>>>(
        ctxh, wth + 3 * WSZ, wtl + 3 * WSZ, bo, (float*)d_out);
}